// round 3
// baseline (speedup 1.0000x reference)
#include <cuda_runtime.h>
#include <math.h>

#define NN 50000
#define EE 400000
#define ET 450000           // EE + NN self loops
#define NEG 0.2f

// ---------------- scratch (static device globals; no allocs) ----------------
__device__ float    g_H1[(size_t)NN * 512];
__device__ float    g_O1[(size_t)NN * 512];
__device__ float    g_H2[(size_t)NN * 128];
__device__ float    g_O2[(size_t)NN * 128];
__device__ float    g_H3[NN * 8];
__device__ float    g_O3[NN * 8];
__device__ float    g_S [NN * 4];
__device__ float    g_D [NN * 4];
__device__ unsigned g_MX[NN * 4];
__device__ float    g_SUM[NN * 4];
__device__ float    g_RS [NN * 4];
__device__ float    g_EX[(size_t)ET * 4];

// ---------------- helpers ----------------
__device__ __forceinline__ void edge_sd(const int* __restrict__ ei, int e, int& s, int& d) {
    if (e < EE) { s = ei[e]; d = ei[EE + e]; }
    else        { s = d = e - EE; }           // self loop
}

// order-preserving float -> uint encoding for atomicMax
__device__ __forceinline__ unsigned encf(float f) {
    unsigned u = __float_as_uint(f);
    return (u & 0x80000000u) ? ~u : (u | 0x80000000u);
}
__device__ __forceinline__ float decf(unsigned u) {
    return (u & 0x80000000u) ? __uint_as_float(u & 0x7fffffffu) : __uint_as_float(~u);
}

// ---------------- GEMM:  C[m,n] = sum_k A[m,k] * B[n,k]  (A:[M,K], B:[N,K]) ----------------
__global__ void __launch_bounds__(256) gemm_nt(const float* __restrict__ A,
                                               const float* __restrict__ B,
                                               float* __restrict__ C,
                                               int M, int N, int K) {
    const int BM = 64, BN = 64, BK = 16;
    __shared__ float As[BK][BM + 4];
    __shared__ float Bs[BK][BN + 4];
    int bm = blockIdx.y * BM, bn = blockIdx.x * BN;
    int tid = threadIdx.x;
    int lr = tid >> 2;             // 0..63
    int lc = (tid & 3) << 2;       // 0,4,8,12
    int tx = tid & 15, ty = tid >> 4;
    float acc[4][4] = {};
    for (int k0 = 0; k0 < K; k0 += BK) {
        float4 av = make_float4(0.f, 0.f, 0.f, 0.f);
        if (bm + lr < M) av = *(const float4*)(A + (size_t)(bm + lr) * K + k0 + lc);
        As[lc + 0][lr] = av.x; As[lc + 1][lr] = av.y; As[lc + 2][lr] = av.z; As[lc + 3][lr] = av.w;
        float4 bv = *(const float4*)(B + (size_t)(bn + lr) * K + k0 + lc);   // N % 64 == 0
        Bs[lc + 0][lr] = bv.x; Bs[lc + 1][lr] = bv.y; Bs[lc + 2][lr] = bv.z; Bs[lc + 3][lr] = bv.w;
        __syncthreads();
#pragma unroll
        for (int kk = 0; kk < BK; kk++) {
            float4 a = *(const float4*)&As[kk][ty * 4];
            float4 b = *(const float4*)&Bs[kk][tx * 4];
            float ar[4] = {a.x, a.y, a.z, a.w};
            float br[4] = {b.x, b.y, b.z, b.w};
#pragma unroll
            for (int i = 0; i < 4; i++)
#pragma unroll
                for (int j = 0; j < 4; j++) acc[i][j] += ar[i] * br[j];
        }
        __syncthreads();
    }
#pragma unroll
    for (int i = 0; i < 4; i++) {
        int r = bm + ty * 4 + i;
        if (r < M) {
            float4 v = make_float4(acc[i][0], acc[i][1], acc[i][2], acc[i][3]);
            *(float4*)(C + (size_t)r * N + bn + tx * 4) = v;
        }
    }
}

// layer 3 GEMM: Nout = 8, thread per (n, j)
__global__ void gemm_small8(const float* __restrict__ A, const float* __restrict__ B,
                            float* __restrict__ C, int K) {
    int idx = blockIdx.x * blockDim.x + threadIdx.x;
    if (idx >= NN * 8) return;
    int n = idx >> 3, j = idx & 7;
    const float* a = A + (size_t)n * K;
    const float* w = B + (size_t)j * K;
    float acc = 0.f;
    for (int k = 0; k < K; k += 4) {
        float4 av = *(const float4*)(a + k);
        float4 wv = *(const float4*)(w + k);
        acc += av.x * wv.x + av.y * wv.y + av.z * wv.z + av.w * wv.w;
    }
    C[idx] = acc;
}

// ---------------- per-node attention scalars: s[n,h] = <h[n,h,:], a_s[h,:]> ----------------
template <int H, int C>
__global__ void attscore(const float* __restrict__ Hb,
                         const float* __restrict__ as_, const float* __restrict__ ad_,
                         float* __restrict__ S, float* __restrict__ D) {
    int gt = blockIdx.x * blockDim.x + threadIdx.x;
    int w = gt >> 5;
    int lane = gt & 31;
    if (w >= NN * H) return;
    int n = w / H, h = w % H;
    const float* row = Hb + (size_t)n * (H * C) + h * C;
    float s = 0.f, d = 0.f;
    for (int c = lane; c < C; c += 32) {
        float v = row[c];
        s += v * as_[h * C + c];
        d += v * ad_[h * C + c];
    }
#pragma unroll
    for (int o = 16; o; o >>= 1) {
        s += __shfl_xor_sync(0xffffffffu, s, o);
        d += __shfl_xor_sync(0xffffffffu, d, o);
    }
    if (lane == 0) { S[n * H + h] = s; D[n * H + h] = d; }
}

// ---------------- inits ----------------
__global__ void k_init(float* __restrict__ O, int no,
                       unsigned* __restrict__ MX, float* __restrict__ SUM, int nmh) {
    int i = blockIdx.x * blockDim.x + threadIdx.x;
    if (i < no) O[i] = 0.f;
    if (i < nmh) { MX[i] = 0u; SUM[i] = 0.f; }
}

// ---------------- edge phase 1: segment max ----------------
template <int H>
__global__ void edge_max(const int* __restrict__ ei,
                         const float* __restrict__ S, const float* __restrict__ D,
                         unsigned* __restrict__ MX) {
    int idx = blockIdx.x * blockDim.x + threadIdx.x;
    if (idx >= ET * H) return;
    int e = idx / H, h = idx - e * H;
    int s, d; edge_sd(ei, e, s, d);
    float el = S[s * H + h] + D[d * H + h];
    el = el > 0.f ? el : NEG * el;
    atomicMax(&MX[d * H + h], encf(el));
}

// ---------------- edge phase 2: ex = exp(e - m), segment sum, store ex ----------------
template <int H>
__global__ void edge_sum(const int* __restrict__ ei,
                         const float* __restrict__ S, const float* __restrict__ D,
                         const unsigned* __restrict__ MX,
                         float* __restrict__ SUM, float* __restrict__ EX) {
    int idx = blockIdx.x * blockDim.x + threadIdx.x;
    if (idx >= ET * H) return;
    int e = idx / H, h = idx - e * H;
    int s, d; edge_sd(ei, e, s, d);
    float el = S[s * H + h] + D[d * H + h];
    el = el > 0.f ? el : NEG * el;
    float m = decf(MX[d * H + h]);
    float ex = __expf(el - m);
    EX[idx] = ex;
    atomicAdd(&SUM[d * H + h], ex);
}

__global__ void k_rsum(const float* __restrict__ SUM, float* __restrict__ RS, int n) {
    int i = blockIdx.x * blockDim.x + threadIdx.x;
    if (i < n) RS[i] = __frcp_rn(SUM[i]);
}

// ---------------- edge phase 3: O[dst] += alpha * H[src]   (float4 groups) ----------------
template <int H, int C>
__global__ void edge_agg(const int* __restrict__ ei,
                         const float* __restrict__ EX, const float* __restrict__ RS,
                         const float* __restrict__ Hb, float* __restrict__ O) {
    const int G = (H * C) / 4;          // float4 groups per edge (power of 2)
    int idx = blockIdx.x * blockDim.x + threadIdx.x;
    if (idx >= ET * G) return;
    int e = idx / G, g = idx - e * G;
    int f = g * 4;
    int h = f / C;
    int s, d; edge_sd(ei, e, s, d);
    float alpha = EX[e * H + h] * RS[d * H + h];
    float4 v = *(const float4*)&Hb[(size_t)s * (H * C) + f];
    float* o = &O[(size_t)d * (H * C) + f];
    atomicAdd(o + 0, alpha * v.x);
    atomicAdd(o + 1, alpha * v.y);
    atomicAdd(o + 2, alpha * v.z);
    atomicAdd(o + 3, alpha * v.w);
}

// ---------------- bias + ELU (in place) ----------------
__global__ void bias_elu(float* __restrict__ O, const float* __restrict__ b,
                         int n, int hcMask) {
    int i = blockIdx.x * blockDim.x + threadIdx.x;
    if (i >= n) return;
    float v = O[i] + b[i & hcMask];
    O[i] = v > 0.f ? v : expm1f(v);
}

// ---------------- final per-edge MLP ----------------
__global__ void edge_mlp(const int* __restrict__ ei, const float* __restrict__ h3,
                         const float* __restrict__ ea, const float* __restrict__ yr,
                         const float* __restrict__ qt,
                         const float* __restrict__ fc1w, const float* __restrict__ fc1b,
                         const float* __restrict__ fc2w, const float* __restrict__ fc2b,
                         float* __restrict__ out) {
    __shared__ float w1[16 * 19];
    __shared__ float b1s[16];
    __shared__ float w2[16];
    int tid = threadIdx.x;
    for (int i = tid; i < 16 * 19; i += blockDim.x) w1[i] = fc1w[i];
    if (tid < 16) { b1s[tid] = fc1b[tid]; w2[tid] = fc2w[tid]; }
    __syncthreads();
    int e = blockIdx.x * blockDim.x + tid;
    if (e >= EE) return;
    int s = ei[e], d = ei[EE + e];
    float z[19];
    float4 a0 = *(const float4*)&h3[s * 8 + 0];
    float4 a1 = *(const float4*)&h3[s * 8 + 4];
    float4 c0 = *(const float4*)&h3[d * 8 + 0];
    float4 c1 = *(const float4*)&h3[d * 8 + 4];
    z[0] = a0.x; z[1] = a0.y; z[2] = a0.z; z[3] = a0.w;
    z[4] = a1.x; z[5] = a1.y; z[6] = a1.z; z[7] = a1.w;
    z[8] = c0.x; z[9] = c0.y; z[10] = c0.z; z[11] = c0.w;
    z[12] = c1.x; z[13] = c1.y; z[14] = c1.z; z[15] = c1.w;
    z[16] = ea[e]; z[17] = yr[e]; z[18] = qt[e];
    float acc = fc2b[0];
#pragma unroll
    for (int o = 0; o < 16; o++) {
        float t = b1s[o];
#pragma unroll
        for (int i = 0; i < 19; i++) t += w1[o * 19 + i] * z[i];
        t = fmaxf(t, 0.f);
        acc += t * w2[o];
    }
    out[e] = acc;
}

// ---------------- host driver ----------------
static inline int cdiv(long long a, int b) { return (int)((a + b - 1) / b); }

extern "C" void kernel_launch(void* const* d_in, const int* in_sizes, int n_in,
                              void* d_out, int out_size) {
    (void)in_sizes; (void)n_in; (void)out_size;
    const float* x    = (const float*)d_in[0];
    const int*   ei   = (const int*)  d_in[1];
    const float* ea   = (const float*)d_in[2];
    const float* yr   = (const float*)d_in[3];
    const float* qt   = (const float*)d_in[4];
    const float* W1   = (const float*)d_in[5];
    const float* a1s  = (const float*)d_in[6];
    const float* a1d  = (const float*)d_in[7];
    const float* b1   = (const float*)d_in[8];
    const float* W2   = (const float*)d_in[9];
    const float* a2s  = (const float*)d_in[10];
    const float* a2d  = (const float*)d_in[11];
    const float* b2   = (const float*)d_in[12];
    const float* W3   = (const float*)d_in[13];
    const float* a3s  = (const float*)d_in[14];
    const float* a3d  = (const float*)d_in[15];
    const float* b3   = (const float*)d_in[16];
    const float* fc1w = (const float*)d_in[17];
    const float* fc1b = (const float*)d_in[18];
    const float* fc2w = (const float*)d_in[19];
    const float* fc2b = (const float*)d_in[20];
    float* out = (float*)d_out;

    float *H1, *O1, *H2, *O2, *H3, *O3, *S, *D, *SUM, *RS, *EX;
    unsigned* MX;
    cudaGetSymbolAddress((void**)&H1, g_H1);
    cudaGetSymbolAddress((void**)&O1, g_O1);
    cudaGetSymbolAddress((void**)&H2, g_H2);
    cudaGetSymbolAddress((void**)&O2, g_O2);
    cudaGetSymbolAddress((void**)&H3, g_H3);
    cudaGetSymbolAddress((void**)&O3, g_O3);
    cudaGetSymbolAddress((void**)&S,  g_S);
    cudaGetSymbolAddress((void**)&D,  g_D);
    cudaGetSymbolAddress((void**)&MX, g_MX);
    cudaGetSymbolAddress((void**)&SUM, g_SUM);
    cudaGetSymbolAddress((void**)&RS, g_RS);
    cudaGetSymbolAddress((void**)&EX, g_EX);

    const int T = 256;

    // ---------- layer 1: 128 -> 4 x 128 ----------
    gemm_nt<<<dim3(512 / 64, cdiv(NN, 64)), T>>>(x, W1, H1, NN, 512, 128);
    attscore<4, 128><<<cdiv((long long)NN * 4 * 32, T), T>>>(H1, a1s, a1d, S, D);
    k_init<<<cdiv((long long)NN * 512, T), T>>>(O1, NN * 512, MX, SUM, NN * 4);
    edge_max<4><<<cdiv((long long)ET * 4, T), T>>>(ei, S, D, MX);
    edge_sum<4><<<cdiv((long long)ET * 4, T), T>>>(ei, S, D, MX, SUM, EX);
    k_rsum<<<cdiv(NN * 4, T), T>>>(SUM, RS, NN * 4);
    edge_agg<4, 128><<<cdiv((long long)ET * 128, T), T>>>(ei, EX, RS, H1, O1);
    bias_elu<<<cdiv((long long)NN * 512, T), T>>>(O1, b1, NN * 512, 511);

    // ---------- layer 2: 512 -> 4 x 32 ----------
    gemm_nt<<<dim3(128 / 64, cdiv(NN, 64)), T>>>(O1, W2, H2, NN, 128, 512);
    attscore<4, 32><<<cdiv((long long)NN * 4 * 32, T), T>>>(H2, a2s, a2d, S, D);
    k_init<<<cdiv((long long)NN * 128, T), T>>>(O2, NN * 128, MX, SUM, NN * 4);
    edge_max<4><<<cdiv((long long)ET * 4, T), T>>>(ei, S, D, MX);
    edge_sum<4><<<cdiv((long long)ET * 4, T), T>>>(ei, S, D, MX, SUM, EX);
    k_rsum<<<cdiv(NN * 4, T), T>>>(SUM, RS, NN * 4);
    edge_agg<4, 32><<<cdiv((long long)ET * 32, T), T>>>(ei, EX, RS, H2, O2);
    bias_elu<<<cdiv((long long)NN * 128, T), T>>>(O2, b2, NN * 128, 127);

    // ---------- layer 3: 128 -> 1 x 8 ----------
    gemm_small8<<<cdiv(NN * 8, T), T>>>(O2, W3, H3, 128);
    attscore<1, 8><<<cdiv((long long)NN * 32, T), T>>>(H3, a3s, a3d, S, D);
    k_init<<<cdiv(NN * 8, T), T>>>(O3, NN * 8, MX, SUM, NN);
    edge_max<1><<<cdiv(ET, T), T>>>(ei, S, D, MX);
    edge_sum<1><<<cdiv(ET, T), T>>>(ei, S, D, MX, SUM, EX);
    k_rsum<<<cdiv(NN, T), T>>>(SUM, RS, NN);
    edge_agg<1, 8><<<cdiv((long long)ET * 2, T), T>>>(ei, EX, RS, H3, O3);
    bias_elu<<<cdiv(NN * 8, T), T>>>(O3, b3, NN * 8, 7);

    // ---------- final per-edge MLP ----------
    edge_mlp<<<cdiv(EE, T), T>>>(ei, O3, ea, yr, qt, fc1w, fc1b, fc2w, fc2b, out);
}

// round 5
// speedup vs baseline: 1.5912x; 1.5912x over previous
#include <cuda_runtime.h>
#include <math.h>

#define NN 50000
#define EE 400000
#define ET 450000           // EE + NN self loops
#define NEG 0.2f

// ---------------- scratch (static device globals; no allocs) ----------------
__device__ float g_H1[(size_t)NN * 512];
__device__ float g_O1[(size_t)NN * 512];
__device__ float g_H2[(size_t)NN * 128];
__device__ float g_O2[(size_t)NN * 128];
__device__ float g_H3[NN * 8];
__device__ float g_O3[NN * 8];
__device__ float g_S [NN * 4];
__device__ float g_D [NN * 4];
__device__ float g_SUM[NN * 4];
__device__ float g_RS [NN * 4];
__device__ float g_EX[(size_t)ET * 4];

// ---------------- helpers ----------------
__device__ __forceinline__ void edge_sd(const int* __restrict__ ei, int e, int& s, int& d) {
    if (e < EE) { s = ei[e]; d = ei[EE + e]; }
    else        { s = d = e - EE; }           // self loop
}
__device__ __forceinline__ float lrelu(float v) { return v > 0.f ? v : NEG * v; }

// vectorized global reduction (sm_90+): 1 instruction, 16B
__device__ __forceinline__ void red4(float* p, float x, float y, float z, float w) {
    asm volatile("red.global.add.v4.f32 [%0], {%1,%2,%3,%4};"
                 :: "l"(p), "f"(x), "f"(y), "f"(z), "f"(w) : "memory");
}

// ---------------- SGEMM:  C[m,n] = sum_k A[m,k]*B[n,k]  (A:[M,K], B:[N,K]) ----------------
// 128x128 block tile, BK=8, 256 threads, 8x8 per thread. N%128==0, K%8==0 assumed.
__global__ void __launch_bounds__(256) gemm128(const float* __restrict__ A,
                                               const float* __restrict__ B,
                                               float* __restrict__ C,
                                               int M, int N, int K) {
    __shared__ float As[8][132];
    __shared__ float Bs[8][132];
    int bm = blockIdx.y * 128, bn = blockIdx.x * 128;
    int tid = threadIdx.x;
    int lr = tid >> 1;            // 0..127
    int lc = (tid & 1) * 4;       // 0 or 4
    int tx = tid & 15, ty = tid >> 4;
    bool aval = (bm + lr) < M;
    const float* Ap = A + (size_t)(aval ? bm + lr : M - 1) * K + lc;
    const float* Bp = B + (size_t)(bn + lr) * K + lc;
    float acc[8][8] = {};
    for (int k0 = 0; k0 < K; k0 += 8) {
        float4 av = *(const float4*)(Ap + k0);
        if (!aval) av = make_float4(0.f, 0.f, 0.f, 0.f);
        As[lc + 0][lr] = av.x; As[lc + 1][lr] = av.y; As[lc + 2][lr] = av.z; As[lc + 3][lr] = av.w;
        float4 bv = *(const float4*)(Bp + k0);
        Bs[lc + 0][lr] = bv.x; Bs[lc + 1][lr] = bv.y; Bs[lc + 2][lr] = bv.z; Bs[lc + 3][lr] = bv.w;
        __syncthreads();
#pragma unroll
        for (int kk = 0; kk < 8; kk++) {
            float4 a0 = *(const float4*)&As[kk][ty * 8];
            float4 a1 = *(const float4*)&As[kk][ty * 8 + 4];
            float4 b0 = *(const float4*)&Bs[kk][tx * 8];
            float4 b1 = *(const float4*)&Bs[kk][tx * 8 + 4];
            float ar[8] = {a0.x, a0.y, a0.z, a0.w, a1.x, a1.y, a1.z, a1.w};
            float br[8] = {b0.x, b0.y, b0.z, b0.w, b1.x, b1.y, b1.z, b1.w};
#pragma unroll
            for (int i = 0; i < 8; i++)
#pragma unroll
                for (int j = 0; j < 8; j++) acc[i][j] += ar[i] * br[j];
        }
        __syncthreads();
    }
#pragma unroll
    for (int i = 0; i < 8; i++) {
        int r = bm + ty * 8 + i;
        if (r < M) {
            float* c = C + (size_t)r * N + bn + tx * 8;
            *(float4*)(c + 0) = make_float4(acc[i][0], acc[i][1], acc[i][2], acc[i][3]);
            *(float4*)(c + 4) = make_float4(acc[i][4], acc[i][5], acc[i][6], acc[i][7]);
        }
    }
}

// ---------------- layer-3 linear: warp per node, 8 outputs ----------------
__global__ void h3gemm(const float* __restrict__ A, const float* __restrict__ W,
                       float* __restrict__ C) {
    int gt = blockIdx.x * blockDim.x + threadIdx.x;
    int w = gt >> 5, lane = gt & 31;
    if (w >= NN) return;
    float4 a = *(const float4*)(A + (size_t)w * 128 + lane * 4);
    float r[8];
#pragma unroll
    for (int j = 0; j < 8; j++) {
        float4 wv = *(const float4*)(W + j * 128 + lane * 4);
        float p = a.x * wv.x + a.y * wv.y + a.z * wv.z + a.w * wv.w;
#pragma unroll
        for (int o = 16; o; o >>= 1) p += __shfl_xor_sync(0xffffffffu, p, o);
        r[j] = p;
    }
    if (lane == 0) {
        *(float4*)(C + w * 8 + 0) = make_float4(r[0], r[1], r[2], r[3]);
        *(float4*)(C + w * 8 + 4) = make_float4(r[4], r[5], r[6], r[7]);
    }
}

// ---------------- per-node attention scalars ----------------
template <int H, int C>
__global__ void attscore(const float* __restrict__ Hb,
                         const float* __restrict__ as_, const float* __restrict__ ad_,
                         float* __restrict__ S, float* __restrict__ D) {
    int gt = blockIdx.x * blockDim.x + threadIdx.x;
    int w = gt >> 5, lane = gt & 31;
    if (w >= NN * H) return;
    int n = w / H, h = w - n * H;
    const float* row = Hb + (size_t)n * (H * C) + h * C;
    float s = 0.f, d = 0.f;
    for (int c = lane * 4; c < C; c += 128) {
        float4 v = *(const float4*)(row + c);
        float4 a = *(const float4*)(as_ + h * C + c);
        float4 b = *(const float4*)(ad_ + h * C + c);
        s += v.x * a.x + v.y * a.y + v.z * a.z + v.w * a.w;
        d += v.x * b.x + v.y * b.y + v.z * b.z + v.w * b.w;
    }
#pragma unroll
    for (int o = 16; o; o >>= 1) {
        s += __shfl_xor_sync(0xffffffffu, s, o);
        d += __shfl_xor_sync(0xffffffffu, d, o);
    }
    if (lane == 0) { S[n * H + h] = s; D[n * H + h] = d; }
}

// ---------------- inits ----------------
__global__ void k_init(float4* __restrict__ O, int no4, float* __restrict__ SUM, int nmh) {
    int i = blockIdx.x * blockDim.x + threadIdx.x;
    if (i < no4) O[i] = make_float4(0.f, 0.f, 0.f, 0.f);
    if (i < nmh) SUM[i] = 0.f;
}

// ---------------- softmax numerator + denominator (no max: logits bounded) ----------------
__global__ void edge_sum4(const int* __restrict__ ei,
                          const float* __restrict__ S, const float* __restrict__ D,
                          float* __restrict__ SUM, float* __restrict__ EX) {
    int e = blockIdx.x * blockDim.x + threadIdx.x;
    if (e >= ET) return;
    int s, d; edge_sd(ei, e, s, d);
    float4 sv = *(const float4*)(S + s * 4);
    float4 dv = *(const float4*)(D + d * 4);
    float e0 = __expf(lrelu(sv.x + dv.x));
    float e1 = __expf(lrelu(sv.y + dv.y));
    float e2 = __expf(lrelu(sv.z + dv.z));
    float e3 = __expf(lrelu(sv.w + dv.w));
    *(float4*)(EX + (size_t)e * 4) = make_float4(e0, e1, e2, e3);
    red4(SUM + d * 4, e0, e1, e2, e3);
}

__global__ void edge_sum1(const int* __restrict__ ei,
                          const float* __restrict__ S, const float* __restrict__ D,
                          float* __restrict__ SUM, float* __restrict__ EX) {
    int e = blockIdx.x * blockDim.x + threadIdx.x;
    if (e >= ET) return;
    int s, d; edge_sd(ei, e, s, d);
    float ex = __expf(lrelu(S[s] + D[d]));
    EX[e] = ex;
    atomicAdd(&SUM[d], ex);
}

__global__ void k_rsum(const float* __restrict__ SUM, float* __restrict__ RS, int n) {
    int i = blockIdx.x * blockDim.x + threadIdx.x;
    if (i < n) RS[i] = __frcp_rn(SUM[i]);
}

// ---------------- aggregation: O[dst] += alpha * H[src] ----------------
// layer 1: H=4, C=128 -> warp per edge, 4 float4 per lane
__global__ void edge_agg1(const int* __restrict__ ei,
                          const float* __restrict__ EX, const float* __restrict__ RS,
                          const float* __restrict__ Hb, float* __restrict__ O) {
    int gt = blockIdx.x * blockDim.x + threadIdx.x;
    int w = gt >> 5, lane = gt & 31;
    if (w >= ET) return;
    int s, d; edge_sd(ei, w, s, d);
    float4 exv = *(const float4*)(EX + (size_t)w * 4);
    float4 rsv = *(const float4*)(RS + d * 4);
    float al[4] = {exv.x * rsv.x, exv.y * rsv.y, exv.z * rsv.z, exv.w * rsv.w};
    const float* hs = Hb + (size_t)s * 512;
    float* o = O + (size_t)d * 512;
#pragma unroll
    for (int i = 0; i < 4; i++) {
        int f = (lane + 32 * i) * 4;      // head = i
        float4 v = *(const float4*)(hs + f);
        red4(o + f, al[i] * v.x, al[i] * v.y, al[i] * v.z, al[i] * v.w);
    }
}

// layer 2: H=4, C=32 -> warp per edge, 1 float4 per lane (head = lane/8)
__global__ void edge_agg2(const int* __restrict__ ei,
                          const float* __restrict__ EX, const float* __restrict__ RS,
                          const float* __restrict__ Hb, float* __restrict__ O) {
    int gt = blockIdx.x * blockDim.x + threadIdx.x;
    int w = gt >> 5, lane = gt & 31;
    if (w >= ET) return;
    int s, d; edge_sd(ei, w, s, d);
    float4 exv = *(const float4*)(EX + (size_t)w * 4);
    float4 rsv = *(const float4*)(RS + d * 4);
    int hs = lane >> 3;
    float a = hs == 0 ? exv.x * rsv.x : hs == 1 ? exv.y * rsv.y
            : hs == 2 ? exv.z * rsv.z : exv.w * rsv.w;
    int f = lane * 4;
    float4 v = *(const float4*)(Hb + (size_t)s * 128 + f);
    red4(O + (size_t)d * 128 + f, a * v.x, a * v.y, a * v.z, a * v.w);
}

// layer 3: H=1, C=8 -> thread per edge
__global__ void edge_agg3(const int* __restrict__ ei,
                          const float* __restrict__ EX, const float* __restrict__ RS,
                          const float* __restrict__ Hb, float* __restrict__ O) {
    int e = blockIdx.x * blockDim.x + threadIdx.x;
    if (e >= ET) return;
    int s, d; edge_sd(ei, e, s, d);
    float a = EX[e] * RS[d];
    float4 v0 = *(const float4*)(Hb + s * 8 + 0);
    float4 v1 = *(const float4*)(Hb + s * 8 + 4);
    red4(O + d * 8 + 0, a * v0.x, a * v0.y, a * v0.z, a * v0.w);
    red4(O + d * 8 + 4, a * v1.x, a * v1.y, a * v1.z, a * v1.w);
}

// ---------------- bias + ELU (vectorized, in place) ----------------
__global__ void bias_elu4(float4* __restrict__ O, const float* __restrict__ b,
                          int n4, int mask) {
    int i = blockIdx.x * blockDim.x + threadIdx.x;
    if (i >= n4) return;
    float4 v = O[i];
    float4 bb = *(const float4*)(b + ((i * 4) & mask));
    v.x += bb.x; v.y += bb.y; v.z += bb.z; v.w += bb.w;
    v.x = v.x > 0.f ? v.x : expm1f(v.x);
    v.y = v.y > 0.f ? v.y : expm1f(v.y);
    v.z = v.z > 0.f ? v.z : expm1f(v.z);
    v.w = v.w > 0.f ? v.w : expm1f(v.w);
    O[i] = v;
}

// ---------------- final per-edge MLP ----------------
__global__ void edge_mlp(const int* __restrict__ ei, const float* __restrict__ h3,
                         const float* __restrict__ ea, const float* __restrict__ yr,
                         const float* __restrict__ qt,
                         const float* __restrict__ fc1w, const float* __restrict__ fc1b,
                         const float* __restrict__ fc2w, const float* __restrict__ fc2b,
                         float* __restrict__ out) {
    __shared__ float w1[16 * 19];
    __shared__ float b1s[16];
    __shared__ float w2[16];
    int tid = threadIdx.x;
    for (int i = tid; i < 16 * 19; i += blockDim.x) w1[i] = fc1w[i];
    if (tid < 16) { b1s[tid] = fc1b[tid]; w2[tid] = fc2w[tid]; }
    __syncthreads();
    int e = blockIdx.x * blockDim.x + tid;
    if (e >= EE) return;
    int s = ei[e], d = ei[EE + e];
    float z[19];
    float4 a0 = *(const float4*)&h3[s * 8 + 0];
    float4 a1 = *(const float4*)&h3[s * 8 + 4];
    float4 c0 = *(const float4*)&h3[d * 8 + 0];
    float4 c1 = *(const float4*)&h3[d * 8 + 4];
    z[0] = a0.x; z[1] = a0.y; z[2] = a0.z; z[3] = a0.w;
    z[4] = a1.x; z[5] = a1.y; z[6] = a1.z; z[7] = a1.w;
    z[8] = c0.x; z[9] = c0.y; z[10] = c0.z; z[11] = c0.w;
    z[12] = c1.x; z[13] = c1.y; z[14] = c1.z; z[15] = c1.w;
    z[16] = ea[e]; z[17] = yr[e]; z[18] = qt[e];
    float acc = fc2b[0];
#pragma unroll
    for (int o = 0; o < 16; o++) {
        float t = b1s[o];
#pragma unroll
        for (int i = 0; i < 19; i++) t += w1[o * 19 + i] * z[i];
        t = fmaxf(t, 0.f);
        acc += t * w2[o];
    }
    out[e] = acc;
}

// ---------------- host driver ----------------
static inline int cdiv(long long a, int b) { return (int)((a + b - 1) / b); }

extern "C" void kernel_launch(void* const* d_in, const int* in_sizes, int n_in,
                              void* d_out, int out_size) {
    (void)in_sizes; (void)n_in; (void)out_size;
    const float* x    = (const float*)d_in[0];
    const int*   ei   = (const int*)  d_in[1];
    const float* ea   = (const float*)d_in[2];
    const float* yr   = (const float*)d_in[3];
    const float* qt   = (const float*)d_in[4];
    const float* W1   = (const float*)d_in[5];
    const float* a1s  = (const float*)d_in[6];
    const float* a1d  = (const float*)d_in[7];
    const float* b1   = (const float*)d_in[8];
    const float* W2   = (const float*)d_in[9];
    const float* a2s  = (const float*)d_in[10];
    const float* a2d  = (const float*)d_in[11];
    const float* b2   = (const float*)d_in[12];
    const float* W3   = (const float*)d_in[13];
    const float* a3s  = (const float*)d_in[14];
    const float* a3d  = (const float*)d_in[15];
    const float* b3   = (const float*)d_in[16];
    const float* fc1w = (const float*)d_in[17];
    const float* fc1b = (const float*)d_in[18];
    const float* fc2w = (const float*)d_in[19];
    const float* fc2b = (const float*)d_in[20];
    float* out = (float*)d_out;

    float *H1, *O1, *H2, *O2, *H3, *O3, *S, *D, *SUM, *RS, *EX;
    cudaGetSymbolAddress((void**)&H1, g_H1);
    cudaGetSymbolAddress((void**)&O1, g_O1);
    cudaGetSymbolAddress((void**)&H2, g_H2);
    cudaGetSymbolAddress((void**)&O2, g_O2);
    cudaGetSymbolAddress((void**)&H3, g_H3);
    cudaGetSymbolAddress((void**)&O3, g_O3);
    cudaGetSymbolAddress((void**)&S,  g_S);
    cudaGetSymbolAddress((void**)&D,  g_D);
    cudaGetSymbolAddress((void**)&SUM, g_SUM);
    cudaGetSymbolAddress((void**)&RS, g_RS);
    cudaGetSymbolAddress((void**)&EX, g_EX);

    const int T = 256;

    // ---------- layer 1: 128 -> 4 x 128 ----------
    gemm128<<<dim3(512 / 128, cdiv(NN, 128)), T>>>(x, W1, H1, NN, 512, 128);
    attscore<4, 128><<<cdiv((long long)NN * 4 * 32, T), T>>>(H1, a1s, a1d, S, D);
    k_init<<<cdiv((long long)NN * 128, T), T>>>((float4*)O1, NN * 128, SUM, NN * 4);
    edge_sum4<<<cdiv(ET, T), T>>>(ei, S, D, SUM, EX);
    k_rsum<<<cdiv(NN * 4, T), T>>>(SUM, RS, NN * 4);
    edge_agg1<<<cdiv((long long)ET * 32, T), T>>>(ei, EX, RS, H1, O1);
    bias_elu4<<<cdiv((long long)NN * 128, T), T>>>((float4*)O1, b1, NN * 128, 511);

    // ---------- layer 2: 512 -> 4 x 32 ----------
    gemm128<<<dim3(128 / 128, cdiv(NN, 128)), T>>>(O1, W2, H2, NN, 128, 512);
    attscore<4, 32><<<cdiv((long long)NN * 4 * 32, T), T>>>(H2, a2s, a2d, S, D);
    k_init<<<cdiv((long long)NN * 32, T), T>>>((float4*)O2, NN * 32, SUM, NN * 4);
    edge_sum4<<<cdiv(ET, T), T>>>(ei, S, D, SUM, EX);
    k_rsum<<<cdiv(NN * 4, T), T>>>(SUM, RS, NN * 4);
    edge_agg2<<<cdiv((long long)ET * 32, T), T>>>(ei, EX, RS, H2, O2);
    bias_elu4<<<cdiv((long long)NN * 32, T), T>>>((float4*)O2, b2, NN * 32, 127);

    // ---------- layer 3: 128 -> 1 x 8 ----------
    h3gemm<<<cdiv((long long)NN * 32, T), T>>>(O2, W3, H3);
    attscore<1, 8><<<cdiv((long long)NN * 32, T), T>>>(H3, a3s, a3d, S, D);
    k_init<<<cdiv(NN * 2, T), T>>>((float4*)O3, NN * 2, SUM, NN);
    edge_sum1<<<cdiv(ET, T), T>>>(ei, S, D, SUM, EX);
    k_rsum<<<cdiv(NN, T), T>>>(SUM, RS, NN);
    edge_agg3<<<cdiv(ET, T), T>>>(ei, EX, RS, H3, O3);
    bias_elu4<<<cdiv(NN * 2, T), T>>>((float4*)O3, b3, NN * 2, 7);

    // ---------- final per-edge MLP ----------
    edge_mlp<<<cdiv(EE, T), T>>>(ei, O3, ea, yr, qt, fc1w, fc1b, fc2w, fc2b, out);
}

// round 6
// speedup vs baseline: 2.7427x; 1.7236x over previous
#include <cuda_runtime.h>
#include <math.h>

#define NN 50000
#define EE 400000
#define ET 450000           // EE + NN self loops
#define NEG 0.2f

// ---------------- scratch (static device globals; no allocs) ----------------
__device__ float g_H1[(size_t)NN * 512];
__device__ float g_O1[(size_t)NN * 512];
__device__ float g_H2[(size_t)NN * 128];
__device__ float g_O2[(size_t)NN * 128];
__device__ float g_H3[NN * 8];
__device__ float g_O3[NN * 8];
__device__ float g_S [NN * 4];
__device__ float g_D [NN * 4];
__device__ float g_SUM[NN * 4];
__device__ float g_RS [NN * 4];
__device__ float g_EX[(size_t)ET * 4];
// CSR
__device__ int g_cnt[NN];
__device__ int g_ofs[NN];
__device__ int g_cur[NN];
__device__ int g_eix[ET];

// ---------------- helpers ----------------
__device__ __forceinline__ int edge_src(const int* __restrict__ ei, int e) {
    return e < EE ? ei[e] : e - EE;
}
__device__ __forceinline__ int edge_dst(const int* __restrict__ ei, int e) {
    return e < EE ? ei[EE + e] : e - EE;
}
__device__ __forceinline__ float lrelu(float v) { return v > 0.f ? v : NEG * v; }
__device__ __forceinline__ float elu(float v)   { return v > 0.f ? v : expm1f(v); }

__device__ __forceinline__ void red4(float* p, float x, float y, float z, float w) {
    asm volatile("red.global.add.v4.f32 [%0], {%1,%2,%3,%4};"
                 :: "l"(p), "f"(x), "f"(y), "f"(z), "f"(w) : "memory");
}

__device__ __forceinline__ unsigned f2tf(float f) {
    unsigned u;
    asm("cvt.rna.tf32.f32 %0, %1;" : "=r"(u) : "f"(f));
    return u;
}
__device__ __forceinline__ void mma_tf32(float c[4],
                                         unsigned a0, unsigned a1, unsigned a2, unsigned a3,
                                         unsigned b0, unsigned b1) {
    asm volatile("mma.sync.aligned.m16n8k8.row.col.f32.tf32.tf32.f32 "
                 "{%0,%1,%2,%3}, {%4,%5,%6,%7}, {%8,%9}, {%0,%1,%2,%3};"
                 : "+f"(c[0]), "+f"(c[1]), "+f"(c[2]), "+f"(c[3])
                 : "r"(a0), "r"(a1), "r"(a2), "r"(a3), "r"(b0), "r"(b1));
}
__device__ __forceinline__ float4 fma4(float4 acc, float a, float4 v) {
    acc.x = fmaf(a, v.x, acc.x); acc.y = fmaf(a, v.y, acc.y);
    acc.z = fmaf(a, v.z, acc.z); acc.w = fmaf(a, v.w, acc.w);
    return acc;
}

// ---------------- tf32 tensor-core GEMM: C[m,n] = sum_k A[m,k]*B[n,k] ----------------
// A:[M,K] row-major, B:[N,K] row-major (= col-major KxN for mma .col).
// Block tile 128x64, BK=32, 256 threads (8 warps, 4x2), warp tile 32x32.
__global__ void __launch_bounds__(256) gemm_tf32(const float* __restrict__ A,
                                                 const float* __restrict__ B,
                                                 float* __restrict__ C,
                                                 int M, int N, int K) {
    __shared__ unsigned As[128][36];
    __shared__ unsigned Bs[64][36];
    int bm = blockIdx.y * 128, bn = blockIdx.x * 64;
    int tid = threadIdx.x;
    int wid = tid >> 5, lane = tid & 31;
    int wm = (wid >> 1) * 32, wn = (wid & 1) * 32;
    int g = lane >> 2, t = lane & 3;
    float c[2][4][4] = {};
    for (int k0 = 0; k0 < K; k0 += 32) {
#pragma unroll
        for (int p = 0; p < 4; p++) {               // A tile: 128x32
            int idx = p * 256 + tid;
            int r = idx >> 3, c4 = (idx & 7) * 4;
            int row = bm + r;
            float4 v = make_float4(0.f, 0.f, 0.f, 0.f);
            if (row < M) v = *(const float4*)(A + (size_t)row * K + k0 + c4);
            As[r][c4 + 0] = f2tf(v.x); As[r][c4 + 1] = f2tf(v.y);
            As[r][c4 + 2] = f2tf(v.z); As[r][c4 + 3] = f2tf(v.w);
        }
#pragma unroll
        for (int p = 0; p < 2; p++) {               // B tile: 64x32
            int idx = p * 256 + tid;
            int r = idx >> 3, c4 = (idx & 7) * 4;
            float4 v = *(const float4*)(B + (size_t)(bn + r) * K + k0 + c4);
            Bs[r][c4 + 0] = f2tf(v.x); Bs[r][c4 + 1] = f2tf(v.y);
            Bs[r][c4 + 2] = f2tf(v.z); Bs[r][c4 + 3] = f2tf(v.w);
        }
        __syncthreads();
#pragma unroll
        for (int kk = 0; kk < 4; kk++) {
            int kc = kk * 8 + t;
            unsigned a[2][4], bf[4][2];
#pragma unroll
            for (int im = 0; im < 2; im++) {
                int r0 = wm + im * 16 + g;
                a[im][0] = As[r0][kc];     a[im][1] = As[r0 + 8][kc];
                a[im][2] = As[r0][kc + 4]; a[im][3] = As[r0 + 8][kc + 4];
            }
#pragma unroll
            for (int jn = 0; jn < 4; jn++) {
                int n0 = wn + jn * 8 + g;
                bf[jn][0] = Bs[n0][kc]; bf[jn][1] = Bs[n0][kc + 4];
            }
#pragma unroll
            for (int im = 0; im < 2; im++)
#pragma unroll
                for (int jn = 0; jn < 4; jn++)
                    mma_tf32(c[im][jn], a[im][0], a[im][1], a[im][2], a[im][3],
                             bf[jn][0], bf[jn][1]);
        }
        __syncthreads();
    }
#pragma unroll
    for (int im = 0; im < 2; im++) {
        int r0 = bm + wm + im * 16 + g;
#pragma unroll
        for (int jn = 0; jn < 4; jn++) {
            int col = bn + wn + jn * 8 + 2 * t;
            if (r0 < M)
                *(float2*)(C + (size_t)r0 * N + col) = make_float2(c[im][jn][0], c[im][jn][1]);
            if (r0 + 8 < M)
                *(float2*)(C + (size_t)(r0 + 8) * N + col) = make_float2(c[im][jn][2], c[im][jn][3]);
        }
    }
}

// ---------------- layer-3 linear: warp per node, 8 outputs ----------------
__global__ void h3gemm(const float* __restrict__ A, const float* __restrict__ W,
                       float* __restrict__ C) {
    int gt = blockIdx.x * blockDim.x + threadIdx.x;
    int w = gt >> 5, lane = gt & 31;
    if (w >= NN) return;
    float4 a = *(const float4*)(A + (size_t)w * 128 + lane * 4);
    float r[8];
#pragma unroll
    for (int j = 0; j < 8; j++) {
        float4 wv = *(const float4*)(W + j * 128 + lane * 4);
        float p = a.x * wv.x + a.y * wv.y + a.z * wv.z + a.w * wv.w;
#pragma unroll
        for (int o = 16; o; o >>= 1) p += __shfl_xor_sync(0xffffffffu, p, o);
        r[j] = p;
    }
    if (lane == 0) {
        *(float4*)(C + w * 8 + 0) = make_float4(r[0], r[1], r[2], r[3]);
        *(float4*)(C + w * 8 + 4) = make_float4(r[4], r[5], r[6], r[7]);
    }
}

// ---------------- per-node attention scalars ----------------
template <int H, int C>
__global__ void attscore(const float* __restrict__ Hb,
                         const float* __restrict__ as_, const float* __restrict__ ad_,
                         float* __restrict__ S, float* __restrict__ D) {
    int gt = blockIdx.x * blockDim.x + threadIdx.x;
    int w = gt >> 5, lane = gt & 31;
    if (w >= NN * H) return;
    int n = w / H, h = w - n * H;
    const float* row = Hb + (size_t)n * (H * C) + h * C;
    float s = 0.f, d = 0.f;
    for (int c = lane * 4; c < C; c += 128) {
        float4 v = *(const float4*)(row + c);
        float4 a = *(const float4*)(as_ + h * C + c);
        float4 b = *(const float4*)(ad_ + h * C + c);
        s += v.x * a.x + v.y * a.y + v.z * a.z + v.w * a.w;
        d += v.x * b.x + v.y * b.y + v.z * b.z + v.w * b.w;
    }
#pragma unroll
    for (int o = 16; o; o >>= 1) {
        s += __shfl_xor_sync(0xffffffffu, s, o);
        d += __shfl_xor_sync(0xffffffffu, d, o);
    }
    if (lane == 0) { S[n * H + h] = s; D[n * H + h] = d; }
}

// ---------------- CSR build ----------------
__global__ void k_zero(float* __restrict__ p, int n) {
    int i = blockIdx.x * blockDim.x + threadIdx.x;
    if (i < n) p[i] = 0.f;
}
__global__ void k_count(const int* __restrict__ ei, int* __restrict__ cnt) {
    int e = blockIdx.x * blockDim.x + threadIdx.x;
    if (e >= ET) return;
    atomicAdd(&cnt[edge_dst(ei, e)], 1);
}
__global__ void __launch_bounds__(1024) k_scan(const int* __restrict__ cnt,
                                               int* __restrict__ ofs, int* __restrict__ cur) {
    __shared__ int sh[1024];
    const int CH = (NN + 1023) / 1024;
    int t = threadIdx.x;
    int base = t * CH, end = base + CH < NN ? base + CH : NN;
    int s = 0;
    for (int i = base; i < end; i++) s += cnt[i];
    sh[t] = s;
    __syncthreads();
    for (int off = 1; off < 1024; off <<= 1) {
        int v = t >= off ? sh[t - off] : 0;
        __syncthreads();
        sh[t] += v;
        __syncthreads();
    }
    int run = t ? sh[t - 1] : 0;
    for (int i = base; i < end; i++) {
        ofs[i] = run; cur[i] = run;
        run += cnt[i];
    }
}
__global__ void k_scatter(const int* __restrict__ ei, int* __restrict__ cur,
                          int* __restrict__ eix) {
    int e = blockIdx.x * blockDim.x + threadIdx.x;
    if (e >= ET) return;
    int pos = atomicAdd(&cur[edge_dst(ei, e)], 1);
    eix[pos] = e;
}

// ---------------- softmax numerator + denominator (logits bounded; no max) ----------------
__global__ void edge_sum4(const int* __restrict__ ei,
                          const float* __restrict__ S, const float* __restrict__ D,
                          float* __restrict__ SUM, float* __restrict__ EX) {
    int e = blockIdx.x * blockDim.x + threadIdx.x;
    if (e >= ET) return;
    int s = edge_src(ei, e), d = edge_dst(ei, e);
    float4 sv = *(const float4*)(S + s * 4);
    float4 dv = *(const float4*)(D + d * 4);
    float e0 = __expf(lrelu(sv.x + dv.x));
    float e1 = __expf(lrelu(sv.y + dv.y));
    float e2 = __expf(lrelu(sv.z + dv.z));
    float e3 = __expf(lrelu(sv.w + dv.w));
    *(float4*)(EX + (size_t)e * 4) = make_float4(e0, e1, e2, e3);
    red4(SUM + d * 4, e0, e1, e2, e3);
}
__global__ void edge_sum1(const int* __restrict__ ei,
                          const float* __restrict__ S, const float* __restrict__ D,
                          float* __restrict__ SUM, float* __restrict__ EX) {
    int e = blockIdx.x * blockDim.x + threadIdx.x;
    if (e >= ET) return;
    int s = edge_src(ei, e), d = edge_dst(ei, e);
    float ex = __expf(lrelu(S[s] + D[d]));
    EX[e] = ex;
    atomicAdd(&SUM[d], ex);
}
__global__ void k_rsum(const float* __restrict__ SUM, float* __restrict__ RS, int n) {
    int i = blockIdx.x * blockDim.x + threadIdx.x;
    if (i < n) RS[i] = __frcp_rn(SUM[i]);
}

// ---------------- CSR gather aggregation (+bias+ELU fused) ----------------
// layer 1: H=4, C=128; warp per node, lane owns float4 j at f4idx = lane + 32j (head j)
__global__ void agg1(const int* __restrict__ ei, const int* __restrict__ ofs,
                     const int* __restrict__ cnt, const int* __restrict__ eix,
                     const float* __restrict__ EX, const float* __restrict__ RS,
                     const float* __restrict__ Hb, const float* __restrict__ b,
                     float* __restrict__ O) {
    int gt = blockIdx.x * blockDim.x + threadIdx.x;
    int n = gt >> 5, lane = gt & 31;
    if (n >= NN) return;
    float4 rs = *(const float4*)(RS + n * 4);
    int st = ofs[n], deg = cnt[n];
    float4 acc0 = {0, 0, 0, 0}, acc1 = {0, 0, 0, 0}, acc2 = {0, 0, 0, 0}, acc3 = {0, 0, 0, 0};
    for (int i = 0; i < deg; i++) {
        int e = eix[st + i];
        int s = edge_src(ei, e);
        float4 ex = *(const float4*)(EX + (size_t)e * 4);
        float a0 = ex.x * rs.x, a1 = ex.y * rs.y, a2 = ex.z * rs.z, a3 = ex.w * rs.w;
        const float4* hs = (const float4*)(Hb + (size_t)s * 512);
        acc0 = fma4(acc0, a0, hs[lane]);
        acc1 = fma4(acc1, a1, hs[lane + 32]);
        acc2 = fma4(acc2, a2, hs[lane + 64]);
        acc3 = fma4(acc3, a3, hs[lane + 96]);
    }
    float4* o = (float4*)(O + (size_t)n * 512);
    const float4* bb = (const float4*)b;
    float4 v;
    v = acc0; float4 bv = bb[lane];
    v.x = elu(v.x + bv.x); v.y = elu(v.y + bv.y); v.z = elu(v.z + bv.z); v.w = elu(v.w + bv.w);
    o[lane] = v;
    v = acc1; bv = bb[lane + 32];
    v.x = elu(v.x + bv.x); v.y = elu(v.y + bv.y); v.z = elu(v.z + bv.z); v.w = elu(v.w + bv.w);
    o[lane + 32] = v;
    v = acc2; bv = bb[lane + 64];
    v.x = elu(v.x + bv.x); v.y = elu(v.y + bv.y); v.z = elu(v.z + bv.z); v.w = elu(v.w + bv.w);
    o[lane + 64] = v;
    v = acc3; bv = bb[lane + 96];
    v.x = elu(v.x + bv.x); v.y = elu(v.y + bv.y); v.z = elu(v.z + bv.z); v.w = elu(v.w + bv.w);
    o[lane + 96] = v;
}

// layer 2: H=4, C=32; warp per node, lane owns float4 lane (head = lane>>3)
__global__ void agg2(const int* __restrict__ ei, const int* __restrict__ ofs,
                     const int* __restrict__ cnt, const int* __restrict__ eix,
                     const float* __restrict__ EX, const float* __restrict__ RS,
                     const float* __restrict__ Hb, const float* __restrict__ b,
                     float* __restrict__ O) {
    int gt = blockIdx.x * blockDim.x + threadIdx.x;
    int n = gt >> 5, lane = gt & 31;
    if (n >= NN) return;
    float4 rs = *(const float4*)(RS + n * 4);
    int st = ofs[n], deg = cnt[n];
    int h = lane >> 3;
    float rsh = h == 0 ? rs.x : h == 1 ? rs.y : h == 2 ? rs.z : rs.w;
    float4 acc = {0, 0, 0, 0};
    for (int i = 0; i < deg; i++) {
        int e = eix[st + i];
        int s = edge_src(ei, e);
        float exh = EX[(size_t)e * 4 + h];
        acc = fma4(acc, exh * rsh, ((const float4*)(Hb + (size_t)s * 128))[lane]);
    }
    float4 bv = ((const float4*)b)[lane];
    acc.x = elu(acc.x + bv.x); acc.y = elu(acc.y + bv.y);
    acc.z = elu(acc.z + bv.z); acc.w = elu(acc.w + bv.w);
    ((float4*)(O + (size_t)n * 128))[lane] = acc;
}

// layer 3: H=1, C=8; thread per node
__global__ void agg3(const int* __restrict__ ei, const int* __restrict__ ofs,
                     const int* __restrict__ cnt, const int* __restrict__ eix,
                     const float* __restrict__ EX, const float* __restrict__ RS,
                     const float* __restrict__ Hb, const float* __restrict__ b,
                     float* __restrict__ O) {
    int n = blockIdx.x * blockDim.x + threadIdx.x;
    if (n >= NN) return;
    float rs = RS[n];
    int st = ofs[n], deg = cnt[n];
    float4 acc0 = {0, 0, 0, 0}, acc1 = {0, 0, 0, 0};
    for (int i = 0; i < deg; i++) {
        int e = eix[st + i];
        int s = edge_src(ei, e);
        float a = EX[e] * rs;
        acc0 = fma4(acc0, a, *(const float4*)(Hb + s * 8));
        acc1 = fma4(acc1, a, *(const float4*)(Hb + s * 8 + 4));
    }
    float4 b0 = *(const float4*)(b), b1 = *(const float4*)(b + 4);
    acc0.x = elu(acc0.x + b0.x); acc0.y = elu(acc0.y + b0.y);
    acc0.z = elu(acc0.z + b0.z); acc0.w = elu(acc0.w + b0.w);
    acc1.x = elu(acc1.x + b1.x); acc1.y = elu(acc1.y + b1.y);
    acc1.z = elu(acc1.z + b1.z); acc1.w = elu(acc1.w + b1.w);
    *(float4*)(O + n * 8) = acc0;
    *(float4*)(O + n * 8 + 4) = acc1;
}

// ---------------- final per-edge MLP ----------------
__global__ void edge_mlp(const int* __restrict__ ei, const float* __restrict__ h3,
                         const float* __restrict__ ea, const float* __restrict__ yr,
                         const float* __restrict__ qt,
                         const float* __restrict__ fc1w, const float* __restrict__ fc1b,
                         const float* __restrict__ fc2w, const float* __restrict__ fc2b,
                         float* __restrict__ out) {
    __shared__ float w1[16 * 19];
    __shared__ float b1s[16];
    __shared__ float w2[16];
    int tid = threadIdx.x;
    for (int i = tid; i < 16 * 19; i += blockDim.x) w1[i] = fc1w[i];
    if (tid < 16) { b1s[tid] = fc1b[tid]; w2[tid] = fc2w[tid]; }
    __syncthreads();
    int e = blockIdx.x * blockDim.x + tid;
    if (e >= EE) return;
    int s = ei[e], d = ei[EE + e];
    float z[19];
    float4 a0 = *(const float4*)&h3[s * 8 + 0];
    float4 a1 = *(const float4*)&h3[s * 8 + 4];
    float4 c0 = *(const float4*)&h3[d * 8 + 0];
    float4 c1 = *(const float4*)&h3[d * 8 + 4];
    z[0] = a0.x; z[1] = a0.y; z[2] = a0.z; z[3] = a0.w;
    z[4] = a1.x; z[5] = a1.y; z[6] = a1.z; z[7] = a1.w;
    z[8] = c0.x; z[9] = c0.y; z[10] = c0.z; z[11] = c0.w;
    z[12] = c1.x; z[13] = c1.y; z[14] = c1.z; z[15] = c1.w;
    z[16] = ea[e]; z[17] = yr[e]; z[18] = qt[e];
    float acc = fc2b[0];
#pragma unroll
    for (int o = 0; o < 16; o++) {
        float t = b1s[o];
#pragma unroll
        for (int i = 0; i < 19; i++) t += w1[o * 19 + i] * z[i];
        t = fmaxf(t, 0.f);
        acc += t * w2[o];
    }
    out[e] = acc;
}

// ---------------- host driver ----------------
static inline int cdiv(long long a, int b) { return (int)((a + b - 1) / b); }

extern "C" void kernel_launch(void* const* d_in, const int* in_sizes, int n_in,
                              void* d_out, int out_size) {
    (void)in_sizes; (void)n_in; (void)out_size;
    const float* x    = (const float*)d_in[0];
    const int*   ei   = (const int*)  d_in[1];
    const float* ea   = (const float*)d_in[2];
    const float* yr   = (const float*)d_in[3];
    const float* qt   = (const float*)d_in[4];
    const float* W1   = (const float*)d_in[5];
    const float* a1s  = (const float*)d_in[6];
    const float* a1d  = (const float*)d_in[7];
    const float* b1   = (const float*)d_in[8];
    const float* W2   = (const float*)d_in[9];
    const float* a2s  = (const float*)d_in[10];
    const float* a2d  = (const float*)d_in[11];
    const float* b2   = (const float*)d_in[12];
    const float* W3   = (const float*)d_in[13];
    const float* a3s  = (const float*)d_in[14];
    const float* a3d  = (const float*)d_in[15];
    const float* b3   = (const float*)d_in[16];
    const float* fc1w = (const float*)d_in[17];
    const float* fc1b = (const float*)d_in[18];
    const float* fc2w = (const float*)d_in[19];
    const float* fc2b = (const float*)d_in[20];
    float* out = (float*)d_out;

    float *H1, *O1, *H2, *O2, *H3, *O3, *S, *D, *SUM, *RS, *EX;
    int *cnt, *ofs, *cur, *eix;
    cudaGetSymbolAddress((void**)&H1, g_H1);
    cudaGetSymbolAddress((void**)&O1, g_O1);
    cudaGetSymbolAddress((void**)&H2, g_H2);
    cudaGetSymbolAddress((void**)&O2, g_O2);
    cudaGetSymbolAddress((void**)&H3, g_H3);
    cudaGetSymbolAddress((void**)&O3, g_O3);
    cudaGetSymbolAddress((void**)&S,  g_S);
    cudaGetSymbolAddress((void**)&D,  g_D);
    cudaGetSymbolAddress((void**)&SUM, g_SUM);
    cudaGetSymbolAddress((void**)&RS, g_RS);
    cudaGetSymbolAddress((void**)&EX, g_EX);
    cudaGetSymbolAddress((void**)&cnt, g_cnt);
    cudaGetSymbolAddress((void**)&ofs, g_ofs);
    cudaGetSymbolAddress((void**)&cur, g_cur);
    cudaGetSymbolAddress((void**)&eix, g_eix);

    const int T = 256;

    // ---------- CSR build ----------
    k_zero<<<cdiv(NN, T), T>>>((float*)cnt, NN);
    k_count<<<cdiv(ET, T), T>>>(ei, cnt);
    k_scan<<<1, 1024>>>(cnt, ofs, cur);
    k_scatter<<<cdiv(ET, T), T>>>(ei, cur, eix);

    // ---------- layer 1: 128 -> 4 x 128 ----------
    gemm_tf32<<<dim3(512 / 64, cdiv(NN, 128)), T>>>(x, W1, H1, NN, 512, 128);
    attscore<4, 128><<<cdiv((long long)NN * 4 * 32, T), T>>>(H1, a1s, a1d, S, D);
    k_zero<<<cdiv(NN * 4, T), T>>>(SUM, NN * 4);
    edge_sum4<<<cdiv(ET, T), T>>>(ei, S, D, SUM, EX);
    k_rsum<<<cdiv(NN * 4, T), T>>>(SUM, RS, NN * 4);
    agg1<<<cdiv((long long)NN * 32, T), T>>>(ei, ofs, cnt, eix, EX, RS, H1, b1, O1);

    // ---------- layer 2: 512 -> 4 x 32 ----------
    gemm_tf32<<<dim3(128 / 64, cdiv(NN, 128)), T>>>(O1, W2, H2, NN, 128, 512);
    attscore<4, 32><<<cdiv((long long)NN * 4 * 32, T), T>>>(H2, a2s, a2d, S, D);
    k_zero<<<cdiv(NN * 4, T), T>>>(SUM, NN * 4);
    edge_sum4<<<cdiv(ET, T), T>>>(ei, S, D, SUM, EX);
    k_rsum<<<cdiv(NN * 4, T), T>>>(SUM, RS, NN * 4);
    agg2<<<cdiv((long long)NN * 32, T), T>>>(ei, ofs, cnt, eix, EX, RS, H2, b2, O2);

    // ---------- layer 3: 128 -> 1 x 8 ----------
    h3gemm<<<cdiv((long long)NN * 32, T), T>>>(O2, W3, H3);
    attscore<1, 8><<<cdiv((long long)NN * 32, T), T>>>(H3, a3s, a3d, S, D);
    k_zero<<<cdiv(NN, T), T>>>(SUM, NN);
    edge_sum1<<<cdiv(ET, T), T>>>(ei, S, D, SUM, EX);
    k_rsum<<<cdiv(NN, T), T>>>(SUM, RS, NN);
    agg3<<<cdiv(NN, T), T>>>(ei, ofs, cnt, eix, EX, RS, H3, b3, O3);

    // ---------- final per-edge MLP ----------
    edge_mlp<<<cdiv(EE, T), T>>>(ei, O3, ea, yr, qt, fc1w, fc1b, fc2w, fc2b, out);
}

// round 7
// speedup vs baseline: 2.7683x; 1.0093x over previous
#include <cuda_runtime.h>
#include <math.h>

#define NN 50000
#define EE 400000
#define ET 450000           // EE + NN self loops
#define NEG 0.2f

// ---------------- scratch (static device globals; no allocs) ----------------
__device__ float g_H1[(size_t)NN * 512];
__device__ float g_O1[(size_t)NN * 512];
__device__ float g_H2[(size_t)NN * 128];
__device__ float g_O2[(size_t)NN * 128];
__device__ float g_H3[NN * 8];
__device__ float g_O3[NN * 8];
__device__ float g_S [NN * 4];
__device__ float g_D [NN * 4];
__device__ float g_SUM[NN * 4];
__device__ float g_RS [NN * 4];
__device__ float g_EX[(size_t)ET * 4];
// CSR
__device__ int g_cnt[NN];
__device__ int g_ofs[NN];
__device__ int g_cur[NN];
__device__ int g_eix[ET];

// ---------------- helpers ----------------
__device__ __forceinline__ int edge_src(const int* __restrict__ ei, int e) {
    return e < EE ? ei[e] : e - EE;
}
__device__ __forceinline__ int edge_dst(const int* __restrict__ ei, int e) {
    return e < EE ? ei[EE + e] : e - EE;
}
__device__ __forceinline__ float lrelu(float v) { return v > 0.f ? v : NEG * v; }
__device__ __forceinline__ float elu(float v)   { return v > 0.f ? v : expm1f(v); }

__device__ __forceinline__ void red4(float* p, float x, float y, float z, float w) {
    asm volatile("red.global.add.v4.f32 [%0], {%1,%2,%3,%4};"
                 :: "l"(p), "f"(x), "f"(y), "f"(z), "f"(w) : "memory");
}

__device__ __forceinline__ void mma_tf32(float c[4],
                                         unsigned a0, unsigned a1, unsigned a2, unsigned a3,
                                         unsigned b0, unsigned b1) {
    asm volatile("mma.sync.aligned.m16n8k8.row.col.f32.tf32.tf32.f32 "
                 "{%0,%1,%2,%3}, {%4,%5,%6,%7}, {%8,%9}, {%0,%1,%2,%3};"
                 : "+f"(c[0]), "+f"(c[1]), "+f"(c[2]), "+f"(c[3])
                 : "r"(a0), "r"(a1), "r"(a2), "r"(a3), "r"(b0), "r"(b1));
}
__device__ __forceinline__ float4 fma4(float4 acc, float a, float4 v) {
    acc.x = fmaf(a, v.x, acc.x); acc.y = fmaf(a, v.y, acc.y);
    acc.z = fmaf(a, v.z, acc.z); acc.w = fmaf(a, v.w, acc.w);
    return acc;
}
__device__ __forceinline__ void cp16(void* smem_dst, const void* gmem_src) {
    unsigned sa = (unsigned)__cvta_generic_to_shared(smem_dst);
    asm volatile("cp.async.ca.shared.global [%0], [%1], 16;" :: "r"(sa), "l"(gmem_src));
}

// ---------------- tf32 tensor-core GEMM: C[m,n] = sum_k A[m,k]*B[n,k] ----------------
// A:[M,K] row-major, B:[N,K] row-major (= col-major for mma .col).
// 128x128 block tile, BK=16, 256 threads (8 warps as 2x4, warp tile 64x32),
// cp.async double-buffered; fp32 bits fed to tf32 mma directly (HW ignores low bits).
__global__ void __launch_bounds__(256) gemm_tf32(const float* __restrict__ A,
                                                 const float* __restrict__ B,
                                                 float* __restrict__ C,
                                                 int M, int N, int K) {
    __shared__ float As[2][128][20];
    __shared__ float Bs[2][128][20];
    int bm = blockIdx.y * 128, bn = blockIdx.x * 128;
    int tid = threadIdx.x;
    int wid = tid >> 5, lane = tid & 31;
    int wm = (wid >> 2) * 64, wn = (wid & 3) * 32;
    int g = lane >> 2, t = lane & 3;

    // load mapping: 512 16B-chunks per tile, 2 per thread
    int lrow0 = tid >> 2, lc4 = (tid & 3) * 4;          // chunk 0: rows 0..63
    int lrow1 = lrow0 + 64;                             // chunk 1: rows 64..127
    int ar0 = bm + lrow0 < M ? bm + lrow0 : M - 1;
    int ar1 = bm + lrow1 < M ? bm + lrow1 : M - 1;

    float acc[4][4][4] = {};

    // prologue: stage 0
    {
        cp16(&As[0][lrow0][lc4], A + (size_t)ar0 * K + lc4);
        cp16(&As[0][lrow1][lc4], A + (size_t)ar1 * K + lc4);
        cp16(&Bs[0][lrow0][lc4], B + (size_t)(bn + lrow0) * K + lc4);
        cp16(&Bs[0][lrow1][lc4], B + (size_t)(bn + lrow1) * K + lc4);
        asm volatile("cp.async.commit_group;");
    }

    int buf = 0;
    for (int k0 = 0; k0 < K; k0 += 16, buf ^= 1) {
        if (k0 + 16 < K) {
            int kn = k0 + 16;
            cp16(&As[buf ^ 1][lrow0][lc4], A + (size_t)ar0 * K + kn + lc4);
            cp16(&As[buf ^ 1][lrow1][lc4], A + (size_t)ar1 * K + kn + lc4);
            cp16(&Bs[buf ^ 1][lrow0][lc4], B + (size_t)(bn + lrow0) * K + kn + lc4);
            cp16(&Bs[buf ^ 1][lrow1][lc4], B + (size_t)(bn + lrow1) * K + kn + lc4);
            asm volatile("cp.async.commit_group;");
            asm volatile("cp.async.wait_group 1;");
        } else {
            asm volatile("cp.async.wait_group 0;");
        }
        __syncthreads();
#pragma unroll
        for (int kk = 0; kk < 2; kk++) {
            int kc = kk * 8 + t;
            unsigned a[4][4], bf[4][2];
#pragma unroll
            for (int im = 0; im < 4; im++) {
                int r0 = wm + im * 16 + g;
                a[im][0] = __float_as_uint(As[buf][r0][kc]);
                a[im][1] = __float_as_uint(As[buf][r0 + 8][kc]);
                a[im][2] = __float_as_uint(As[buf][r0][kc + 4]);
                a[im][3] = __float_as_uint(As[buf][r0 + 8][kc + 4]);
            }
#pragma unroll
            for (int jn = 0; jn < 4; jn++) {
                int n0 = wn + jn * 8 + g;
                bf[jn][0] = __float_as_uint(Bs[buf][n0][kc]);
                bf[jn][1] = __float_as_uint(Bs[buf][n0][kc + 4]);
            }
#pragma unroll
            for (int im = 0; im < 4; im++)
#pragma unroll
                for (int jn = 0; jn < 4; jn++)
                    mma_tf32(acc[im][jn], a[im][0], a[im][1], a[im][2], a[im][3],
                             bf[jn][0], bf[jn][1]);
        }
        __syncthreads();
    }

#pragma unroll
    for (int im = 0; im < 4; im++) {
        int r0 = bm + wm + im * 16 + g;
#pragma unroll
        for (int jn = 0; jn < 4; jn++) {
            int col = bn + wn + jn * 8 + 2 * t;
            if (r0 < M)
                *(float2*)(C + (size_t)r0 * N + col) = make_float2(acc[im][jn][0], acc[im][jn][1]);
            if (r0 + 8 < M)
                *(float2*)(C + (size_t)(r0 + 8) * N + col) = make_float2(acc[im][jn][2], acc[im][jn][3]);
        }
    }
}

// ---------------- layer-3 linear: warp per node, 8 outputs ----------------
__global__ void h3gemm(const float* __restrict__ A, const float* __restrict__ W,
                       float* __restrict__ C) {
    int gt = blockIdx.x * blockDim.x + threadIdx.x;
    int w = gt >> 5, lane = gt & 31;
    if (w >= NN) return;
    float4 a = *(const float4*)(A + (size_t)w * 128 + lane * 4);
    float r[8];
#pragma unroll
    for (int j = 0; j < 8; j++) {
        float4 wv = *(const float4*)(W + j * 128 + lane * 4);
        float p = a.x * wv.x + a.y * wv.y + a.z * wv.z + a.w * wv.w;
#pragma unroll
        for (int o = 16; o; o >>= 1) p += __shfl_xor_sync(0xffffffffu, p, o);
        r[j] = p;
    }
    if (lane == 0) {
        *(float4*)(C + w * 8 + 0) = make_float4(r[0], r[1], r[2], r[3]);
        *(float4*)(C + w * 8 + 4) = make_float4(r[4], r[5], r[6], r[7]);
    }
}

// ---------------- per-node attention scalars ----------------
template <int H, int C>
__global__ void attscore(const float* __restrict__ Hb,
                         const float* __restrict__ as_, const float* __restrict__ ad_,
                         float* __restrict__ S, float* __restrict__ D) {
    int gt = blockIdx.x * blockDim.x + threadIdx.x;
    int w = gt >> 5, lane = gt & 31;
    if (w >= NN * H) return;
    int n = w / H, h = w - n * H;
    const float* row = Hb + (size_t)n * (H * C) + h * C;
    float s = 0.f, d = 0.f;
    for (int c = lane * 4; c < C; c += 128) {
        float4 v = *(const float4*)(row + c);
        float4 a = *(const float4*)(as_ + h * C + c);
        float4 b = *(const float4*)(ad_ + h * C + c);
        s += v.x * a.x + v.y * a.y + v.z * a.z + v.w * a.w;
        d += v.x * b.x + v.y * b.y + v.z * b.z + v.w * b.w;
    }
#pragma unroll
    for (int o = 16; o; o >>= 1) {
        s += __shfl_xor_sync(0xffffffffu, s, o);
        d += __shfl_xor_sync(0xffffffffu, d, o);
    }
    if (lane == 0) { S[n * H + h] = s; D[n * H + h] = d; }
}

// ---------------- CSR build ----------------
__global__ void k_zero(float* __restrict__ p, int n) {
    int i = blockIdx.x * blockDim.x + threadIdx.x;
    if (i < n) p[i] = 0.f;
}
__global__ void k_count(const int* __restrict__ ei, int* __restrict__ cnt) {
    int e = blockIdx.x * blockDim.x + threadIdx.x;
    if (e >= ET) return;
    atomicAdd(&cnt[edge_dst(ei, e)], 1);
}
__global__ void __launch_bounds__(1024) k_scan(const int* __restrict__ cnt,
                                               int* __restrict__ ofs, int* __restrict__ cur) {
    __shared__ int sh[1024];
    const int CH = (NN + 1023) / 1024;
    int t = threadIdx.x;
    int base = t * CH, end = base + CH < NN ? base + CH : NN;
    int s = 0;
    for (int i = base; i < end; i++) s += cnt[i];
    sh[t] = s;
    __syncthreads();
    for (int off = 1; off < 1024; off <<= 1) {
        int v = t >= off ? sh[t - off] : 0;
        __syncthreads();
        sh[t] += v;
        __syncthreads();
    }
    int run = t ? sh[t - 1] : 0;
    for (int i = base; i < end; i++) {
        ofs[i] = run; cur[i] = run;
        run += cnt[i];
    }
}
__global__ void k_scatter(const int* __restrict__ ei, int* __restrict__ cur,
                          int* __restrict__ eix) {
    int e = blockIdx.x * blockDim.x + threadIdx.x;
    if (e >= ET) return;
    int pos = atomicAdd(&cur[edge_dst(ei, e)], 1);
    eix[pos] = e;
}

// ---------------- softmax numerator + denominator (logits bounded; no max) ----------------
__global__ void edge_sum4(const int* __restrict__ ei,
                          const float* __restrict__ S, const float* __restrict__ D,
                          float* __restrict__ SUM, float* __restrict__ EX) {
    int e = blockIdx.x * blockDim.x + threadIdx.x;
    if (e >= ET) return;
    int s = edge_src(ei, e), d = edge_dst(ei, e);
    float4 sv = *(const float4*)(S + s * 4);
    float4 dv = *(const float4*)(D + d * 4);
    float e0 = __expf(lrelu(sv.x + dv.x));
    float e1 = __expf(lrelu(sv.y + dv.y));
    float e2 = __expf(lrelu(sv.z + dv.z));
    float e3 = __expf(lrelu(sv.w + dv.w));
    *(float4*)(EX + (size_t)e * 4) = make_float4(e0, e1, e2, e3);
    red4(SUM + d * 4, e0, e1, e2, e3);
}
__global__ void edge_sum1(const int* __restrict__ ei,
                          const float* __restrict__ S, const float* __restrict__ D,
                          float* __restrict__ SUM, float* __restrict__ EX) {
    int e = blockIdx.x * blockDim.x + threadIdx.x;
    if (e >= ET) return;
    int s = edge_src(ei, e), d = edge_dst(ei, e);
    float ex = __expf(lrelu(S[s] + D[d]));
    EX[e] = ex;
    atomicAdd(&SUM[d], ex);
}
__global__ void k_rsum(const float* __restrict__ SUM, float* __restrict__ RS, int n) {
    int i = blockIdx.x * blockDim.x + threadIdx.x;
    if (i < n) RS[i] = __frcp_rn(SUM[i]);
}

// ---------------- CSR gather aggregation (+bias+ELU fused) ----------------
// layer 1: H=4, C=128; warp per node, lane owns float4 j at f4idx = lane + 32j (head j)
__global__ void agg1(const int* __restrict__ ei, const int* __restrict__ ofs,
                     const int* __restrict__ cnt, const int* __restrict__ eix,
                     const float* __restrict__ EX, const float* __restrict__ RS,
                     const float* __restrict__ Hb, const float* __restrict__ b,
                     float* __restrict__ O) {
    int gt = blockIdx.x * blockDim.x + threadIdx.x;
    int n = gt >> 5, lane = gt & 31;
    if (n >= NN) return;
    float4 rs = *(const float4*)(RS + n * 4);
    int st = ofs[n], deg = cnt[n];
    float4 acc0 = {0, 0, 0, 0}, acc1 = {0, 0, 0, 0}, acc2 = {0, 0, 0, 0}, acc3 = {0, 0, 0, 0};
    for (int i = 0; i < deg; i++) {
        int e = eix[st + i];
        int s = edge_src(ei, e);
        float4 ex = *(const float4*)(EX + (size_t)e * 4);
        float a0 = ex.x * rs.x, a1 = ex.y * rs.y, a2 = ex.z * rs.z, a3 = ex.w * rs.w;
        const float4* hs = (const float4*)(Hb + (size_t)s * 512);
        acc0 = fma4(acc0, a0, hs[lane]);
        acc1 = fma4(acc1, a1, hs[lane + 32]);
        acc2 = fma4(acc2, a2, hs[lane + 64]);
        acc3 = fma4(acc3, a3, hs[lane + 96]);
    }
    float4* o = (float4*)(O + (size_t)n * 512);
    const float4* bb = (const float4*)b;
    float4 v;
    v = acc0; float4 bv = bb[lane];
    v.x = elu(v.x + bv.x); v.y = elu(v.y + bv.y); v.z = elu(v.z + bv.z); v.w = elu(v.w + bv.w);
    o[lane] = v;
    v = acc1; bv = bb[lane + 32];
    v.x = elu(v.x + bv.x); v.y = elu(v.y + bv.y); v.z = elu(v.z + bv.z); v.w = elu(v.w + bv.w);
    o[lane + 32] = v;
    v = acc2; bv = bb[lane + 64];
    v.x = elu(v.x + bv.x); v.y = elu(v.y + bv.y); v.z = elu(v.z + bv.z); v.w = elu(v.w + bv.w);
    o[lane + 64] = v;
    v = acc3; bv = bb[lane + 96];
    v.x = elu(v.x + bv.x); v.y = elu(v.y + bv.y); v.z = elu(v.z + bv.z); v.w = elu(v.w + bv.w);
    o[lane + 96] = v;
}

// layer 2: H=4, C=32; warp per node, lane owns float4 lane (head = lane>>3)
__global__ void agg2(const int* __restrict__ ei, const int* __restrict__ ofs,
                     const int* __restrict__ cnt, const int* __restrict__ eix,
                     const float* __restrict__ EX, const float* __restrict__ RS,
                     const float* __restrict__ Hb, const float* __restrict__ b,
                     float* __restrict__ O) {
    int gt = blockIdx.x * blockDim.x + threadIdx.x;
    int n = gt >> 5, lane = gt & 31;
    if (n >= NN) return;
    float4 rs = *(const float4*)(RS + n * 4);
    int st = ofs[n], deg = cnt[n];
    int h = lane >> 3;
    float rsh = h == 0 ? rs.x : h == 1 ? rs.y : h == 2 ? rs.z : rs.w;
    float4 acc = {0, 0, 0, 0};
    for (int i = 0; i < deg; i++) {
        int e = eix[st + i];
        int s = edge_src(ei, e);
        float exh = EX[(size_t)e * 4 + h];
        acc = fma4(acc, exh * rsh, ((const float4*)(Hb + (size_t)s * 128))[lane]);
    }
    float4 bv = ((const float4*)b)[lane];
    acc.x = elu(acc.x + bv.x); acc.y = elu(acc.y + bv.y);
    acc.z = elu(acc.z + bv.z); acc.w = elu(acc.w + bv.w);
    ((float4*)(O + (size_t)n * 128))[lane] = acc;
}

// layer 3: H=1, C=8; thread per node
__global__ void agg3(const int* __restrict__ ei, const int* __restrict__ ofs,
                     const int* __restrict__ cnt, const int* __restrict__ eix,
                     const float* __restrict__ EX, const float* __restrict__ RS,
                     const float* __restrict__ Hb, const float* __restrict__ b,
                     float* __restrict__ O) {
    int n = blockIdx.x * blockDim.x + threadIdx.x;
    if (n >= NN) return;
    float rs = RS[n];
    int st = ofs[n], deg = cnt[n];
    float4 acc0 = {0, 0, 0, 0}, acc1 = {0, 0, 0, 0};
    for (int i = 0; i < deg; i++) {
        int e = eix[st + i];
        int s = edge_src(ei, e);
        float a = EX[e] * rs;
        acc0 = fma4(acc0, a, *(const float4*)(Hb + s * 8));
        acc1 = fma4(acc1, a, *(const float4*)(Hb + s * 8 + 4));
    }
    float4 b0 = *(const float4*)(b), b1 = *(const float4*)(b + 4);
    acc0.x = elu(acc0.x + b0.x); acc0.y = elu(acc0.y + b0.y);
    acc0.z = elu(acc0.z + b0.z); acc0.w = elu(acc0.w + b0.w);
    acc1.x = elu(acc1.x + b1.x); acc1.y = elu(acc1.y + b1.y);
    acc1.z = elu(acc1.z + b1.z); acc1.w = elu(acc1.w + b1.w);
    *(float4*)(O + n * 8) = acc0;
    *(float4*)(O + n * 8 + 4) = acc1;
}

// ---------------- final per-edge MLP ----------------
__global__ void edge_mlp(const int* __restrict__ ei, const float* __restrict__ h3,
                         const float* __restrict__ ea, const float* __restrict__ yr,
                         const float* __restrict__ qt,
                         const float* __restrict__ fc1w, const float* __restrict__ fc1b,
                         const float* __restrict__ fc2w, const float* __restrict__ fc2b,
                         float* __restrict__ out) {
    __shared__ float w1[16 * 19];
    __shared__ float b1s[16];
    __shared__ float w2[16];
    int tid = threadIdx.x;
    for (int i = tid; i < 16 * 19; i += blockDim.x) w1[i] = fc1w[i];
    if (tid < 16) { b1s[tid] = fc1b[tid]; w2[tid] = fc2w[tid]; }
    __syncthreads();
    int e = blockIdx.x * blockDim.x + tid;
    if (e >= EE) return;
    int s = ei[e], d = ei[EE + e];
    float z[19];
    float4 a0 = *(const float4*)&h3[s * 8 + 0];
    float4 a1 = *(const float4*)&h3[s * 8 + 4];
    float4 c0 = *(const float4*)&h3[d * 8 + 0];
    float4 c1 = *(const float4*)&h3[d * 8 + 4];
    z[0] = a0.x; z[1] = a0.y; z[2] = a0.z; z[3] = a0.w;
    z[4] = a1.x; z[5] = a1.y; z[6] = a1.z; z[7] = a1.w;
    z[8] = c0.x; z[9] = c0.y; z[10] = c0.z; z[11] = c0.w;
    z[12] = c1.x; z[13] = c1.y; z[14] = c1.z; z[15] = c1.w;
    z[16] = ea[e]; z[17] = yr[e]; z[18] = qt[e];
    float acc = fc2b[0];
#pragma unroll
    for (int o = 0; o < 16; o++) {
        float t = b1s[o];
#pragma unroll
        for (int i = 0; i < 19; i++) t += w1[o * 19 + i] * z[i];
        t = fmaxf(t, 0.f);
        acc += t * w2[o];
    }
    out[e] = acc;
}

// ---------------- host driver ----------------
static inline int cdiv(long long a, int b) { return (int)((a + b - 1) / b); }

extern "C" void kernel_launch(void* const* d_in, const int* in_sizes, int n_in,
                              void* d_out, int out_size) {
    (void)in_sizes; (void)n_in; (void)out_size;
    const float* x    = (const float*)d_in[0];
    const int*   ei   = (const int*)  d_in[1];
    const float* ea   = (const float*)d_in[2];
    const float* yr   = (const float*)d_in[3];
    const float* qt   = (const float*)d_in[4];
    const float* W1   = (const float*)d_in[5];
    const float* a1s  = (const float*)d_in[6];
    const float* a1d  = (const float*)d_in[7];
    const float* b1   = (const float*)d_in[8];
    const float* W2   = (const float*)d_in[9];
    const float* a2s  = (const float*)d_in[10];
    const float* a2d  = (const float*)d_in[11];
    const float* b2   = (const float*)d_in[12];
    const float* W3   = (const float*)d_in[13];
    const float* a3s  = (const float*)d_in[14];
    const float* a3d  = (const float*)d_in[15];
    const float* b3   = (const float*)d_in[16];
    const float* fc1w = (const float*)d_in[17];
    const float* fc1b = (const float*)d_in[18];
    const float* fc2w = (const float*)d_in[19];
    const float* fc2b = (const float*)d_in[20];
    float* out = (float*)d_out;

    float *H1, *O1, *H2, *O2, *H3, *O3, *S, *D, *SUM, *RS, *EX;
    int *cnt, *ofs, *cur, *eix;
    cudaGetSymbolAddress((void**)&H1, g_H1);
    cudaGetSymbolAddress((void**)&O1, g_O1);
    cudaGetSymbolAddress((void**)&H2, g_H2);
    cudaGetSymbolAddress((void**)&O2, g_O2);
    cudaGetSymbolAddress((void**)&H3, g_H3);
    cudaGetSymbolAddress((void**)&O3, g_O3);
    cudaGetSymbolAddress((void**)&S,  g_S);
    cudaGetSymbolAddress((void**)&D,  g_D);
    cudaGetSymbolAddress((void**)&SUM, g_SUM);
    cudaGetSymbolAddress((void**)&RS, g_RS);
    cudaGetSymbolAddress((void**)&EX, g_EX);
    cudaGetSymbolAddress((void**)&cnt, g_cnt);
    cudaGetSymbolAddress((void**)&ofs, g_ofs);
    cudaGetSymbolAddress((void**)&cur, g_cur);
    cudaGetSymbolAddress((void**)&eix, g_eix);

    const int T = 256;

    // ---------- CSR build ----------
    k_zero<<<cdiv(NN, T), T>>>((float*)cnt, NN);
    k_count<<<cdiv(ET, T), T>>>(ei, cnt);
    k_scan<<<1, 1024>>>(cnt, ofs, cur);
    k_scatter<<<cdiv(ET, T), T>>>(ei, cur, eix);

    // ---------- layer 1: 128 -> 4 x 128 ----------
    gemm_tf32<<<dim3(512 / 128, cdiv(NN, 128)), T>>>(x, W1, H1, NN, 512, 128);
    attscore<4, 128><<<cdiv((long long)NN * 4 * 32, T), T>>>(H1, a1s, a1d, S, D);
    k_zero<<<cdiv(NN * 4, T), T>>>(SUM, NN * 4);
    edge_sum4<<<cdiv(ET, T), T>>>(ei, S, D, SUM, EX);
    k_rsum<<<cdiv(NN * 4, T), T>>>(SUM, RS, NN * 4);
    agg1<<<cdiv((long long)NN * 32, T), T>>>(ei, ofs, cnt, eix, EX, RS, H1, b1, O1);

    // ---------- layer 2: 512 -> 4 x 32 ----------
    gemm_tf32<<<dim3(128 / 128, cdiv(NN, 128)), T>>>(O1, W2, H2, NN, 128, 512);
    attscore<4, 32><<<cdiv((long long)NN * 4 * 32, T), T>>>(H2, a2s, a2d, S, D);
    k_zero<<<cdiv(NN * 4, T), T>>>(SUM, NN * 4);
    edge_sum4<<<cdiv(ET, T), T>>>(ei, S, D, SUM, EX);
    k_rsum<<<cdiv(NN * 4, T), T>>>(SUM, RS, NN * 4);
    agg2<<<cdiv((long long)NN * 32, T), T>>>(ei, ofs, cnt, eix, EX, RS, H2, b2, O2);

    // ---------- layer 3: 128 -> 1 x 8 ----------
    h3gemm<<<cdiv((long long)NN * 32, T), T>>>(O2, W3, H3);
    attscore<1, 8><<<cdiv((long long)NN * 32, T), T>>>(H3, a3s, a3d, S, D);
    k_zero<<<cdiv(NN, T), T>>>(SUM, NN);
    edge_sum1<<<cdiv(ET, T), T>>>(ei, S, D, SUM, EX);
    k_rsum<<<cdiv(NN, T), T>>>(SUM, RS, NN);
    agg3<<<cdiv(NN, T), T>>>(ei, ofs, cnt, eix, EX, RS, H3, b3, O3);

    // ---------- final per-edge MLP ----------
    edge_mlp<<<cdiv(EE, T), T>>>(ei, O3, ea, yr, qt, fc1w, fc1b, fc2w, fc2b, out);
}

// round 9
// speedup vs baseline: 3.1280x; 1.1299x over previous
#include <cuda_runtime.h>
#include <math.h>

#define NN 50000
#define EE 400000
#define ET 450000           // EE + NN self loops
#define NEG 0.2f

// ---------------- scratch (static device globals; no allocs) ----------------
__device__ float g_H1[(size_t)NN * 512];
__device__ float g_O1[(size_t)NN * 512];
__device__ float g_H2[(size_t)NN * 128];
__device__ float g_O2[(size_t)NN * 128];
__device__ float g_H3[NN * 8];
__device__ float g_O3[NN * 8];
__device__ float g_S [NN * 4];
__device__ float g_D [NN * 4];
__device__ float g_SUM[NN * 4];
// CSR
__device__ int g_cnt[NN];
__device__ int g_ofs[NN];
__device__ int g_cur[NN];
__device__ int g_pos[ET];                 // edge -> CSR slot
__device__ int g_esrc[ET];                // CSR slot -> source node
__device__ float g_EXc[(size_t)ET * 4];   // CSR-ordered softmax numerators

// ---------------- helpers ----------------
__device__ __forceinline__ int edge_src(const int* __restrict__ ei, int e) {
    return e < EE ? ei[e] : e - EE;
}
__device__ __forceinline__ int edge_dst(const int* __restrict__ ei, int e) {
    return e < EE ? ei[EE + e] : e - EE;
}
__device__ __forceinline__ float lrelu(float v) { return v > 0.f ? v : NEG * v; }
__device__ __forceinline__ float elu(float v)   { return v > 0.f ? v : expm1f(v); }

__device__ __forceinline__ void red4(float* p, float x, float y, float z, float w) {
    asm volatile("red.global.add.v4.f32 [%0], {%1,%2,%3,%4};"
                 :: "l"(p), "f"(x), "f"(y), "f"(z), "f"(w) : "memory");
}

__device__ __forceinline__ void mma_tf32(float c[4],
                                         unsigned a0, unsigned a1, unsigned a2, unsigned a3,
                                         unsigned b0, unsigned b1) {
    asm volatile("mma.sync.aligned.m16n8k8.row.col.f32.tf32.tf32.f32 "
                 "{%0,%1,%2,%3}, {%4,%5,%6,%7}, {%8,%9}, {%0,%1,%2,%3};"
                 : "+f"(c[0]), "+f"(c[1]), "+f"(c[2]), "+f"(c[3])
                 : "r"(a0), "r"(a1), "r"(a2), "r"(a3), "r"(b0), "r"(b1));
}
__device__ __forceinline__ float4 fma4(float4 acc, float a, float4 v) {
    acc.x = fmaf(a, v.x, acc.x); acc.y = fmaf(a, v.y, acc.y);
    acc.z = fmaf(a, v.z, acc.z); acc.w = fmaf(a, v.w, acc.w);
    return acc;
}
__device__ __forceinline__ void cp16(void* smem_dst, const void* gmem_src) {
    unsigned sa = (unsigned)__cvta_generic_to_shared(smem_dst);
    asm volatile("cp.async.ca.shared.global [%0], [%1], 16;" :: "r"(sa), "l"(gmem_src));
}

// ---------------- tf32 tensor-core GEMM: C[m,n] = sum_k A[m,k]*B[n,k] ----------------
__global__ void __launch_bounds__(256) gemm_tf32(const float* __restrict__ A,
                                                 const float* __restrict__ B,
                                                 float* __restrict__ C,
                                                 int M, int N, int K) {
    __shared__ float As[2][128][20];
    __shared__ float Bs[2][128][20];
    int bm = blockIdx.y * 128, bn = blockIdx.x * 128;
    int tid = threadIdx.x;
    int wid = tid >> 5, lane = tid & 31;
    int wm = (wid >> 2) * 64, wn = (wid & 3) * 32;
    int g = lane >> 2, t = lane & 3;

    int lrow0 = tid >> 2, lc4 = (tid & 3) * 4;
    int lrow1 = lrow0 + 64;
    int ar0 = bm + lrow0 < M ? bm + lrow0 : M - 1;
    int ar1 = bm + lrow1 < M ? bm + lrow1 : M - 1;

    float acc[4][4][4] = {};

    cp16(&As[0][lrow0][lc4], A + (size_t)ar0 * K + lc4);
    cp16(&As[0][lrow1][lc4], A + (size_t)ar1 * K + lc4);
    cp16(&Bs[0][lrow0][lc4], B + (size_t)(bn + lrow0) * K + lc4);
    cp16(&Bs[0][lrow1][lc4], B + (size_t)(bn + lrow1) * K + lc4);
    asm volatile("cp.async.commit_group;");

    int buf = 0;
    for (int k0 = 0; k0 < K; k0 += 16, buf ^= 1) {
        if (k0 + 16 < K) {
            int kn = k0 + 16;
            cp16(&As[buf ^ 1][lrow0][lc4], A + (size_t)ar0 * K + kn + lc4);
            cp16(&As[buf ^ 1][lrow1][lc4], A + (size_t)ar1 * K + kn + lc4);
            cp16(&Bs[buf ^ 1][lrow0][lc4], B + (size_t)(bn + lrow0) * K + kn + lc4);
            cp16(&Bs[buf ^ 1][lrow1][lc4], B + (size_t)(bn + lrow1) * K + kn + lc4);
            asm volatile("cp.async.commit_group;");
            asm volatile("cp.async.wait_group 1;");
        } else {
            asm volatile("cp.async.wait_group 0;");
        }
        __syncthreads();
#pragma unroll
        for (int kk = 0; kk < 2; kk++) {
            int kc = kk * 8 + t;
            unsigned a[4][4], bf[4][2];
#pragma unroll
            for (int im = 0; im < 4; im++) {
                int r0 = wm + im * 16 + g;
                a[im][0] = __float_as_uint(As[buf][r0][kc]);
                a[im][1] = __float_as_uint(As[buf][r0 + 8][kc]);
                a[im][2] = __float_as_uint(As[buf][r0][kc + 4]);
                a[im][3] = __float_as_uint(As[buf][r0 + 8][kc + 4]);
            }
#pragma unroll
            for (int jn = 0; jn < 4; jn++) {
                int n0 = wn + jn * 8 + g;
                bf[jn][0] = __float_as_uint(Bs[buf][n0][kc]);
                bf[jn][1] = __float_as_uint(Bs[buf][n0][kc + 4]);
            }
#pragma unroll
            for (int im = 0; im < 4; im++)
#pragma unroll
                for (int jn = 0; jn < 4; jn++)
                    mma_tf32(acc[im][jn], a[im][0], a[im][1], a[im][2], a[im][3],
                             bf[jn][0], bf[jn][1]);
        }
        __syncthreads();
    }

#pragma unroll
    for (int im = 0; im < 4; im++) {
        int r0 = bm + wm + im * 16 + g;
#pragma unroll
        for (int jn = 0; jn < 4; jn++) {
            int col = bn + wn + jn * 8 + 2 * t;
            if (r0 < M)
                *(float2*)(C + (size_t)r0 * N + col) = make_float2(acc[im][jn][0], acc[im][jn][1]);
            if (r0 + 8 < M)
                *(float2*)(C + (size_t)(r0 + 8) * N + col) = make_float2(acc[im][jn][2], acc[im][jn][3]);
        }
    }
}

// ---------------- layer-3 linear: warp per node, 8 outputs ----------------
__global__ void h3gemm(const float* __restrict__ A, const float* __restrict__ W,
                       float* __restrict__ C) {
    int gt = blockIdx.x * blockDim.x + threadIdx.x;
    int w = gt >> 5, lane = gt & 31;
    if (w >= NN) return;
    float4 a = *(const float4*)(A + (size_t)w * 128 + lane * 4);
    float r[8];
#pragma unroll
    for (int j = 0; j < 8; j++) {
        float4 wv = *(const float4*)(W + j * 128 + lane * 4);
        float p = a.x * wv.x + a.y * wv.y + a.z * wv.z + a.w * wv.w;
#pragma unroll
        for (int o = 16; o; o >>= 1) p += __shfl_xor_sync(0xffffffffu, p, o);
        r[j] = p;
    }
    if (lane == 0) {
        *(float4*)(C + w * 8 + 0) = make_float4(r[0], r[1], r[2], r[3]);
        *(float4*)(C + w * 8 + 4) = make_float4(r[4], r[5], r[6], r[7]);
    }
}

// ---------------- per-node attention scalars (+ SUM zeroing fused) ----------------
template <int H, int C>
__global__ void attscore(const float* __restrict__ Hb,
                         const float* __restrict__ as_, const float* __restrict__ ad_,
                         float* __restrict__ S, float* __restrict__ D,
                         float* __restrict__ SUM) {
    int gt = blockIdx.x * blockDim.x + threadIdx.x;
    int w = gt >> 5, lane = gt & 31;
    if (w >= NN * H) return;
    int n = w / H, h = w - n * H;
    const float* row = Hb + (size_t)n * (H * C) + h * C;
    float s = 0.f, d = 0.f;
    for (int c = lane * 4; c < C; c += 128) {
        float4 v = *(const float4*)(row + c);
        float4 a = *(const float4*)(as_ + h * C + c);
        float4 b = *(const float4*)(ad_ + h * C + c);
        s += v.x * a.x + v.y * a.y + v.z * a.z + v.w * a.w;
        d += v.x * b.x + v.y * b.y + v.z * b.z + v.w * b.w;
    }
#pragma unroll
    for (int o = 16; o; o >>= 1) {
        s += __shfl_xor_sync(0xffffffffu, s, o);
        d += __shfl_xor_sync(0xffffffffu, d, o);
    }
    if (lane == 0) { S[n * H + h] = s; D[n * H + h] = d; SUM[n * H + h] = 0.f; }
}

// ---------------- CSR build ----------------
__global__ void k_zero(int* __restrict__ p, int n) {
    int i = blockIdx.x * blockDim.x + threadIdx.x;
    if (i < n) p[i] = 0;
}
__global__ void k_count(const int* __restrict__ ei, int* __restrict__ cnt) {
    int e = blockIdx.x * blockDim.x + threadIdx.x;
    if (e >= ET) return;
    atomicAdd(&cnt[edge_dst(ei, e)], 1);
}
__global__ void __launch_bounds__(1024) k_scan(const int* __restrict__ cnt,
                                               int* __restrict__ ofs, int* __restrict__ cur) {
    __shared__ int sh[1024];
    const int CH = (NN + 1023) / 1024;
    int t = threadIdx.x;
    int base = t * CH, end = base + CH < NN ? base + CH : NN;
    int s = 0;
    for (int i = base; i < end; i++) s += cnt[i];
    sh[t] = s;
    __syncthreads();
    for (int off = 1; off < 1024; off <<= 1) {
        int v = t >= off ? sh[t - off] : 0;
        __syncthreads();
        sh[t] += v;
        __syncthreads();
    }
    int run = t ? sh[t - 1] : 0;
    for (int i = base; i < end; i++) {
        ofs[i] = run; cur[i] = run;
        run += cnt[i];
    }
}
__global__ void k_scatter(const int* __restrict__ ei, int* __restrict__ cur,
                          int* __restrict__ pos, int* __restrict__ esrc) {
    int e = blockIdx.x * blockDim.x + threadIdx.x;
    if (e >= ET) return;
    int p = atomicAdd(&cur[edge_dst(ei, e)], 1);
    pos[e] = p;
    esrc[p] = edge_src(ei, e);
}

// ---------------- softmax numerators (CSR-ordered) + denominator ----------------
__global__ void edge_sum4(const int* __restrict__ ei, const int* __restrict__ pos,
                          const float* __restrict__ S, const float* __restrict__ D,
                          float* __restrict__ SUM, float* __restrict__ EXc) {
    int e = blockIdx.x * blockDim.x + threadIdx.x;
    if (e >= ET) return;
    int s = edge_src(ei, e), d = edge_dst(ei, e);
    float4 sv = *(const float4*)(S + s * 4);
    float4 dv = *(const float4*)(D + d * 4);
    float e0 = __expf(lrelu(sv.x + dv.x));
    float e1 = __expf(lrelu(sv.y + dv.y));
    float e2 = __expf(lrelu(sv.z + dv.z));
    float e3 = __expf(lrelu(sv.w + dv.w));
    *(float4*)(EXc + (size_t)pos[e] * 4) = make_float4(e0, e1, e2, e3);
    red4(SUM + d * 4, e0, e1, e2, e3);
}
__global__ void edge_sum1(const int* __restrict__ ei, const int* __restrict__ pos,
                          const float* __restrict__ S, const float* __restrict__ D,
                          float* __restrict__ SUM, float* __restrict__ EXc) {
    int e = blockIdx.x * blockDim.x + threadIdx.x;
    if (e >= ET) return;
    int s = edge_src(ei, e), d = edge_dst(ei, e);
    float ex = __expf(lrelu(S[s] + D[d]));
    EXc[pos[e]] = ex;
    atomicAdd(&SUM[d], ex);
}

// ---------------- CSR gather aggregation (+1/den, bias, ELU fused) ----------------
// layer 1: H=4, C=128; 4 warps per node (one per head), lane owns one float4.
__global__ void agg1(const int* __restrict__ ofs, const int* __restrict__ cnt,
                     const int* __restrict__ esrc, const float* __restrict__ EXc,
                     const float* __restrict__ SUM,
                     const float* __restrict__ Hb, const float* __restrict__ b,
                     float* __restrict__ O) {
    int gt = blockIdx.x * blockDim.x + threadIdx.x;
    int w = gt >> 5, lane = gt & 31;
    if (w >= NN * 4) return;
    int n = w >> 2, h = w & 3;
    int st = ofs[n], deg = cnt[n];
    int off = h * 32 + lane;                          // float4 index within row
    const float4* Hb4 = (const float4*)Hb;
    float4 acc = {0, 0, 0, 0};
    int i = 0;
    for (; i + 2 <= deg; i += 2) {
        int s0 = esrc[st + i], s1 = esrc[st + i + 1];
        float a0 = EXc[(size_t)(st + i) * 4 + h];
        float a1 = EXc[(size_t)(st + i + 1) * 4 + h];
        float4 v0 = Hb4[(size_t)s0 * 128 + off];
        float4 v1 = Hb4[(size_t)s1 * 128 + off];
        acc = fma4(acc, a0, v0);
        acc = fma4(acc, a1, v1);
    }
    if (i < deg) {
        int s0 = esrc[st + i];
        float a0 = EXc[(size_t)(st + i) * 4 + h];
        acc = fma4(acc, a0, Hb4[(size_t)s0 * 128 + off]);
    }
    float rs = __frcp_rn(SUM[n * 4 + h]);
    float4 bv = ((const float4*)b)[off];
    acc.x = elu(fmaf(acc.x, rs, bv.x)); acc.y = elu(fmaf(acc.y, rs, bv.y));
    acc.z = elu(fmaf(acc.z, rs, bv.z)); acc.w = elu(fmaf(acc.w, rs, bv.w));
    ((float4*)(O + (size_t)n * 512))[off] = acc;
}

// layer 2: H=4, C=32; warp per node, lane owns float4 lane (head = lane>>3)
__global__ void agg2(const int* __restrict__ ofs, const int* __restrict__ cnt,
                     const int* __restrict__ esrc, const float* __restrict__ EXc,
                     const float* __restrict__ SUM,
                     const float* __restrict__ Hb, const float* __restrict__ b,
                     float* __restrict__ O) {
    int gt = blockIdx.x * blockDim.x + threadIdx.x;
    int n = gt >> 5, lane = gt & 31;
    if (n >= NN) return;
    int st = ofs[n], deg = cnt[n];
    int h = lane >> 3;
    const float4* Hb4 = (const float4*)Hb;
    float4 acc = {0, 0, 0, 0};
    int i = 0;
    for (; i + 2 <= deg; i += 2) {
        int s0 = esrc[st + i], s1 = esrc[st + i + 1];
        float4 e0 = *(const float4*)(EXc + (size_t)(st + i) * 4);
        float4 e1 = *(const float4*)(EXc + (size_t)(st + i + 1) * 4);
        float a0 = h == 0 ? e0.x : h == 1 ? e0.y : h == 2 ? e0.z : e0.w;
        float a1 = h == 0 ? e1.x : h == 1 ? e1.y : h == 2 ? e1.z : e1.w;
        float4 v0 = Hb4[(size_t)s0 * 32 + lane];
        float4 v1 = Hb4[(size_t)s1 * 32 + lane];
        acc = fma4(acc, a0, v0);
        acc = fma4(acc, a1, v1);
    }
    if (i < deg) {
        int s0 = esrc[st + i];
        float4 e0 = *(const float4*)(EXc + (size_t)(st + i) * 4);
        float a0 = h == 0 ? e0.x : h == 1 ? e0.y : h == 2 ? e0.z : e0.w;
        acc = fma4(acc, a0, Hb4[(size_t)s0 * 32 + lane]);
    }
    float rs = __frcp_rn(SUM[n * 4 + h]);
    float4 bv = ((const float4*)b)[lane];
    acc.x = elu(fmaf(acc.x, rs, bv.x)); acc.y = elu(fmaf(acc.y, rs, bv.y));
    acc.z = elu(fmaf(acc.z, rs, bv.z)); acc.w = elu(fmaf(acc.w, rs, bv.w));
    ((float4*)(O + (size_t)n * 128))[lane] = acc;
}

// layer 3: H=1, C=8; thread per node
__global__ void agg3(const int* __restrict__ ofs, const int* __restrict__ cnt,
                     const int* __restrict__ esrc, const float* __restrict__ EXc,
                     const float* __restrict__ SUM,
                     const float* __restrict__ Hb, const float* __restrict__ b,
                     float* __restrict__ O) {
    int n = blockIdx.x * blockDim.x + threadIdx.x;
    if (n >= NN) return;
    int st = ofs[n], deg = cnt[n];
    float4 acc0 = {0, 0, 0, 0}, acc1 = {0, 0, 0, 0};
    int i = 0;
    for (; i + 2 <= deg; i += 2) {
        int s0 = esrc[st + i], s1 = esrc[st + i + 1];
        float a0 = EXc[st + i], a1 = EXc[st + i + 1];
        acc0 = fma4(acc0, a0, *(const float4*)(Hb + s0 * 8));
        acc1 = fma4(acc1, a0, *(const float4*)(Hb + s0 * 8 + 4));
        acc0 = fma4(acc0, a1, *(const float4*)(Hb + s1 * 8));
        acc1 = fma4(acc1, a1, *(const float4*)(Hb + s1 * 8 + 4));
    }
    if (i < deg) {
        int s0 = esrc[st + i];
        float a0 = EXc[st + i];
        acc0 = fma4(acc0, a0, *(const float4*)(Hb + s0 * 8));
        acc1 = fma4(acc1, a0, *(const float4*)(Hb + s0 * 8 + 4));
    }
    float rs = __frcp_rn(SUM[n]);
    float4 b0 = *(const float4*)(b), b1 = *(const float4*)(b + 4);
    acc0.x = elu(fmaf(acc0.x, rs, b0.x)); acc0.y = elu(fmaf(acc0.y, rs, b0.y));
    acc0.z = elu(fmaf(acc0.z, rs, b0.z)); acc0.w = elu(fmaf(acc0.w, rs, b0.w));
    acc1.x = elu(fmaf(acc1.x, rs, b1.x)); acc1.y = elu(fmaf(acc1.y, rs, b1.y));
    acc1.z = elu(fmaf(acc1.z, rs, b1.z)); acc1.w = elu(fmaf(acc1.w, rs, b1.w));
    *(float4*)(O + n * 8) = acc0;
    *(float4*)(O + n * 8 + 4) = acc1;
}

// ---------------- final per-edge MLP ----------------
__global__ void edge_mlp(const int* __restrict__ ei, const float* __restrict__ h3,
                         const float* __restrict__ ea, const float* __restrict__ yr,
                         const float* __restrict__ qt,
                         const float* __restrict__ fc1w, const float* __restrict__ fc1b,
                         const float* __restrict__ fc2w, const float* __restrict__ fc2b,
                         float* __restrict__ out) {
    __shared__ float w1[16 * 19];
    __shared__ float b1s[16];
    __shared__ float w2[16];
    int tid = threadIdx.x;
    for (int i = tid; i < 16 * 19; i += blockDim.x) w1[i] = fc1w[i];
    if (tid < 16) { b1s[tid] = fc1b[tid]; w2[tid] = fc2w[tid]; }
    __syncthreads();
    int e = blockIdx.x * blockDim.x + tid;
    if (e >= EE) return;
    int s = ei[e], d = ei[EE + e];
    float z[19];
    float4 a0 = *(const float4*)&h3[s * 8 + 0];
    float4 a1 = *(const float4*)&h3[s * 8 + 4];
    float4 c0 = *(const float4*)&h3[d * 8 + 0];
    float4 c1 = *(const float4*)&h3[d * 8 + 4];
    z[0] = a0.x; z[1] = a0.y; z[2] = a0.z; z[3] = a0.w;
    z[4] = a1.x; z[5] = a1.y; z[6] = a1.z; z[7] = a1.w;
    z[8] = c0.x; z[9] = c0.y; z[10] = c0.z; z[11] = c0.w;
    z[12] = c1.x; z[13] = c1.y; z[14] = c1.z; z[15] = c1.w;
    z[16] = ea[e]; z[17] = yr[e]; z[18] = qt[e];
    float acc = fc2b[0];
#pragma unroll
    for (int o = 0; o < 16; o++) {
        float t = b1s[o];
#pragma unroll
        for (int i = 0; i < 19; i++) t += w1[o * 19 + i] * z[i];
        t = fmaxf(t, 0.f);
        acc += t * w2[o];
    }
    out[e] = acc;
}

// ---------------- host driver ----------------
static inline int cdiv(long long a, int b) { return (int)((a + b - 1) / b); }

extern "C" void kernel_launch(void* const* d_in, const int* in_sizes, int n_in,
                              void* d_out, int out_size) {
    (void)in_sizes; (void)n_in; (void)out_size;
    const float* x    = (const float*)d_in[0];
    const int*   ei   = (const int*)  d_in[1];
    const float* ea   = (const float*)d_in[2];
    const float* yr   = (const float*)d_in[3];
    const float* qt   = (const float*)d_in[4];
    const float* W1   = (const float*)d_in[5];
    const float* a1s  = (const float*)d_in[6];
    const float* a1d  = (const float*)d_in[7];
    const float* b1   = (const float*)d_in[8];
    const float* W2   = (const float*)d_in[9];
    const float* a2s  = (const float*)d_in[10];
    const float* a2d  = (const float*)d_in[11];
    const float* b2   = (const float*)d_in[12];
    const float* W3   = (const float*)d_in[13];
    const float* a3s  = (const float*)d_in[14];
    const float* a3d  = (const float*)d_in[15];
    const float* b3   = (const float*)d_in[16];
    const float* fc1w = (const float*)d_in[17];
    const float* fc1b = (const float*)d_in[18];
    const float* fc2w = (const float*)d_in[19];
    const float* fc2b = (const float*)d_in[20];
    float* out = (float*)d_out;

    float *H1, *O1, *H2, *O2, *H3, *O3, *S, *D, *SUM, *EXc;
    int *cnt, *ofs, *cur, *pos, *esrc;
    cudaGetSymbolAddress((void**)&H1, g_H1);
    cudaGetSymbolAddress((void**)&O1, g_O1);
    cudaGetSymbolAddress((void**)&H2, g_H2);
    cudaGetSymbolAddress((void**)&O2, g_O2);
    cudaGetSymbolAddress((void**)&H3, g_H3);
    cudaGetSymbolAddress((void**)&O3, g_O3);
    cudaGetSymbolAddress((void**)&S,  g_S);
    cudaGetSymbolAddress((void**)&D,  g_D);
    cudaGetSymbolAddress((void**)&SUM, g_SUM);
    cudaGetSymbolAddress((void**)&EXc, g_EXc);
    cudaGetSymbolAddress((void**)&cnt, g_cnt);
    cudaGetSymbolAddress((void**)&ofs, g_ofs);
    cudaGetSymbolAddress((void**)&cur, g_cur);
    cudaGetSymbolAddress((void**)&pos, g_pos);
    cudaGetSymbolAddress((void**)&esrc, g_esrc);

    const int T = 256;

    // ---------- CSR build ----------
    k_zero<<<cdiv(NN, T), T>>>(cnt, NN);
    k_count<<<cdiv(ET, T), T>>>(ei, cnt);
    k_scan<<<1, 1024>>>(cnt, ofs, cur);
    k_scatter<<<cdiv(ET, T), T>>>(ei, cur, pos, esrc);

    // ---------- layer 1: 128 -> 4 x 128 ----------
    gemm_tf32<<<dim3(512 / 128, cdiv(NN, 128)), T>>>(x, W1, H1, NN, 512, 128);
    attscore<4, 128><<<cdiv((long long)NN * 4 * 32, T), T>>>(H1, a1s, a1d, S, D, SUM);
    edge_sum4<<<cdiv(ET, T), T>>>(ei, pos, S, D, SUM, EXc);
    agg1<<<cdiv((long long)NN * 128, T), T>>>(ofs, cnt, esrc, EXc, SUM, H1, b1, O1);

    // ---------- layer 2: 512 -> 4 x 32 ----------
    gemm_tf32<<<dim3(128 / 128, cdiv(NN, 128)), T>>>(O1, W2, H2, NN, 128, 512);
    attscore<4, 32><<<cdiv((long long)NN * 4 * 32, T), T>>>(H2, a2s, a2d, S, D, SUM);
    edge_sum4<<<cdiv(ET, T), T>>>(ei, pos, S, D, SUM, EXc);
    agg2<<<cdiv((long long)NN * 32, T), T>>>(ofs, cnt, esrc, EXc, SUM, H2, b2, O2);

    // ---------- layer 3: 128 -> 1 x 8 ----------
    h3gemm<<<cdiv((long long)NN * 32, T), T>>>(O2, W3, H3);
    attscore<1, 8><<<cdiv((long long)NN * 32, T), T>>>(H3, a3s, a3d, S, D, SUM);
    edge_sum1<<<cdiv(ET, T), T>>>(ei, pos, S, D, SUM, EXc);
    agg3<<<cdiv(NN, T), T>>>(ofs, cnt, esrc, EXc, SUM, H3, b3, O3);

    // ---------- final per-edge MLP ----------
    edge_mlp<<<cdiv(EE, T), T>>>(ei, O3, ea, yr, qt, fc1w, fc1b, fc2w, fc2b, out);
}

// round 10
// speedup vs baseline: 3.4510x; 1.1033x over previous
#include <cuda_runtime.h>
#include <cuda_fp16.h>
#include <math.h>

#define NN 50000
#define EE 400000
#define ET 450000           // EE + NN self loops
#define NEG 0.2f

// ---------------- scratch (static device globals; no allocs) ----------------
__device__ __half g_H1h[(size_t)NN * 512];
__device__ float  g_O1[(size_t)NN * 512];
__device__ __half g_H2h[(size_t)NN * 128];
__device__ float  g_O2[(size_t)NN * 128];
__device__ float  g_H3[NN * 8];
__device__ float  g_O3[NN * 8];
__device__ float  g_S [NN * 4];
__device__ float  g_D [NN * 4];
__device__ float  g_SUM[NN * 4];
// CSR
__device__ int g_cnt[NN];
__device__ int g_ofs[NN];
__device__ int g_cur[NN];
__device__ int g_pos[ET];                 // edge -> CSR slot
__device__ int g_esrc[ET];                // CSR slot -> source node
__device__ float g_EXc[(size_t)ET * 4];   // CSR-ordered softmax numerators

// ---------------- helpers ----------------
__device__ __forceinline__ int edge_src(const int* __restrict__ ei, int e) {
    return e < EE ? ei[e] : e - EE;
}
__device__ __forceinline__ int edge_dst(const int* __restrict__ ei, int e) {
    return e < EE ? ei[EE + e] : e - EE;
}
__device__ __forceinline__ float lrelu(float v) { return v > 0.f ? v : NEG * v; }
__device__ __forceinline__ float elu(float v)   { return v > 0.f ? v : expm1f(v); }

__device__ __forceinline__ void red4(float* p, float x, float y, float z, float w) {
    asm volatile("red.global.add.v4.f32 [%0], {%1,%2,%3,%4};"
                 :: "l"(p), "f"(x), "f"(y), "f"(z), "f"(w) : "memory");
}

__device__ __forceinline__ void mma_tf32(float c[4],
                                         unsigned a0, unsigned a1, unsigned a2, unsigned a3,
                                         unsigned b0, unsigned b1) {
    asm volatile("mma.sync.aligned.m16n8k8.row.col.f32.tf32.tf32.f32 "
                 "{%0,%1,%2,%3}, {%4,%5,%6,%7}, {%8,%9}, {%0,%1,%2,%3};"
                 : "+f"(c[0]), "+f"(c[1]), "+f"(c[2]), "+f"(c[3])
                 : "r"(a0), "r"(a1), "r"(a2), "r"(a3), "r"(b0), "r"(b1));
}
__device__ __forceinline__ float4 fma4(float4 acc, float a, float4 v) {
    acc.x = fmaf(a, v.x, acc.x); acc.y = fmaf(a, v.y, acc.y);
    acc.z = fmaf(a, v.z, acc.z); acc.w = fmaf(a, v.w, acc.w);
    return acc;
}
// fma two packed halves into a float2 accumulator
__device__ __forceinline__ void fmah2(float2& a, float s, unsigned u) {
    float2 p = __half22float2(*(__half2*)&u);
    a.x = fmaf(s, p.x, a.x); a.y = fmaf(s, p.y, a.y);
}
__device__ __forceinline__ void cp16(void* smem_dst, const void* gmem_src) {
    unsigned sa = (unsigned)__cvta_generic_to_shared(smem_dst);
    asm volatile("cp.async.ca.shared.global [%0], [%1], 16;" :: "r"(sa), "l"(gmem_src));
}

// ---------------- tf32 GEMM + fused attention scores + fp16 output ----------------
// C[m,n] = sum_k A[m,k]*B[n,k];  A:[M,K] fp32, B:[N,K] fp32, Ch:[M,N] fp16.
// Also computes S[n,h] = <C[n, head h], as>, D likewise, and zeroes SUM.
// Tile 128x128, BK=16, 256 thr (8 warps as 2x4, warp tile 64x32).
// CC = channels per head; each warp's 32-col slice lies in ONE head.
template <int CC>
__global__ void __launch_bounds__(256) gemm_att(const float* __restrict__ A,
                                                const float* __restrict__ B,
                                                __half* __restrict__ Ch,
                                                const float* __restrict__ as_,
                                                const float* __restrict__ ad_,
                                                float* __restrict__ S,
                                                float* __restrict__ D,
                                                float* __restrict__ SUM,
                                                int M, int N, int K) {
    const int NHB  = 128 / CC;        // heads covered by this block tile
    const int HTOT = 4;               // total heads (both layers use 4)
    __shared__ float As[2][128][20];
    __shared__ float Bs[2][128][20];
    __shared__ float sS[128][4];
    __shared__ float sD[128][4];
    int bm = blockIdx.y * 128, bn = blockIdx.x * 128;
    int tid = threadIdx.x;
    int wid = tid >> 5, lane = tid & 31;
    int wm = (wid >> 2) * 64, wn = (wid & 3) * 32;
    int g = lane >> 2, t = lane & 3;

    int lrow0 = tid >> 2, lc4 = (tid & 3) * 4;
    int lrow1 = lrow0 + 64;
    int ar0 = bm + lrow0 < M ? bm + lrow0 : M - 1;
    int ar1 = bm + lrow1 < M ? bm + lrow1 : M - 1;

    float acc[4][4][4] = {};

    cp16(&As[0][lrow0][lc4], A + (size_t)ar0 * K + lc4);
    cp16(&As[0][lrow1][lc4], A + (size_t)ar1 * K + lc4);
    cp16(&Bs[0][lrow0][lc4], B + (size_t)(bn + lrow0) * K + lc4);
    cp16(&Bs[0][lrow1][lc4], B + (size_t)(bn + lrow1) * K + lc4);
    asm volatile("cp.async.commit_group;");

    int buf = 0;
    for (int k0 = 0; k0 < K; k0 += 16, buf ^= 1) {
        if (k0 + 16 < K) {
            int kn = k0 + 16;
            cp16(&As[buf ^ 1][lrow0][lc4], A + (size_t)ar0 * K + kn + lc4);
            cp16(&As[buf ^ 1][lrow1][lc4], A + (size_t)ar1 * K + kn + lc4);
            cp16(&Bs[buf ^ 1][lrow0][lc4], B + (size_t)(bn + lrow0) * K + kn + lc4);
            cp16(&Bs[buf ^ 1][lrow1][lc4], B + (size_t)(bn + lrow1) * K + kn + lc4);
            asm volatile("cp.async.commit_group;");
            asm volatile("cp.async.wait_group 1;");
        } else {
            asm volatile("cp.async.wait_group 0;");
        }
        __syncthreads();
#pragma unroll
        for (int kk = 0; kk < 2; kk++) {
            int kc = kk * 8 + t;
            unsigned a[4][4], bf[4][2];
#pragma unroll
            for (int im = 0; im < 4; im++) {
                int r0 = wm + im * 16 + g;
                a[im][0] = __float_as_uint(As[buf][r0][kc]);
                a[im][1] = __float_as_uint(As[buf][r0 + 8][kc]);
                a[im][2] = __float_as_uint(As[buf][r0][kc + 4]);
                a[im][3] = __float_as_uint(As[buf][r0 + 8][kc + 4]);
            }
#pragma unroll
            for (int jn = 0; jn < 4; jn++) {
                int n0 = wn + jn * 8 + g;
                bf[jn][0] = __float_as_uint(Bs[buf][n0][kc]);
                bf[jn][1] = __float_as_uint(Bs[buf][n0][kc + 4]);
            }
#pragma unroll
            for (int im = 0; im < 4; im++)
#pragma unroll
                for (int jn = 0; jn < 4; jn++)
                    mma_tf32(acc[im][jn], a[im][0], a[im][1], a[im][2], a[im][3],
                             bf[jn][0], bf[jn][1]);
        }
        __syncthreads();
    }

    // ---- epilogue: fp16 store + fused attention scores ----
    int hw = wn / CC;                          // this warp's block-local head
    float asv[8], adv[8];
#pragma unroll
    for (int jn = 0; jn < 4; jn++)
#pragma unroll
        for (int k = 0; k < 2; k++) {
            int gcol = bn + wn + jn * 8 + 2 * t + k;
            asv[jn * 2 + k] = as_[gcol];
            adv[jn * 2 + k] = ad_[gcol];
        }
    for (int i = tid; i < 128 * 4; i += 256) {
        ((float*)sS)[i] = 0.f; ((float*)sD)[i] = 0.f;
    }
    __syncthreads();
#pragma unroll
    for (int im = 0; im < 4; im++) {
#pragma unroll
        for (int hf = 0; hf < 2; hf++) {
            int lrow = wm + im * 16 + hf * 8 + g;
            int r = bm + lrow;
            float sp = 0.f, dp = 0.f;
#pragma unroll
            for (int jn = 0; jn < 4; jn++) {
                float c0 = acc[im][jn][hf * 2 + 0], c1 = acc[im][jn][hf * 2 + 1];
                sp += c0 * asv[jn * 2] + c1 * asv[jn * 2 + 1];
                dp += c0 * adv[jn * 2] + c1 * adv[jn * 2 + 1];
                if (r < M) {
                    int gcol = bn + wn + jn * 8 + 2 * t;
                    *(__half2*)(Ch + (size_t)r * N + gcol) = __floats2half2_rn(c0, c1);
                }
            }
            sp += __shfl_xor_sync(0xffffffffu, sp, 1);
            sp += __shfl_xor_sync(0xffffffffu, sp, 2);
            dp += __shfl_xor_sync(0xffffffffu, dp, 1);
            dp += __shfl_xor_sync(0xffffffffu, dp, 2);
            if ((lane & 3) == 0) {
                atomicAdd(&sS[lrow][hw], sp);
                atomicAdd(&sD[lrow][hw], dp);
            }
        }
    }
    __syncthreads();
    if (tid < 128) {
        int nrow = bm + tid;
        if (nrow < M) {
#pragma unroll
            for (int lh = 0; lh < NHB; lh++) {
                int gh = blockIdx.x * NHB + lh;
                S[nrow * HTOT + gh] = sS[tid][lh];
                D[nrow * HTOT + gh] = sD[tid][lh];
                SUM[nrow * HTOT + gh] = 0.f;
            }
        }
    }
}

// ---------------- layer-3 linear: warp per node, 8 outputs ----------------
__global__ void h3gemm(const float* __restrict__ A, const float* __restrict__ W,
                       float* __restrict__ C) {
    int gt = blockIdx.x * blockDim.x + threadIdx.x;
    int w = gt >> 5, lane = gt & 31;
    if (w >= NN) return;
    float4 a = *(const float4*)(A + (size_t)w * 128 + lane * 4);
    float r[8];
#pragma unroll
    for (int j = 0; j < 8; j++) {
        float4 wv = *(const float4*)(W + j * 128 + lane * 4);
        float p = a.x * wv.x + a.y * wv.y + a.z * wv.z + a.w * wv.w;
#pragma unroll
        for (int o = 16; o; o >>= 1) p += __shfl_xor_sync(0xffffffffu, p, o);
        r[j] = p;
    }
    if (lane == 0) {
        *(float4*)(C + w * 8 + 0) = make_float4(r[0], r[1], r[2], r[3]);
        *(float4*)(C + w * 8 + 4) = make_float4(r[4], r[5], r[6], r[7]);
    }
}

// ---------------- layer-3 attention scalars (+SUM zero) ----------------
__global__ void attscore3(const float* __restrict__ Hb,
                          const float* __restrict__ as_, const float* __restrict__ ad_,
                          float* __restrict__ S, float* __restrict__ D,
                          float* __restrict__ SUM) {
    int n = blockIdx.x * blockDim.x + threadIdx.x;
    if (n >= NN) return;
    float4 v0 = *(const float4*)(Hb + n * 8);
    float4 v1 = *(const float4*)(Hb + n * 8 + 4);
    float4 a0 = *(const float4*)(as_), a1 = *(const float4*)(as_ + 4);
    float4 b0 = *(const float4*)(ad_), b1 = *(const float4*)(ad_ + 4);
    S[n] = v0.x*a0.x + v0.y*a0.y + v0.z*a0.z + v0.w*a0.w
         + v1.x*a1.x + v1.y*a1.y + v1.z*a1.z + v1.w*a1.w;
    D[n] = v0.x*b0.x + v0.y*b0.y + v0.z*b0.z + v0.w*b0.w
         + v1.x*b1.x + v1.y*b1.y + v1.z*b1.z + v1.w*b1.w;
    SUM[n] = 0.f;
}

// ---------------- CSR build ----------------
__global__ void k_zero(int* __restrict__ p, int n) {
    int i = blockIdx.x * blockDim.x + threadIdx.x;
    if (i < n) p[i] = 0;
}
__global__ void k_count(const int* __restrict__ ei, int* __restrict__ cnt) {
    int e = blockIdx.x * blockDim.x + threadIdx.x;
    if (e >= ET) return;
    atomicAdd(&cnt[edge_dst(ei, e)], 1);
}
__global__ void __launch_bounds__(1024) k_scan(const int* __restrict__ cnt,
                                               int* __restrict__ ofs, int* __restrict__ cur) {
    __shared__ int sh[1024];
    const int CH = (NN + 1023) / 1024;
    int t = threadIdx.x;
    int base = t * CH, end = base + CH < NN ? base + CH : NN;
    int s = 0;
    for (int i = base; i < end; i++) s += cnt[i];
    sh[t] = s;
    __syncthreads();
    for (int off = 1; off < 1024; off <<= 1) {
        int v = t >= off ? sh[t - off] : 0;
        __syncthreads();
        sh[t] += v;
        __syncthreads();
    }
    int run = t ? sh[t - 1] : 0;
    for (int i = base; i < end; i++) {
        ofs[i] = run; cur[i] = run;
        run += cnt[i];
    }
}
__global__ void k_scatter(const int* __restrict__ ei, int* __restrict__ cur,
                          int* __restrict__ pos, int* __restrict__ esrc) {
    int e = blockIdx.x * blockDim.x + threadIdx.x;
    if (e >= ET) return;
    int p = atomicAdd(&cur[edge_dst(ei, e)], 1);
    pos[e] = p;
    esrc[p] = edge_src(ei, e);
}

// ---------------- softmax numerators (CSR-ordered) + denominator ----------------
__global__ void edge_sum4(const int* __restrict__ ei, const int* __restrict__ pos,
                          const float* __restrict__ S, const float* __restrict__ D,
                          float* __restrict__ SUM, float* __restrict__ EXc) {
    int e = blockIdx.x * blockDim.x + threadIdx.x;
    if (e >= ET) return;
    int s = edge_src(ei, e), d = edge_dst(ei, e);
    float4 sv = *(const float4*)(S + s * 4);
    float4 dv = *(const float4*)(D + d * 4);
    float e0 = __expf(lrelu(sv.x + dv.x));
    float e1 = __expf(lrelu(sv.y + dv.y));
    float e2 = __expf(lrelu(sv.z + dv.z));
    float e3 = __expf(lrelu(sv.w + dv.w));
    *(float4*)(EXc + (size_t)pos[e] * 4) = make_float4(e0, e1, e2, e3);
    red4(SUM + d * 4, e0, e1, e2, e3);
}
__global__ void edge_sum1(const int* __restrict__ ei, const int* __restrict__ pos,
                          const float* __restrict__ S, const float* __restrict__ D,
                          float* __restrict__ SUM, float* __restrict__ EXc) {
    int e = blockIdx.x * blockDim.x + threadIdx.x;
    if (e >= ET) return;
    int s = edge_src(ei, e), d = edge_dst(ei, e);
    float ex = __expf(lrelu(S[s] + D[d]));
    EXc[pos[e]] = ex;
    atomicAdd(&SUM[d], ex);
}

// ---------------- CSR gather aggregation (fp16 H, +1/den, bias, ELU fused) ----------------
// layer 1: H=4, C=128; warp per node; lane owns chunks (lane) and (lane+32) of 64
// 8-half chunks; chunk head = chunkIdx/16.
__global__ void agg1(const int* __restrict__ ofs, const int* __restrict__ cnt,
                     const int* __restrict__ esrc, const float* __restrict__ EXc,
                     const float* __restrict__ SUM,
                     const __half* __restrict__ Hh, const float* __restrict__ b,
                     float* __restrict__ O) {
    int gt = blockIdx.x * blockDim.x + threadIdx.x;
    int n = gt >> 5, lane = gt & 31;
    if (n >= NN) return;
    int st = ofs[n], deg = cnt[n];
    int hsel = lane >> 4;                       // 0/1: head of low chunk (high = +2)
    const uint4* H4 = (const uint4*)Hh;         // 16B = 8 halfs
    float2 aL[4] = {}, aH[4] = {};
#pragma unroll 2
    for (int i = 0; i < deg; i++) {
        int s = esrc[st + i];
        float4 ex = *(const float4*)(EXc + (size_t)(st + i) * 4);
        float aLo = hsel ? ex.y : ex.x;
        float aHi = hsel ? ex.w : ex.z;
        uint4 v0 = H4[(size_t)s * 64 + lane];
        uint4 v1 = H4[(size_t)s * 64 + lane + 32];
        fmah2(aL[0], aLo, v0.x); fmah2(aL[1], aLo, v0.y);
        fmah2(aL[2], aLo, v0.z); fmah2(aL[3], aLo, v0.w);
        fmah2(aH[0], aHi, v1.x); fmah2(aH[1], aHi, v1.y);
        fmah2(aH[2], aHi, v1.z); fmah2(aH[3], aHi, v1.w);
    }
    float4 sm = *(const float4*)(SUM + n * 4);
    float rLo = __frcp_rn(hsel ? sm.y : sm.x);
    float rHi = __frcp_rn(hsel ? sm.w : sm.z);
    float* orow = O + (size_t)n * 512;
#pragma unroll
    for (int j = 0; j < 4; j++) {
        int c = lane * 8 + j * 2;
        float2 r;
        r.x = elu(fmaf(aL[j].x, rLo, b[c]));
        r.y = elu(fmaf(aL[j].y, rLo, b[c + 1]));
        *(float2*)(orow + c) = r;
        int c2 = c + 256;
        float2 r2;
        r2.x = elu(fmaf(aH[j].x, rHi, b[c2]));
        r2.y = elu(fmaf(aH[j].y, rHi, b[c2 + 1]));
        *(float2*)(orow + c2) = r2;
    }
}

// layer 2: H=4, C=32; warp per node; lane owns 4 halfs at channels lane*4 (head = lane/8)
__global__ void agg2(const int* __restrict__ ofs, const int* __restrict__ cnt,
                     const int* __restrict__ esrc, const float* __restrict__ EXc,
                     const float* __restrict__ SUM,
                     const __half* __restrict__ Hh, const float* __restrict__ b,
                     float* __restrict__ O) {
    int gt = blockIdx.x * blockDim.x + threadIdx.x;
    int n = gt >> 5, lane = gt & 31;
    if (n >= NN) return;
    int st = ofs[n], deg = cnt[n];
    int h = lane >> 3;
    const uint2* H2v = (const uint2*)Hh;        // 8B = 4 halfs
    float2 acc0 = {}, acc1 = {};
#pragma unroll 2
    for (int i = 0; i < deg; i++) {
        int s = esrc[st + i];
        float4 ex = *(const float4*)(EXc + (size_t)(st + i) * 4);
        float a = h == 0 ? ex.x : h == 1 ? ex.y : h == 2 ? ex.z : ex.w;
        uint2 v = H2v[(size_t)s * 32 + lane];
        fmah2(acc0, a, v.x);
        fmah2(acc1, a, v.y);
    }
    float rs = __frcp_rn(SUM[n * 4 + h]);
    float4 bv = ((const float4*)b)[lane];
    float4 r;
    r.x = elu(fmaf(acc0.x, rs, bv.x)); r.y = elu(fmaf(acc0.y, rs, bv.y));
    r.z = elu(fmaf(acc1.x, rs, bv.z)); r.w = elu(fmaf(acc1.y, rs, bv.w));
    ((float4*)(O + (size_t)n * 128))[lane] = r;
}

// layer 3: H=1, C=8; thread per node (fp32 H3)
__global__ void agg3(const int* __restrict__ ofs, const int* __restrict__ cnt,
                     const int* __restrict__ esrc, const float* __restrict__ EXc,
                     const float* __restrict__ SUM,
                     const float* __restrict__ Hb, const float* __restrict__ b,
                     float* __restrict__ O) {
    int n = blockIdx.x * blockDim.x + threadIdx.x;
    if (n >= NN) return;
    int st = ofs[n], deg = cnt[n];
    float4 acc0 = {0, 0, 0, 0}, acc1 = {0, 0, 0, 0};
    int i = 0;
    for (; i + 2 <= deg; i += 2) {
        int s0 = esrc[st + i], s1 = esrc[st + i + 1];
        float a0 = EXc[st + i], a1 = EXc[st + i + 1];
        acc0 = fma4(acc0, a0, *(const float4*)(Hb + s0 * 8));
        acc1 = fma4(acc1, a0, *(const float4*)(Hb + s0 * 8 + 4));
        acc0 = fma4(acc0, a1, *(const float4*)(Hb + s1 * 8));
        acc1 = fma4(acc1, a1, *(const float4*)(Hb + s1 * 8 + 4));
    }
    if (i < deg) {
        int s0 = esrc[st + i];
        float a0 = EXc[st + i];
        acc0 = fma4(acc0, a0, *(const float4*)(Hb + s0 * 8));
        acc1 = fma4(acc1, a0, *(const float4*)(Hb + s0 * 8 + 4));
    }
    float rs = __frcp_rn(SUM[n]);
    float4 b0 = *(const float4*)(b), b1 = *(const float4*)(b + 4);
    acc0.x = elu(fmaf(acc0.x, rs, b0.x)); acc0.y = elu(fmaf(acc0.y, rs, b0.y));
    acc0.z = elu(fmaf(acc0.z, rs, b0.z)); acc0.w = elu(fmaf(acc0.w, rs, b0.w));
    acc1.x = elu(fmaf(acc1.x, rs, b1.x)); acc1.y = elu(fmaf(acc1.y, rs, b1.y));
    acc1.z = elu(fmaf(acc1.z, rs, b1.z)); acc1.w = elu(fmaf(acc1.w, rs, b1.w));
    *(float4*)(O + n * 8) = acc0;
    *(float4*)(O + n * 8 + 4) = acc1;
}

// ---------------- final per-edge MLP ----------------
__global__ void edge_mlp(const int* __restrict__ ei, const float* __restrict__ h3,
                         const float* __restrict__ ea, const float* __restrict__ yr,
                         const float* __restrict__ qt,
                         const float* __restrict__ fc1w, const float* __restrict__ fc1b,
                         const float* __restrict__ fc2w, const float* __restrict__ fc2b,
                         float* __restrict__ out) {
    __shared__ float w1[16 * 19];
    __shared__ float b1s[16];
    __shared__ float w2[16];
    int tid = threadIdx.x;
    for (int i = tid; i < 16 * 19; i += blockDim.x) w1[i] = fc1w[i];
    if (tid < 16) { b1s[tid] = fc1b[tid]; w2[tid] = fc2w[tid]; }
    __syncthreads();
    int e = blockIdx.x * blockDim.x + tid;
    if (e >= EE) return;
    int s = ei[e], d = ei[EE + e];
    float z[19];
    float4 a0 = *(const float4*)&h3[s * 8 + 0];
    float4 a1 = *(const float4*)&h3[s * 8 + 4];
    float4 c0 = *(const float4*)&h3[d * 8 + 0];
    float4 c1 = *(const float4*)&h3[d * 8 + 4];
    z[0] = a0.x; z[1] = a0.y; z[2] = a0.z; z[3] = a0.w;
    z[4] = a1.x; z[5] = a1.y; z[6] = a1.z; z[7] = a1.w;
    z[8] = c0.x; z[9] = c0.y; z[10] = c0.z; z[11] = c0.w;
    z[12] = c1.x; z[13] = c1.y; z[14] = c1.z; z[15] = c1.w;
    z[16] = ea[e]; z[17] = yr[e]; z[18] = qt[e];
    float acc = fc2b[0];
#pragma unroll
    for (int o = 0; o < 16; o++) {
        float t = b1s[o];
#pragma unroll
        for (int i = 0; i < 19; i++) t += w1[o * 19 + i] * z[i];
        t = fmaxf(t, 0.f);
        acc += t * w2[o];
    }
    out[e] = acc;
}

// ---------------- host driver ----------------
static inline int cdiv(long long a, int b) { return (int)((a + b - 1) / b); }

extern "C" void kernel_launch(void* const* d_in, const int* in_sizes, int n_in,
                              void* d_out, int out_size) {
    (void)in_sizes; (void)n_in; (void)out_size;
    const float* x    = (const float*)d_in[0];
    const int*   ei   = (const int*)  d_in[1];
    const float* ea   = (const float*)d_in[2];
    const float* yr   = (const float*)d_in[3];
    const float* qt   = (const float*)d_in[4];
    const float* W1   = (const float*)d_in[5];
    const float* a1s  = (const float*)d_in[6];
    const float* a1d  = (const float*)d_in[7];
    const float* b1   = (const float*)d_in[8];
    const float* W2   = (const float*)d_in[9];
    const float* a2s  = (const float*)d_in[10];
    const float* a2d  = (const float*)d_in[11];
    const float* b2   = (const float*)d_in[12];
    const float* W3   = (const float*)d_in[13];
    const float* a3s  = (const float*)d_in[14];
    const float* a3d  = (const float*)d_in[15];
    const float* b3   = (const float*)d_in[16];
    const float* fc1w = (const float*)d_in[17];
    const float* fc1b = (const float*)d_in[18];
    const float* fc2w = (const float*)d_in[19];
    const float* fc2b = (const float*)d_in[20];
    float* out = (float*)d_out;

    __half *H1h, *H2h;
    float *O1, *O2, *H3, *O3, *S, *D, *SUM, *EXc;
    int *cnt, *ofs, *cur, *pos, *esrc;
    cudaGetSymbolAddress((void**)&H1h, g_H1h);
    cudaGetSymbolAddress((void**)&O1, g_O1);
    cudaGetSymbolAddress((void**)&H2h, g_H2h);
    cudaGetSymbolAddress((void**)&O2, g_O2);
    cudaGetSymbolAddress((void**)&H3, g_H3);
    cudaGetSymbolAddress((void**)&O3, g_O3);
    cudaGetSymbolAddress((void**)&S,  g_S);
    cudaGetSymbolAddress((void**)&D,  g_D);
    cudaGetSymbolAddress((void**)&SUM, g_SUM);
    cudaGetSymbolAddress((void**)&EXc, g_EXc);
    cudaGetSymbolAddress((void**)&cnt, g_cnt);
    cudaGetSymbolAddress((void**)&ofs, g_ofs);
    cudaGetSymbolAddress((void**)&cur, g_cur);
    cudaGetSymbolAddress((void**)&pos, g_pos);
    cudaGetSymbolAddress((void**)&esrc, g_esrc);

    const int T = 256;

    // ---------- CSR build ----------
    k_zero<<<cdiv(NN, T), T>>>(cnt, NN);
    k_count<<<cdiv(ET, T), T>>>(ei, cnt);
    k_scan<<<1, 1024>>>(cnt, ofs, cur);
    k_scatter<<<cdiv(ET, T), T>>>(ei, cur, pos, esrc);

    // ---------- layer 1: 128 -> 4 x 128 (GEMM + fused attscore, fp16 H) ----------
    gemm_att<128><<<dim3(4, cdiv(NN, 128)), T>>>(x, W1, H1h, a1s, a1d, S, D, SUM,
                                                 NN, 512, 128);
    edge_sum4<<<cdiv(ET, T), T>>>(ei, pos, S, D, SUM, EXc);
    agg1<<<cdiv((long long)NN * 32, T), T>>>(ofs, cnt, esrc, EXc, SUM, H1h, b1, O1);

    // ---------- layer 2: 512 -> 4 x 32 ----------
    gemm_att<32><<<dim3(1, cdiv(NN, 128)), T>>>(O1, W2, H2h, a2s, a2d, S, D, SUM,
                                                NN, 128, 512);
    edge_sum4<<<cdiv(ET, T), T>>>(ei, pos, S, D, SUM, EXc);
    agg2<<<cdiv((long long)NN * 32, T), T>>>(ofs, cnt, esrc, EXc, SUM, H2h, b2, O2);

    // ---------- layer 3: 128 -> 1 x 8 ----------
    h3gemm<<<cdiv((long long)NN * 32, T), T>>>(O2, W3, H3);
    attscore3<<<cdiv(NN, T), T>>>(H3, a3s, a3d, S, D, SUM);
    edge_sum1<<<cdiv(ET, T), T>>>(ei, pos, S, D, SUM, EXc);
    agg3<<<cdiv(NN, T), T>>>(ofs, cnt, esrc, EXc, SUM, H3, b3, O3);

    // ---------- final per-edge MLP ----------
    edge_mlp<<<cdiv(EE, T), T>>>(ei, O3, ea, yr, qt, fc1w, fc1b, fc2w, fc2b, out);
}

// round 11
// speedup vs baseline: 3.9158x; 1.1347x over previous
#include <cuda_runtime.h>
#include <cuda_fp16.h>
#include <math.h>

#define NN 50000
#define EE 400000
#define ET 450000           // EE + NN self loops
#define NEG 0.2f

// ---------------- scratch (static device globals; no allocs) ----------------
__device__ __half g_H1h[(size_t)NN * 512];
__device__ __half g_O1h[(size_t)NN * 512];
__device__ __half g_H2h[(size_t)NN * 128];
__device__ float  g_O2[(size_t)NN * 128];
__device__ float  g_H3[NN * 8];
__device__ float  g_O3[NN * 8];
__device__ float  g_S [NN * 4];
__device__ float  g_D [NN * 4];
__device__ float  g_SUM[NN * 4];
__device__ __half g_W2h[128 * 512];
// CSR
__device__ int g_cnt[NN];
__device__ int g_ofs[NN];
__device__ int g_cur[NN];
__device__ int g_pos[ET];                 // edge -> CSR slot
__device__ int g_esrc[ET];                // CSR slot -> source node
__device__ float g_EXc[(size_t)ET * 4];   // CSR-ordered softmax numerators

// ---------------- helpers ----------------
__device__ __forceinline__ int edge_src(const int* __restrict__ ei, int e) {
    return e < EE ? ei[e] : e - EE;
}
__device__ __forceinline__ int edge_dst(const int* __restrict__ ei, int e) {
    return e < EE ? ei[EE + e] : e - EE;
}
__device__ __forceinline__ float lrelu(float v) { return v > 0.f ? v : NEG * v; }
__device__ __forceinline__ float elu(float v)   { return v > 0.f ? v : expm1f(v); }

__device__ __forceinline__ void red4(float* p, float x, float y, float z, float w) {
    asm volatile("red.global.add.v4.f32 [%0], {%1,%2,%3,%4};"
                 :: "l"(p), "f"(x), "f"(y), "f"(z), "f"(w) : "memory");
}

__device__ __forceinline__ void mma_tf32(float c[4],
                                         unsigned a0, unsigned a1, unsigned a2, unsigned a3,
                                         unsigned b0, unsigned b1) {
    asm volatile("mma.sync.aligned.m16n8k8.row.col.f32.tf32.tf32.f32 "
                 "{%0,%1,%2,%3}, {%4,%5,%6,%7}, {%8,%9}, {%0,%1,%2,%3};"
                 : "+f"(c[0]), "+f"(c[1]), "+f"(c[2]), "+f"(c[3])
                 : "r"(a0), "r"(a1), "r"(a2), "r"(a3), "r"(b0), "r"(b1));
}
__device__ __forceinline__ void mma_f16(float c[4],
                                        unsigned a0, unsigned a1, unsigned a2, unsigned a3,
                                        unsigned b0, unsigned b1) {
    asm volatile("mma.sync.aligned.m16n8k16.row.col.f32.f16.f16.f32 "
                 "{%0,%1,%2,%3}, {%4,%5,%6,%7}, {%8,%9}, {%0,%1,%2,%3};"
                 : "+f"(c[0]), "+f"(c[1]), "+f"(c[2]), "+f"(c[3])
                 : "r"(a0), "r"(a1), "r"(a2), "r"(a3), "r"(b0), "r"(b1));
}
__device__ __forceinline__ float4 fma4(float4 acc, float a, float4 v) {
    acc.x = fmaf(a, v.x, acc.x); acc.y = fmaf(a, v.y, acc.y);
    acc.z = fmaf(a, v.z, acc.z); acc.w = fmaf(a, v.w, acc.w);
    return acc;
}
__device__ __forceinline__ void fmah2(float2& a, float s, unsigned u) {
    float2 p = __half22float2(*(__half2*)&u);
    a.x = fmaf(s, p.x, a.x); a.y = fmaf(s, p.y, a.y);
}
__device__ __forceinline__ void cp16(void* smem_dst, const void* gmem_src) {
    unsigned sa = (unsigned)__cvta_generic_to_shared(smem_dst);
    asm volatile("cp.async.ca.shared.global [%0], [%1], 16;" :: "r"(sa), "l"(gmem_src));
}

// ---------------- layer 1: tf32 GEMM + fused attention scores + fp16 out ----------------
// C[m,n] = sum_k A[m,k]*B[n,k]; A fp32 [M,K], B fp32 [N,K], Ch fp16 [M,N].
// Tile 128x128, BK=16, 256 thr (8 warps 2x4, warp tile 64x32). CC = chans/head.
template <int CC>
__global__ void __launch_bounds__(256) gemm_att(const float* __restrict__ A,
                                                const float* __restrict__ B,
                                                __half* __restrict__ Ch,
                                                const float* __restrict__ as_,
                                                const float* __restrict__ ad_,
                                                float* __restrict__ S,
                                                float* __restrict__ D,
                                                float* __restrict__ SUM,
                                                int M, int N, int K) {
    const int NHB  = 128 / CC;
    const int HTOT = 4;
    __shared__ float As[2][128][20];
    __shared__ float Bs[2][128][20];
    __shared__ float sS[128][4];
    __shared__ float sD[128][4];
    int bm = blockIdx.y * 128, bn = blockIdx.x * 128;
    int tid = threadIdx.x;
    int wid = tid >> 5, lane = tid & 31;
    int wm = (wid >> 2) * 64, wn = (wid & 3) * 32;
    int g = lane >> 2, t = lane & 3;

    int lrow0 = tid >> 2, lc4 = (tid & 3) * 4;
    int lrow1 = lrow0 + 64;
    int ar0 = bm + lrow0 < M ? bm + lrow0 : M - 1;
    int ar1 = bm + lrow1 < M ? bm + lrow1 : M - 1;

    float acc[4][4][4] = {};

    cp16(&As[0][lrow0][lc4], A + (size_t)ar0 * K + lc4);
    cp16(&As[0][lrow1][lc4], A + (size_t)ar1 * K + lc4);
    cp16(&Bs[0][lrow0][lc4], B + (size_t)(bn + lrow0) * K + lc4);
    cp16(&Bs[0][lrow1][lc4], B + (size_t)(bn + lrow1) * K + lc4);
    asm volatile("cp.async.commit_group;");

    int buf = 0;
    for (int k0 = 0; k0 < K; k0 += 16, buf ^= 1) {
        if (k0 + 16 < K) {
            int kn = k0 + 16;
            cp16(&As[buf ^ 1][lrow0][lc4], A + (size_t)ar0 * K + kn + lc4);
            cp16(&As[buf ^ 1][lrow1][lc4], A + (size_t)ar1 * K + kn + lc4);
            cp16(&Bs[buf ^ 1][lrow0][lc4], B + (size_t)(bn + lrow0) * K + kn + lc4);
            cp16(&Bs[buf ^ 1][lrow1][lc4], B + (size_t)(bn + lrow1) * K + kn + lc4);
            asm volatile("cp.async.commit_group;");
            asm volatile("cp.async.wait_group 1;");
        } else {
            asm volatile("cp.async.wait_group 0;");
        }
        __syncthreads();
#pragma unroll
        for (int kk = 0; kk < 2; kk++) {
            int kc = kk * 8 + t;
            unsigned a[4][4], bf[4][2];
#pragma unroll
            for (int im = 0; im < 4; im++) {
                int r0 = wm + im * 16 + g;
                a[im][0] = __float_as_uint(As[buf][r0][kc]);
                a[im][1] = __float_as_uint(As[buf][r0 + 8][kc]);
                a[im][2] = __float_as_uint(As[buf][r0][kc + 4]);
                a[im][3] = __float_as_uint(As[buf][r0 + 8][kc + 4]);
            }
#pragma unroll
            for (int jn = 0; jn < 4; jn++) {
                int n0 = wn + jn * 8 + g;
                bf[jn][0] = __float_as_uint(Bs[buf][n0][kc]);
                bf[jn][1] = __float_as_uint(Bs[buf][n0][kc + 4]);
            }
#pragma unroll
            for (int im = 0; im < 4; im++)
#pragma unroll
                for (int jn = 0; jn < 4; jn++)
                    mma_tf32(acc[im][jn], a[im][0], a[im][1], a[im][2], a[im][3],
                             bf[jn][0], bf[jn][1]);
        }
        __syncthreads();
    }

    // epilogue: fp16 store + fused attention scores
    int hw = wn / CC;
    float asv[8], adv[8];
#pragma unroll
    for (int jn = 0; jn < 4; jn++)
#pragma unroll
        for (int k = 0; k < 2; k++) {
            int gcol = bn + wn + jn * 8 + 2 * t + k;
            asv[jn * 2 + k] = as_[gcol];
            adv[jn * 2 + k] = ad_[gcol];
        }
    for (int i = tid; i < 128 * 4; i += 256) {
        ((float*)sS)[i] = 0.f; ((float*)sD)[i] = 0.f;
    }
    __syncthreads();
#pragma unroll
    for (int im = 0; im < 4; im++) {
#pragma unroll
        for (int hf = 0; hf < 2; hf++) {
            int lrow = wm + im * 16 + hf * 8 + g;
            int r = bm + lrow;
            float sp = 0.f, dp = 0.f;
#pragma unroll
            for (int jn = 0; jn < 4; jn++) {
                float c0 = acc[im][jn][hf * 2 + 0], c1 = acc[im][jn][hf * 2 + 1];
                sp += c0 * asv[jn * 2] + c1 * asv[jn * 2 + 1];
                dp += c0 * adv[jn * 2] + c1 * adv[jn * 2 + 1];
                if (r < M) {
                    int gcol = bn + wn + jn * 8 + 2 * t;
                    *(__half2*)(Ch + (size_t)r * N + gcol) = __floats2half2_rn(c0, c1);
                }
            }
            sp += __shfl_xor_sync(0xffffffffu, sp, 1);
            sp += __shfl_xor_sync(0xffffffffu, sp, 2);
            dp += __shfl_xor_sync(0xffffffffu, dp, 1);
            dp += __shfl_xor_sync(0xffffffffu, dp, 2);
            if ((lane & 3) == 0) {
                atomicAdd(&sS[lrow][hw], sp);
                atomicAdd(&sD[lrow][hw], dp);
            }
        }
    }
    __syncthreads();
    if (tid < 128) {
        int nrow = bm + tid;
        if (nrow < M) {
#pragma unroll
            for (int lh = 0; lh < NHB; lh++) {
                int gh = blockIdx.x * NHB + lh;
                S[nrow * HTOT + gh] = sS[tid][lh];
                D[nrow * HTOT + gh] = sD[tid][lh];
                SUM[nrow * HTOT + gh] = 0.f;
            }
        }
    }
}

// ---------------- layer 2: fp16 GEMM + fused attention scores + fp16 out ----------------
// A fp16 [M,K], B fp16 [N,K], Ch fp16 [M,N=128]. Tile 128x128, BK=16, CC=32.
__global__ void __launch_bounds__(256) gemm_att_h(const __half* __restrict__ A,
                                                  const __half* __restrict__ B,
                                                  __half* __restrict__ Ch,
                                                  const float* __restrict__ as_,
                                                  const float* __restrict__ ad_,
                                                  float* __restrict__ S,
                                                  float* __restrict__ D,
                                                  float* __restrict__ SUM,
                                                  int M, int N, int K) {
    const int CC = 32, NHB = 4, HTOT = 4;
    __shared__ __half As[2][128][24];
    __shared__ __half Bs[2][128][24];
    __shared__ float sS[128][4];
    __shared__ float sD[128][4];
    int bm = blockIdx.y * 128, bn = blockIdx.x * 128;
    int tid = threadIdx.x;
    int wid = tid >> 5, lane = tid & 31;
    int wm = (wid >> 2) * 64, wn = (wid & 3) * 32;
    int g = lane >> 2, t = lane & 3;

    int lrow = tid >> 1, lc8 = (tid & 1) * 8;      // one row per thread, 8-half chunk
    int ar = bm + lrow < M ? bm + lrow : M - 1;

    float acc[4][4][4] = {};

    cp16(&As[0][lrow][lc8], A + (size_t)ar * K + lc8);
    cp16(&Bs[0][lrow][lc8], B + (size_t)(bn + lrow) * K + lc8);
    asm volatile("cp.async.commit_group;");

    int buf = 0;
    for (int k0 = 0; k0 < K; k0 += 16, buf ^= 1) {
        if (k0 + 16 < K) {
            int kn = k0 + 16;
            cp16(&As[buf ^ 1][lrow][lc8], A + (size_t)ar * K + kn + lc8);
            cp16(&Bs[buf ^ 1][lrow][lc8], B + (size_t)(bn + lrow) * K + kn + lc8);
            asm volatile("cp.async.commit_group;");
            asm volatile("cp.async.wait_group 1;");
        } else {
            asm volatile("cp.async.wait_group 0;");
        }
        __syncthreads();
        {
            unsigned a[4][4], bf[4][2];
#pragma unroll
            for (int im = 0; im < 4; im++) {
                int r0 = wm + im * 16 + g;
                a[im][0] = *(const unsigned*)&As[buf][r0][2 * t];
                a[im][1] = *(const unsigned*)&As[buf][r0 + 8][2 * t];
                a[im][2] = *(const unsigned*)&As[buf][r0][2 * t + 8];
                a[im][3] = *(const unsigned*)&As[buf][r0 + 8][2 * t + 8];
            }
#pragma unroll
            for (int jn = 0; jn < 4; jn++) {
                int n0 = wn + jn * 8 + g;
                bf[jn][0] = *(const unsigned*)&Bs[buf][n0][2 * t];
                bf[jn][1] = *(const unsigned*)&Bs[buf][n0][2 * t + 8];
            }
#pragma unroll
            for (int im = 0; im < 4; im++)
#pragma unroll
                for (int jn = 0; jn < 4; jn++)
                    mma_f16(acc[im][jn], a[im][0], a[im][1], a[im][2], a[im][3],
                            bf[jn][0], bf[jn][1]);
        }
        __syncthreads();
    }

    // epilogue: fp16 store + fused attention scores
    int hw = wn / CC;
    float asv[8], adv[8];
#pragma unroll
    for (int jn = 0; jn < 4; jn++)
#pragma unroll
        for (int k = 0; k < 2; k++) {
            int gcol = bn + wn + jn * 8 + 2 * t + k;
            asv[jn * 2 + k] = as_[gcol];
            adv[jn * 2 + k] = ad_[gcol];
        }
    for (int i = tid; i < 128 * 4; i += 256) {
        ((float*)sS)[i] = 0.f; ((float*)sD)[i] = 0.f;
    }
    __syncthreads();
#pragma unroll
    for (int im = 0; im < 4; im++) {
#pragma unroll
        for (int hf = 0; hf < 2; hf++) {
            int lrow2 = wm + im * 16 + hf * 8 + g;
            int r = bm + lrow2;
            float sp = 0.f, dp = 0.f;
#pragma unroll
            for (int jn = 0; jn < 4; jn++) {
                float c0 = acc[im][jn][hf * 2 + 0], c1 = acc[im][jn][hf * 2 + 1];
                sp += c0 * asv[jn * 2] + c1 * asv[jn * 2 + 1];
                dp += c0 * adv[jn * 2] + c1 * adv[jn * 2 + 1];
                if (r < M) {
                    int gcol = bn + wn + jn * 8 + 2 * t;
                    *(__half2*)(Ch + (size_t)r * N + gcol) = __floats2half2_rn(c0, c1);
                }
            }
            sp += __shfl_xor_sync(0xffffffffu, sp, 1);
            sp += __shfl_xor_sync(0xffffffffu, sp, 2);
            dp += __shfl_xor_sync(0xffffffffu, dp, 1);
            dp += __shfl_xor_sync(0xffffffffu, dp, 2);
            if ((lane & 3) == 0) {
                atomicAdd(&sS[lrow2][hw], sp);
                atomicAdd(&sD[lrow2][hw], dp);
            }
        }
    }
    __syncthreads();
    if (tid < 128) {
        int nrow = bm + tid;
        if (nrow < M) {
#pragma unroll
            for (int lh = 0; lh < NHB; lh++) {
                int gh = blockIdx.x * NHB + lh;
                S[nrow * HTOT + gh] = sS[tid][lh];
                D[nrow * HTOT + gh] = sD[tid][lh];
                SUM[nrow * HTOT + gh] = 0.f;
            }
        }
    }
}

// ---------------- W2 fp32 -> fp16 ----------------
__global__ void cvtW2(const float* __restrict__ W, __half* __restrict__ Wh) {
    int i = blockIdx.x * blockDim.x + threadIdx.x;   // float4 index
    if (i >= 128 * 512 / 4) return;
    float4 v = ((const float4*)W)[i];
    __half2* o = (__half2*)Wh;
    o[i * 2 + 0] = __floats2half2_rn(v.x, v.y);
    o[i * 2 + 1] = __floats2half2_rn(v.z, v.w);
}

// ---------------- layer-3 linear + attention scalars fused ----------------
__global__ void h3att(const float* __restrict__ A, const float* __restrict__ W,
                      const float* __restrict__ a3s, const float* __restrict__ a3d,
                      float* __restrict__ C, float* __restrict__ S,
                      float* __restrict__ D, float* __restrict__ SUM) {
    int gt = blockIdx.x * blockDim.x + threadIdx.x;
    int w = gt >> 5, lane = gt & 31;
    if (w >= NN) return;
    float4 a = *(const float4*)(A + (size_t)w * 128 + lane * 4);
    float r[8];
#pragma unroll
    for (int j = 0; j < 8; j++) {
        float4 wv = *(const float4*)(W + j * 128 + lane * 4);
        float p = a.x * wv.x + a.y * wv.y + a.z * wv.z + a.w * wv.w;
#pragma unroll
        for (int o = 16; o; o >>= 1) p += __shfl_xor_sync(0xffffffffu, p, o);
        r[j] = p;
    }
    if (lane == 0) {
        *(float4*)(C + w * 8 + 0) = make_float4(r[0], r[1], r[2], r[3]);
        *(float4*)(C + w * 8 + 4) = make_float4(r[4], r[5], r[6], r[7]);
        float s = 0.f, d = 0.f;
#pragma unroll
        for (int j = 0; j < 8; j++) { s += r[j] * a3s[j]; d += r[j] * a3d[j]; }
        S[w] = s; D[w] = d; SUM[w] = 0.f;
    }
}

// ---------------- CSR build ----------------
__global__ void k_zero(int* __restrict__ p, int n) {
    int i = blockIdx.x * blockDim.x + threadIdx.x;
    if (i < n) p[i] = 0;
}
__global__ void k_count(const int* __restrict__ ei, int* __restrict__ cnt) {
    int e = blockIdx.x * blockDim.x + threadIdx.x;
    if (e >= ET) return;
    atomicAdd(&cnt[edge_dst(ei, e)], 1);
}
__global__ void __launch_bounds__(1024) k_scan(const int* __restrict__ cnt,
                                               int* __restrict__ ofs, int* __restrict__ cur) {
    __shared__ int sh[1024];
    const int CH = (NN + 1023) / 1024;
    int t = threadIdx.x;
    int base = t * CH, end = base + CH < NN ? base + CH : NN;
    int s = 0;
    for (int i = base; i < end; i++) s += cnt[i];
    sh[t] = s;
    __syncthreads();
    for (int off = 1; off < 1024; off <<= 1) {
        int v = t >= off ? sh[t - off] : 0;
        __syncthreads();
        sh[t] += v;
        __syncthreads();
    }
    int run = t ? sh[t - 1] : 0;
    for (int i = base; i < end; i++) {
        ofs[i] = run; cur[i] = run;
        run += cnt[i];
    }
}
__global__ void k_scatter(const int* __restrict__ ei, int* __restrict__ cur,
                          int* __restrict__ pos, int* __restrict__ esrc) {
    int e = blockIdx.x * blockDim.x + threadIdx.x;
    if (e >= ET) return;
    int p = atomicAdd(&cur[edge_dst(ei, e)], 1);
    pos[e] = p;
    esrc[p] = edge_src(ei, e);
}

// ---------------- softmax numerators (CSR-ordered) + denominator ----------------
__global__ void edge_sum4(const int* __restrict__ ei, const int* __restrict__ pos,
                          const float* __restrict__ S, const float* __restrict__ D,
                          float* __restrict__ SUM, float* __restrict__ EXc) {
    int e = blockIdx.x * blockDim.x + threadIdx.x;
    if (e >= ET) return;
    int s = edge_src(ei, e), d = edge_dst(ei, e);
    float4 sv = *(const float4*)(S + s * 4);
    float4 dv = *(const float4*)(D + d * 4);
    float e0 = __expf(lrelu(sv.x + dv.x));
    float e1 = __expf(lrelu(sv.y + dv.y));
    float e2 = __expf(lrelu(sv.z + dv.z));
    float e3 = __expf(lrelu(sv.w + dv.w));
    *(float4*)(EXc + (size_t)pos[e] * 4) = make_float4(e0, e1, e2, e3);
    red4(SUM + d * 4, e0, e1, e2, e3);
}
__global__ void edge_sum1(const int* __restrict__ ei, const int* __restrict__ pos,
                          const float* __restrict__ S, const float* __restrict__ D,
                          float* __restrict__ SUM, float* __restrict__ EXc) {
    int e = blockIdx.x * blockDim.x + threadIdx.x;
    if (e >= ET) return;
    int s = edge_src(ei, e), d = edge_dst(ei, e);
    float ex = __expf(lrelu(S[s] + D[d]));
    EXc[pos[e]] = ex;
    atomicAdd(&SUM[d], ex);
}

// ---------------- CSR gather aggregation (fp16 H, +1/den, bias, ELU fused) ----------------
// layer 1: H=4, C=128; TWO warps per node; lane owns one 8-half chunk.
__global__ void agg1(const int* __restrict__ ofs, const int* __restrict__ cnt,
                     const int* __restrict__ esrc, const float* __restrict__ EXc,
                     const float* __restrict__ SUM,
                     const __half* __restrict__ Hh, const float* __restrict__ b,
                     __half* __restrict__ Oh) {
    int gt = blockIdx.x * blockDim.x + threadIdx.x;
    int w = gt >> 5, lane = gt & 31;
    if (w >= NN * 2) return;
    int n = w >> 1, half = w & 1;
    int chunk = half * 32 + lane;               // 0..63, channels chunk*8..+7
    int hsel = chunk >> 4;                      // head 0..3
    int st = ofs[n], deg = cnt[n];
    const uint4* H4 = (const uint4*)Hh;
    float2 acc[4] = {};
#pragma unroll 2
    for (int i = 0; i < deg; i++) {
        int s = esrc[st + i];
        float a = EXc[(size_t)(st + i) * 4 + hsel];
        uint4 v = H4[(size_t)s * 64 + chunk];
        fmah2(acc[0], a, v.x); fmah2(acc[1], a, v.y);
        fmah2(acc[2], a, v.z); fmah2(acc[3], a, v.w);
    }
    float rs = __frcp_rn(SUM[n * 4 + hsel]);
    __half2* orow = (__half2*)(Oh + (size_t)n * 512);
#pragma unroll
    for (int j = 0; j < 4; j++) {
        int c = chunk * 8 + j * 2;
        float2 bv = *(const float2*)(b + c);
        float rx = elu(fmaf(acc[j].x, rs, bv.x));
        float ry = elu(fmaf(acc[j].y, rs, bv.y));
        orow[chunk * 4 + j] = __floats2half2_rn(rx, ry);
    }
}

// layer 2: H=4, C=32; warp per node; lane owns 4 halfs at channels lane*4 (head = lane/8)
__global__ void agg2(const int* __restrict__ ofs, const int* __restrict__ cnt,
                     const int* __restrict__ esrc, const float* __restrict__ EXc,
                     const float* __restrict__ SUM,
                     const __half* __restrict__ Hh, const float* __restrict__ b,
                     float* __restrict__ O) {
    int gt = blockIdx.x * blockDim.x + threadIdx.x;
    int n = gt >> 5, lane = gt & 31;
    if (n >= NN) return;
    int st = ofs[n], deg = cnt[n];
    int h = lane >> 3;
    const uint2* H2v = (const uint2*)Hh;
    float2 acc0 = {}, acc1 = {};
#pragma unroll 2
    for (int i = 0; i < deg; i++) {
        int s = esrc[st + i];
        float a = EXc[(size_t)(st + i) * 4 + h];
        uint2 v = H2v[(size_t)s * 32 + lane];
        fmah2(acc0, a, v.x);
        fmah2(acc1, a, v.y);
    }
    float rs = __frcp_rn(SUM[n * 4 + h]);
    float4 bv = ((const float4*)b)[lane];
    float4 r;
    r.x = elu(fmaf(acc0.x, rs, bv.x)); r.y = elu(fmaf(acc0.y, rs, bv.y));
    r.z = elu(fmaf(acc1.x, rs, bv.z)); r.w = elu(fmaf(acc1.y, rs, bv.w));
    ((float4*)(O + (size_t)n * 128))[lane] = r;
}

// layer 3: H=1, C=8; thread per node (fp32 H3)
__global__ void agg3(const int* __restrict__ ofs, const int* __restrict__ cnt,
                     const int* __restrict__ esrc, const float* __restrict__ EXc,
                     const float* __restrict__ SUM,
                     const float* __restrict__ Hb, const float* __restrict__ b,
                     float* __restrict__ O) {
    int n = blockIdx.x * blockDim.x + threadIdx.x;
    if (n >= NN) return;
    int st = ofs[n], deg = cnt[n];
    float4 acc0 = {0, 0, 0, 0}, acc1 = {0, 0, 0, 0};
    int i = 0;
    for (; i + 2 <= deg; i += 2) {
        int s0 = esrc[st + i], s1 = esrc[st + i + 1];
        float a0 = EXc[st + i], a1 = EXc[st + i + 1];
        acc0 = fma4(acc0, a0, *(const float4*)(Hb + s0 * 8));
        acc1 = fma4(acc1, a0, *(const float4*)(Hb + s0 * 8 + 4));
        acc0 = fma4(acc0, a1, *(const float4*)(Hb + s1 * 8));
        acc1 = fma4(acc1, a1, *(const float4*)(Hb + s1 * 8 + 4));
    }
    if (i < deg) {
        int s0 = esrc[st + i];
        float a0 = EXc[st + i];
        acc0 = fma4(acc0, a0, *(const float4*)(Hb + s0 * 8));
        acc1 = fma4(acc1, a0, *(const float4*)(Hb + s0 * 8 + 4));
    }
    float rs = __frcp_rn(SUM[n]);
    float4 b0 = *(const float4*)(b), b1 = *(const float4*)(b + 4);
    acc0.x = elu(fmaf(acc0.x, rs, b0.x)); acc0.y = elu(fmaf(acc0.y, rs, b0.y));
    acc0.z = elu(fmaf(acc0.z, rs, b0.z)); acc0.w = elu(fmaf(acc0.w, rs, b0.w));
    acc1.x = elu(fmaf(acc1.x, rs, b1.x)); acc1.y = elu(fmaf(acc1.y, rs, b1.y));
    acc1.z = elu(fmaf(acc1.z, rs, b1.z)); acc1.w = elu(fmaf(acc1.w, rs, b1.w));
    *(float4*)(O + n * 8) = acc0;
    *(float4*)(O + n * 8 + 4) = acc1;
}

// ---------------- final per-edge MLP ----------------
__global__ void edge_mlp(const int* __restrict__ ei, const float* __restrict__ h3,
                         const float* __restrict__ ea, const float* __restrict__ yr,
                         const float* __restrict__ qt,
                         const float* __restrict__ fc1w, const float* __restrict__ fc1b,
                         const float* __restrict__ fc2w, const float* __restrict__ fc2b,
                         float* __restrict__ out) {
    __shared__ float w1[16 * 19];
    __shared__ float b1s[16];
    __shared__ float w2[16];
    int tid = threadIdx.x;
    for (int i = tid; i < 16 * 19; i += blockDim.x) w1[i] = fc1w[i];
    if (tid < 16) { b1s[tid] = fc1b[tid]; w2[tid] = fc2w[tid]; }
    __syncthreads();
    int e = blockIdx.x * blockDim.x + tid;
    if (e >= EE) return;
    int s = ei[e], d = ei[EE + e];
    float z[19];
    float4 a0 = *(const float4*)&h3[s * 8 + 0];
    float4 a1 = *(const float4*)&h3[s * 8 + 4];
    float4 c0 = *(const float4*)&h3[d * 8 + 0];
    float4 c1 = *(const float4*)&h3[d * 8 + 4];
    z[0] = a0.x; z[1] = a0.y; z[2] = a0.z; z[3] = a0.w;
    z[4] = a1.x; z[5] = a1.y; z[6] = a1.z; z[7] = a1.w;
    z[8] = c0.x; z[9] = c0.y; z[10] = c0.z; z[11] = c0.w;
    z[12] = c1.x; z[13] = c1.y; z[14] = c1.z; z[15] = c1.w;
    z[16] = ea[e]; z[17] = yr[e]; z[18] = qt[e];
    float acc = fc2b[0];
#pragma unroll
    for (int o = 0; o < 16; o++) {
        float t = b1s[o];
#pragma unroll
        for (int i = 0; i < 19; i++) t += w1[o * 19 + i] * z[i];
        t = fmaxf(t, 0.f);
        acc += t * w2[o];
    }
    out[e] = acc;
}

// ---------------- host driver ----------------
static inline int cdiv(long long a, int b) { return (int)((a + b - 1) / b); }

extern "C" void kernel_launch(void* const* d_in, const int* in_sizes, int n_in,
                              void* d_out, int out_size) {
    (void)in_sizes; (void)n_in; (void)out_size;
    const float* x    = (const float*)d_in[0];
    const int*   ei   = (const int*)  d_in[1];
    const float* ea   = (const float*)d_in[2];
    const float* yr   = (const float*)d_in[3];
    const float* qt   = (const float*)d_in[4];
    const float* W1   = (const float*)d_in[5];
    const float* a1s  = (const float*)d_in[6];
    const float* a1d  = (const float*)d_in[7];
    const float* b1   = (const float*)d_in[8];
    const float* W2   = (const float*)d_in[9];
    const float* a2s  = (const float*)d_in[10];
    const float* a2d  = (const float*)d_in[11];
    const float* b2   = (const float*)d_in[12];
    const float* W3   = (const float*)d_in[13];
    const float* a3s  = (const float*)d_in[14];
    const float* a3d  = (const float*)d_in[15];
    const float* b3   = (const float*)d_in[16];
    const float* fc1w = (const float*)d_in[17];
    const float* fc1b = (const float*)d_in[18];
    const float* fc2w = (const float*)d_in[19];
    const float* fc2b = (const float*)d_in[20];
    float* out = (float*)d_out;

    __half *H1h, *O1h, *H2h, *W2h;
    float *O2, *H3, *O3, *S, *D, *SUM, *EXc;
    int *cnt, *ofs, *cur, *pos, *esrc;
    cudaGetSymbolAddress((void**)&H1h, g_H1h);
    cudaGetSymbolAddress((void**)&O1h, g_O1h);
    cudaGetSymbolAddress((void**)&H2h, g_H2h);
    cudaGetSymbolAddress((void**)&W2h, g_W2h);
    cudaGetSymbolAddress((void**)&O2, g_O2);
    cudaGetSymbolAddress((void**)&H3, g_H3);
    cudaGetSymbolAddress((void**)&O3, g_O3);
    cudaGetSymbolAddress((void**)&S,  g_S);
    cudaGetSymbolAddress((void**)&D,  g_D);
    cudaGetSymbolAddress((void**)&SUM, g_SUM);
    cudaGetSymbolAddress((void**)&EXc, g_EXc);
    cudaGetSymbolAddress((void**)&cnt, g_cnt);
    cudaGetSymbolAddress((void**)&ofs, g_ofs);
    cudaGetSymbolAddress((void**)&cur, g_cur);
    cudaGetSymbolAddress((void**)&pos, g_pos);
    cudaGetSymbolAddress((void**)&esrc, g_esrc);

    const int T = 256;

    // ---------- CSR build + weight conversion ----------
    cvtW2<<<cdiv(128 * 512 / 4, T), T>>>(W2, W2h);
    k_zero<<<cdiv(NN, T), T>>>(cnt, NN);
    k_count<<<cdiv(ET, T), T>>>(ei, cnt);
    k_scan<<<1, 1024>>>(cnt, ofs, cur);
    k_scatter<<<cdiv(ET, T), T>>>(ei, cur, pos, esrc);

    // ---------- layer 1: 128 -> 4 x 128 (tf32 GEMM + fused attscore, fp16 H) ----------
    gemm_att<128><<<dim3(4, cdiv(NN, 128)), T>>>(x, W1, H1h, a1s, a1d, S, D, SUM,
                                                 NN, 512, 128);
    edge_sum4<<<cdiv(ET, T), T>>>(ei, pos, S, D, SUM, EXc);
    agg1<<<cdiv((long long)NN * 64, T), T>>>(ofs, cnt, esrc, EXc, SUM, H1h, b1, O1h);

    // ---------- layer 2: 512 -> 4 x 32 (fp16 GEMM) ----------
    gemm_att_h<<<dim3(1, cdiv(NN, 128)), T>>>(O1h, W2h, H2h, a2s, a2d, S, D, SUM,
                                              NN, 128, 512);
    edge_sum4<<<cdiv(ET, T), T>>>(ei, pos, S, D, SUM, EXc);
    agg2<<<cdiv((long long)NN * 32, T), T>>>(ofs, cnt, esrc, EXc, SUM, H2h, b2, O2);

    // ---------- layer 3: 128 -> 1 x 8 ----------
    h3att<<<cdiv((long long)NN * 32, T), T>>>(O2, W3, a3s, a3d, H3, S, D, SUM);
    edge_sum1<<<cdiv(ET, T), T>>>(ei, pos, S, D, SUM, EXc);
    agg3<<<cdiv(NN, T), T>>>(ofs, cnt, esrc, EXc, SUM, H3, b3, O3);

    // ---------- final per-edge MLP ----------
    edge_mlp<<<cdiv(EE, T), T>>>(ei, O3, ea, yr, qt, fc1w, fc1b, fc2w, fc2b, out);
}

// round 12
// speedup vs baseline: 4.6988x; 1.2000x over previous
#include <cuda_runtime.h>
#include <cuda_fp16.h>
#include <math.h>

#define NN 50000
#define EE 400000
#define ET 450000           // EE + NN self loops
#define NEG 0.2f
#define SCAN_B 256
#define SCAN_G ((NN + SCAN_B - 1) / SCAN_B)   // 196

// ---------------- scratch (static device globals; no allocs) ----------------
__device__ __half g_H1h[(size_t)NN * 512];
__device__ __half g_O1h[(size_t)NN * 512];
__device__ __half g_H2h[(size_t)NN * 128];
__device__ float  g_O2[(size_t)NN * 128];
__device__ float  g_H3[NN * 8];
__device__ float  g_O3[NN * 8];
__device__ float  g_S [NN * 4];
__device__ float  g_D [NN * 4];
__device__ float  g_SUM[NN * 4];
__device__ __half g_W2h[128 * 512];
// CSR
__device__ int g_cnt[NN];
__device__ int g_ofs[NN];
__device__ int g_cur[NN];
__device__ int g_bsum[SCAN_B];
__device__ int g_bofs[SCAN_B];
__device__ int g_pos[ET];                 // edge -> CSR slot
__device__ int g_esrc[ET];                // CSR slot -> source node
__device__ float g_EXc[(size_t)ET * 4];   // CSR-ordered softmax numerators

// ---------------- helpers ----------------
__device__ __forceinline__ int edge_src(const int* __restrict__ ei, int e) {
    return e < EE ? ei[e] : e - EE;
}
__device__ __forceinline__ int edge_dst(const int* __restrict__ ei, int e) {
    return e < EE ? ei[EE + e] : e - EE;
}
__device__ __forceinline__ float lrelu(float v) { return v > 0.f ? v : NEG * v; }
__device__ __forceinline__ float elu(float v)   { return v > 0.f ? v : expm1f(v); }

__device__ __forceinline__ void red4(float* p, float x, float y, float z, float w) {
    asm volatile("red.global.add.v4.f32 [%0], {%1,%2,%3,%4};"
                 :: "l"(p), "f"(x), "f"(y), "f"(z), "f"(w) : "memory");
}

__device__ __forceinline__ void mma_tf32(float c[4],
                                         unsigned a0, unsigned a1, unsigned a2, unsigned a3,
                                         unsigned b0, unsigned b1) {
    asm volatile("mma.sync.aligned.m16n8k8.row.col.f32.tf32.tf32.f32 "
                 "{%0,%1,%2,%3}, {%4,%5,%6,%7}, {%8,%9}, {%0,%1,%2,%3};"
                 : "+f"(c[0]), "+f"(c[1]), "+f"(c[2]), "+f"(c[3])
                 : "r"(a0), "r"(a1), "r"(a2), "r"(a3), "r"(b0), "r"(b1));
}
__device__ __forceinline__ void mma_f16(float c[4],
                                        unsigned a0, unsigned a1, unsigned a2, unsigned a3,
                                        unsigned b0, unsigned b1) {
    asm volatile("mma.sync.aligned.m16n8k16.row.col.f32.f16.f16.f32 "
                 "{%0,%1,%2,%3}, {%4,%5,%6,%7}, {%8,%9}, {%0,%1,%2,%3};"
                 : "+f"(c[0]), "+f"(c[1]), "+f"(c[2]), "+f"(c[3])
                 : "r"(a0), "r"(a1), "r"(a2), "r"(a3), "r"(b0), "r"(b1));
}
__device__ __forceinline__ float4 fma4(float4 acc, float a, float4 v) {
    acc.x = fmaf(a, v.x, acc.x); acc.y = fmaf(a, v.y, acc.y);
    acc.z = fmaf(a, v.z, acc.z); acc.w = fmaf(a, v.w, acc.w);
    return acc;
}
__device__ __forceinline__ void fmah2(float2& a, float s, unsigned u) {
    float2 p = __half22float2(*(__half2*)&u);
    a.x = fmaf(s, p.x, a.x); a.y = fmaf(s, p.y, a.y);
}
__device__ __forceinline__ void cp16(void* smem_dst, const void* gmem_src) {
    unsigned sa = (unsigned)__cvta_generic_to_shared(smem_dst);
    asm volatile("cp.async.ca.shared.global [%0], [%1], 16;" :: "r"(sa), "l"(gmem_src));
}

// ---------------- layer 1: tf32 GEMM + fused attention scores + fp16 out ----------------
template <int CC>
__global__ void __launch_bounds__(256) gemm_att(const float* __restrict__ A,
                                                const float* __restrict__ B,
                                                __half* __restrict__ Ch,
                                                const float* __restrict__ as_,
                                                const float* __restrict__ ad_,
                                                float* __restrict__ S,
                                                float* __restrict__ D,
                                                float* __restrict__ SUM,
                                                int M, int N, int K) {
    const int NHB  = 128 / CC;
    const int HTOT = 4;
    __shared__ float As[2][128][20];
    __shared__ float Bs[2][128][20];
    __shared__ float sS[128][4];
    __shared__ float sD[128][4];
    int bm = blockIdx.y * 128, bn = blockIdx.x * 128;
    int tid = threadIdx.x;
    int wid = tid >> 5, lane = tid & 31;
    int wm = (wid >> 2) * 64, wn = (wid & 3) * 32;
    int g = lane >> 2, t = lane & 3;

    int lrow0 = tid >> 2, lc4 = (tid & 3) * 4;
    int lrow1 = lrow0 + 64;
    int ar0 = bm + lrow0 < M ? bm + lrow0 : M - 1;
    int ar1 = bm + lrow1 < M ? bm + lrow1 : M - 1;

    float acc[4][4][4] = {};

    cp16(&As[0][lrow0][lc4], A + (size_t)ar0 * K + lc4);
    cp16(&As[0][lrow1][lc4], A + (size_t)ar1 * K + lc4);
    cp16(&Bs[0][lrow0][lc4], B + (size_t)(bn + lrow0) * K + lc4);
    cp16(&Bs[0][lrow1][lc4], B + (size_t)(bn + lrow1) * K + lc4);
    asm volatile("cp.async.commit_group;");

    int buf = 0;
    for (int k0 = 0; k0 < K; k0 += 16, buf ^= 1) {
        if (k0 + 16 < K) {
            int kn = k0 + 16;
            cp16(&As[buf ^ 1][lrow0][lc4], A + (size_t)ar0 * K + kn + lc4);
            cp16(&As[buf ^ 1][lrow1][lc4], A + (size_t)ar1 * K + kn + lc4);
            cp16(&Bs[buf ^ 1][lrow0][lc4], B + (size_t)(bn + lrow0) * K + kn + lc4);
            cp16(&Bs[buf ^ 1][lrow1][lc4], B + (size_t)(bn + lrow1) * K + kn + lc4);
            asm volatile("cp.async.commit_group;");
            asm volatile("cp.async.wait_group 1;");
        } else {
            asm volatile("cp.async.wait_group 0;");
        }
        __syncthreads();
#pragma unroll
        for (int kk = 0; kk < 2; kk++) {
            int kc = kk * 8 + t;
            unsigned a[4][4], bf[4][2];
#pragma unroll
            for (int im = 0; im < 4; im++) {
                int r0 = wm + im * 16 + g;
                a[im][0] = __float_as_uint(As[buf][r0][kc]);
                a[im][1] = __float_as_uint(As[buf][r0 + 8][kc]);
                a[im][2] = __float_as_uint(As[buf][r0][kc + 4]);
                a[im][3] = __float_as_uint(As[buf][r0 + 8][kc + 4]);
            }
#pragma unroll
            for (int jn = 0; jn < 4; jn++) {
                int n0 = wn + jn * 8 + g;
                bf[jn][0] = __float_as_uint(Bs[buf][n0][kc]);
                bf[jn][1] = __float_as_uint(Bs[buf][n0][kc + 4]);
            }
#pragma unroll
            for (int im = 0; im < 4; im++)
#pragma unroll
                for (int jn = 0; jn < 4; jn++)
                    mma_tf32(acc[im][jn], a[im][0], a[im][1], a[im][2], a[im][3],
                             bf[jn][0], bf[jn][1]);
        }
        __syncthreads();
    }

    int hw = wn / CC;
    float asv[8], adv[8];
#pragma unroll
    for (int jn = 0; jn < 4; jn++)
#pragma unroll
        for (int k = 0; k < 2; k++) {
            int gcol = bn + wn + jn * 8 + 2 * t + k;
            asv[jn * 2 + k] = as_[gcol];
            adv[jn * 2 + k] = ad_[gcol];
        }
    for (int i = tid; i < 128 * 4; i += 256) {
        ((float*)sS)[i] = 0.f; ((float*)sD)[i] = 0.f;
    }
    __syncthreads();
#pragma unroll
    for (int im = 0; im < 4; im++) {
#pragma unroll
        for (int hf = 0; hf < 2; hf++) {
            int lrow = wm + im * 16 + hf * 8 + g;
            int r = bm + lrow;
            float sp = 0.f, dp = 0.f;
#pragma unroll
            for (int jn = 0; jn < 4; jn++) {
                float c0 = acc[im][jn][hf * 2 + 0], c1 = acc[im][jn][hf * 2 + 1];
                sp += c0 * asv[jn * 2] + c1 * asv[jn * 2 + 1];
                dp += c0 * adv[jn * 2] + c1 * adv[jn * 2 + 1];
                if (r < M) {
                    int gcol = bn + wn + jn * 8 + 2 * t;
                    *(__half2*)(Ch + (size_t)r * N + gcol) = __floats2half2_rn(c0, c1);
                }
            }
            sp += __shfl_xor_sync(0xffffffffu, sp, 1);
            sp += __shfl_xor_sync(0xffffffffu, sp, 2);
            dp += __shfl_xor_sync(0xffffffffu, dp, 1);
            dp += __shfl_xor_sync(0xffffffffu, dp, 2);
            if ((lane & 3) == 0) {
                atomicAdd(&sS[lrow][hw], sp);
                atomicAdd(&sD[lrow][hw], dp);
            }
        }
    }
    __syncthreads();
    if (tid < 128) {
        int nrow = bm + tid;
        if (nrow < M) {
#pragma unroll
            for (int lh = 0; lh < NHB; lh++) {
                int gh = blockIdx.x * NHB + lh;
                S[nrow * HTOT + gh] = sS[tid][lh];
                D[nrow * HTOT + gh] = sD[tid][lh];
                SUM[nrow * HTOT + gh] = 0.f;
            }
        }
    }
}

// ---------------- layer 2: fp16 GEMM + fused attention scores + fp16 out ----------------
__global__ void __launch_bounds__(256) gemm_att_h(const __half* __restrict__ A,
                                                  const __half* __restrict__ B,
                                                  __half* __restrict__ Ch,
                                                  const float* __restrict__ as_,
                                                  const float* __restrict__ ad_,
                                                  float* __restrict__ S,
                                                  float* __restrict__ D,
                                                  float* __restrict__ SUM,
                                                  int M, int N, int K) {
    const int CC = 32, NHB = 4, HTOT = 4;
    __shared__ __half As[2][128][24];
    __shared__ __half Bs[2][128][24];
    __shared__ float sS[128][4];
    __shared__ float sD[128][4];
    int bm = blockIdx.y * 128, bn = blockIdx.x * 128;
    int tid = threadIdx.x;
    int wid = tid >> 5, lane = tid & 31;
    int wm = (wid >> 2) * 64, wn = (wid & 3) * 32;
    int g = lane >> 2, t = lane & 3;

    int lrow = tid >> 1, lc8 = (tid & 1) * 8;
    int ar = bm + lrow < M ? bm + lrow : M - 1;

    float acc[4][4][4] = {};

    cp16(&As[0][lrow][lc8], A + (size_t)ar * K + lc8);
    cp16(&Bs[0][lrow][lc8], B + (size_t)(bn + lrow) * K + lc8);
    asm volatile("cp.async.commit_group;");

    int buf = 0;
    for (int k0 = 0; k0 < K; k0 += 16, buf ^= 1) {
        if (k0 + 16 < K) {
            int kn = k0 + 16;
            cp16(&As[buf ^ 1][lrow][lc8], A + (size_t)ar * K + kn + lc8);
            cp16(&Bs[buf ^ 1][lrow][lc8], B + (size_t)(bn + lrow) * K + kn + lc8);
            asm volatile("cp.async.commit_group;");
            asm volatile("cp.async.wait_group 1;");
        } else {
            asm volatile("cp.async.wait_group 0;");
        }
        __syncthreads();
        {
            unsigned a[4][4], bf[4][2];
#pragma unroll
            for (int im = 0; im < 4; im++) {
                int r0 = wm + im * 16 + g;
                a[im][0] = *(const unsigned*)&As[buf][r0][2 * t];
                a[im][1] = *(const unsigned*)&As[buf][r0 + 8][2 * t];
                a[im][2] = *(const unsigned*)&As[buf][r0][2 * t + 8];
                a[im][3] = *(const unsigned*)&As[buf][r0 + 8][2 * t + 8];
            }
#pragma unroll
            for (int jn = 0; jn < 4; jn++) {
                int n0 = wn + jn * 8 + g;
                bf[jn][0] = *(const unsigned*)&Bs[buf][n0][2 * t];
                bf[jn][1] = *(const unsigned*)&Bs[buf][n0][2 * t + 8];
            }
#pragma unroll
            for (int im = 0; im < 4; im++)
#pragma unroll
                for (int jn = 0; jn < 4; jn++)
                    mma_f16(acc[im][jn], a[im][0], a[im][1], a[im][2], a[im][3],
                            bf[jn][0], bf[jn][1]);
        }
        __syncthreads();
    }

    int hw = wn / CC;
    float asv[8], adv[8];
#pragma unroll
    for (int jn = 0; jn < 4; jn++)
#pragma unroll
        for (int k = 0; k < 2; k++) {
            int gcol = bn + wn + jn * 8 + 2 * t + k;
            asv[jn * 2 + k] = as_[gcol];
            adv[jn * 2 + k] = ad_[gcol];
        }
    for (int i = tid; i < 128 * 4; i += 256) {
        ((float*)sS)[i] = 0.f; ((float*)sD)[i] = 0.f;
    }
    __syncthreads();
#pragma unroll
    for (int im = 0; im < 4; im++) {
#pragma unroll
        for (int hf = 0; hf < 2; hf++) {
            int lrow2 = wm + im * 16 + hf * 8 + g;
            int r = bm + lrow2;
            float sp = 0.f, dp = 0.f;
#pragma unroll
            for (int jn = 0; jn < 4; jn++) {
                float c0 = acc[im][jn][hf * 2 + 0], c1 = acc[im][jn][hf * 2 + 1];
                sp += c0 * asv[jn * 2] + c1 * asv[jn * 2 + 1];
                dp += c0 * adv[jn * 2] + c1 * adv[jn * 2 + 1];
                if (r < M) {
                    int gcol = bn + wn + jn * 8 + 2 * t;
                    *(__half2*)(Ch + (size_t)r * N + gcol) = __floats2half2_rn(c0, c1);
                }
            }
            sp += __shfl_xor_sync(0xffffffffu, sp, 1);
            sp += __shfl_xor_sync(0xffffffffu, sp, 2);
            dp += __shfl_xor_sync(0xffffffffu, dp, 1);
            dp += __shfl_xor_sync(0xffffffffu, dp, 2);
            if ((lane & 3) == 0) {
                atomicAdd(&sS[lrow2][hw], sp);
                atomicAdd(&sD[lrow2][hw], dp);
            }
        }
    }
    __syncthreads();
    if (tid < 128) {
        int nrow = bm + tid;
        if (nrow < M) {
#pragma unroll
            for (int lh = 0; lh < NHB; lh++) {
                int gh = blockIdx.x * NHB + lh;
                S[nrow * HTOT + gh] = sS[tid][lh];
                D[nrow * HTOT + gh] = sD[tid][lh];
                SUM[nrow * HTOT + gh] = 0.f;
            }
        }
    }
}

// ---------------- W2 fp32 -> fp16, fused with cnt zeroing ----------------
__global__ void cvtW2_zero(const float* __restrict__ W, __half* __restrict__ Wh,
                           int* __restrict__ cnt) {
    int i = blockIdx.x * blockDim.x + threadIdx.x;
    if (i < 128 * 512 / 4) {
        float4 v = ((const float4*)W)[i];
        __half2* o = (__half2*)Wh;
        o[i * 2 + 0] = __floats2half2_rn(v.x, v.y);
        o[i * 2 + 1] = __floats2half2_rn(v.z, v.w);
    }
    if (i < NN) cnt[i] = 0;
}

// ---------------- layer-3 linear + attention scalars fused ----------------
__global__ void h3att(const float* __restrict__ A, const float* __restrict__ W,
                      const float* __restrict__ a3s, const float* __restrict__ a3d,
                      float* __restrict__ C, float* __restrict__ S,
                      float* __restrict__ D, float* __restrict__ SUM) {
    int gt = blockIdx.x * blockDim.x + threadIdx.x;
    int w = gt >> 5, lane = gt & 31;
    if (w >= NN) return;
    float4 a = *(const float4*)(A + (size_t)w * 128 + lane * 4);
    float r[8];
#pragma unroll
    for (int j = 0; j < 8; j++) {
        float4 wv = *(const float4*)(W + j * 128 + lane * 4);
        float p = a.x * wv.x + a.y * wv.y + a.z * wv.z + a.w * wv.w;
#pragma unroll
        for (int o = 16; o; o >>= 1) p += __shfl_xor_sync(0xffffffffu, p, o);
        r[j] = p;
    }
    if (lane == 0) {
        *(float4*)(C + w * 8 + 0) = make_float4(r[0], r[1], r[2], r[3]);
        *(float4*)(C + w * 8 + 4) = make_float4(r[4], r[5], r[6], r[7]);
        float s = 0.f, d = 0.f;
#pragma unroll
        for (int j = 0; j < 8; j++) { s += r[j] * a3s[j]; d += r[j] * a3d[j]; }
        S[w] = s; D[w] = d; SUM[w] = 0.f;
    }
}

// ---------------- CSR build ----------------
__global__ void k_count(const int* __restrict__ ei, int* __restrict__ cnt) {
    int e = blockIdx.x * blockDim.x + threadIdx.x;
    if (e >= ET) return;
    atomicAdd(&cnt[edge_dst(ei, e)], 1);
}
// 2-level parallel exclusive scan
__global__ void scanA(const int* __restrict__ cnt, int* __restrict__ ofs,
                      int* __restrict__ bsum) {
    __shared__ int sh[SCAN_B];
    int t = threadIdx.x;
    int i = blockIdx.x * SCAN_B + t;
    int v = i < NN ? cnt[i] : 0;
    sh[t] = v;
    __syncthreads();
#pragma unroll
    for (int off = 1; off < SCAN_B; off <<= 1) {
        int u = t >= off ? sh[t - off] : 0;
        __syncthreads();
        sh[t] += u;
        __syncthreads();
    }
    if (i < NN) ofs[i] = sh[t] - v;                 // exclusive (block-local)
    if (t == SCAN_B - 1) bsum[blockIdx.x] = sh[t];
}
__global__ void __launch_bounds__(SCAN_B) scanB(const int* __restrict__ bsum,
                                                int* __restrict__ bofs) {
    __shared__ int sh[SCAN_B];
    int t = threadIdx.x;
    int v = t < SCAN_G ? bsum[t] : 0;
    sh[t] = v;
    __syncthreads();
#pragma unroll
    for (int off = 1; off < SCAN_B; off <<= 1) {
        int u = t >= off ? sh[t - off] : 0;
        __syncthreads();
        sh[t] += u;
        __syncthreads();
    }
    if (t < SCAN_G) bofs[t] = sh[t] - v;            // exclusive
}
__global__ void scanC(const int* __restrict__ bofs, int* __restrict__ ofs,
                      int* __restrict__ cur) {
    int i = blockIdx.x * SCAN_B + threadIdx.x;
    if (i >= NN) return;
    int o = ofs[i] + bofs[blockIdx.x];
    ofs[i] = o;
    cur[i] = o;
}
__global__ void k_scatter(const int* __restrict__ ei, int* __restrict__ cur,
                          int* __restrict__ pos, int* __restrict__ esrc) {
    int e = blockIdx.x * blockDim.x + threadIdx.x;
    if (e >= ET) return;
    int p = atomicAdd(&cur[edge_dst(ei, e)], 1);
    pos[e] = p;
    esrc[p] = edge_src(ei, e);
}

// ---------------- softmax numerators (CSR-ordered) + denominator ----------------
__global__ void edge_sum4(const int* __restrict__ ei, const int* __restrict__ pos,
                          const float* __restrict__ S, const float* __restrict__ D,
                          float* __restrict__ SUM, float* __restrict__ EXc) {
    int e = blockIdx.x * blockDim.x + threadIdx.x;
    if (e >= ET) return;
    int s = edge_src(ei, e), d = edge_dst(ei, e);
    float4 sv = *(const float4*)(S + s * 4);
    float4 dv = *(const float4*)(D + d * 4);
    float e0 = __expf(lrelu(sv.x + dv.x));
    float e1 = __expf(lrelu(sv.y + dv.y));
    float e2 = __expf(lrelu(sv.z + dv.z));
    float e3 = __expf(lrelu(sv.w + dv.w));
    *(float4*)(EXc + (size_t)pos[e] * 4) = make_float4(e0, e1, e2, e3);
    red4(SUM + d * 4, e0, e1, e2, e3);
}
__global__ void edge_sum1(const int* __restrict__ ei, const int* __restrict__ pos,
                          const float* __restrict__ S, const float* __restrict__ D,
                          float* __restrict__ SUM, float* __restrict__ EXc) {
    int e = blockIdx.x * blockDim.x + threadIdx.x;
    if (e >= ET) return;
    int s = edge_src(ei, e), d = edge_dst(ei, e);
    float ex = __expf(lrelu(S[s] + D[d]));
    EXc[pos[e]] = ex;
    atomicAdd(&SUM[d], ex);
}

// ---------------- CSR gather aggregation (fp16 H, +1/den, bias, ELU fused) ----------------
// layer 1: H=4, C=128; TWO warps per node; lane owns one 8-half chunk.
__global__ void agg1(const int* __restrict__ ofs, const int* __restrict__ cnt,
                     const int* __restrict__ esrc, const float* __restrict__ EXc,
                     const float* __restrict__ SUM,
                     const __half* __restrict__ Hh, const float* __restrict__ b,
                     __half* __restrict__ Oh) {
    int gt = blockIdx.x * blockDim.x + threadIdx.x;
    int w = gt >> 5, lane = gt & 31;
    if (w >= NN * 2) return;
    int n = w >> 1, half = w & 1;
    int chunk = half * 32 + lane;
    int hsel = chunk >> 4;
    int st = ofs[n], deg = cnt[n];
    const uint4* H4 = (const uint4*)Hh;
    float2 acc[4] = {};
#pragma unroll 2
    for (int i = 0; i < deg; i++) {
        int s = esrc[st + i];
        float a = EXc[(size_t)(st + i) * 4 + hsel];
        uint4 v = H4[(size_t)s * 64 + chunk];
        fmah2(acc[0], a, v.x); fmah2(acc[1], a, v.y);
        fmah2(acc[2], a, v.z); fmah2(acc[3], a, v.w);
    }
    float rs = __frcp_rn(SUM[n * 4 + hsel]);
    __half2* orow = (__half2*)(Oh + (size_t)n * 512);
#pragma unroll
    for (int j = 0; j < 4; j++) {
        int c = chunk * 8 + j * 2;
        float2 bv = *(const float2*)(b + c);
        float rx = elu(fmaf(acc[j].x, rs, bv.x));
        float ry = elu(fmaf(acc[j].y, rs, bv.y));
        orow[chunk * 4 + j] = __floats2half2_rn(rx, ry);
    }
}

// layer 2: H=4, C=32; warp per node; lane owns 4 halfs at channels lane*4
__global__ void agg2(const int* __restrict__ ofs, const int* __restrict__ cnt,
                     const int* __restrict__ esrc, const float* __restrict__ EXc,
                     const float* __restrict__ SUM,
                     const __half* __restrict__ Hh, const float* __restrict__ b,
                     float* __restrict__ O) {
    int gt = blockIdx.x * blockDim.x + threadIdx.x;
    int n = gt >> 5, lane = gt & 31;
    if (n >= NN) return;
    int st = ofs[n], deg = cnt[n];
    int h = lane >> 3;
    const uint2* H2v = (const uint2*)Hh;
    float2 acc0 = {}, acc1 = {};
#pragma unroll 2
    for (int i = 0; i < deg; i++) {
        int s = esrc[st + i];
        float a = EXc[(size_t)(st + i) * 4 + h];
        uint2 v = H2v[(size_t)s * 32 + lane];
        fmah2(acc0, a, v.x);
        fmah2(acc1, a, v.y);
    }
    float rs = __frcp_rn(SUM[n * 4 + h]);
    float4 bv = ((const float4*)b)[lane];
    float4 r;
    r.x = elu(fmaf(acc0.x, rs, bv.x)); r.y = elu(fmaf(acc0.y, rs, bv.y));
    r.z = elu(fmaf(acc1.x, rs, bv.z)); r.w = elu(fmaf(acc1.y, rs, bv.w));
    ((float4*)(O + (size_t)n * 128))[lane] = r;
}

// layer 3: H=1, C=8; thread per node (fp32 H3)
__global__ void agg3(const int* __restrict__ ofs, const int* __restrict__ cnt,
                     const int* __restrict__ esrc, const float* __restrict__ EXc,
                     const float* __restrict__ SUM,
                     const float* __restrict__ Hb, const float* __restrict__ b,
                     float* __restrict__ O) {
    int n = blockIdx.x * blockDim.x + threadIdx.x;
    if (n >= NN) return;
    int st = ofs[n], deg = cnt[n];
    float4 acc0 = {0, 0, 0, 0}, acc1 = {0, 0, 0, 0};
    int i = 0;
    for (; i + 2 <= deg; i += 2) {
        int s0 = esrc[st + i], s1 = esrc[st + i + 1];
        float a0 = EXc[st + i], a1 = EXc[st + i + 1];
        acc0 = fma4(acc0, a0, *(const float4*)(Hb + s0 * 8));
        acc1 = fma4(acc1, a0, *(const float4*)(Hb + s0 * 8 + 4));
        acc0 = fma4(acc0, a1, *(const float4*)(Hb + s1 * 8));
        acc1 = fma4(acc1, a1, *(const float4*)(Hb + s1 * 8 + 4));
    }
    if (i < deg) {
        int s0 = esrc[st + i];
        float a0 = EXc[st + i];
        acc0 = fma4(acc0, a0, *(const float4*)(Hb + s0 * 8));
        acc1 = fma4(acc1, a0, *(const float4*)(Hb + s0 * 8 + 4));
    }
    float rs = __frcp_rn(SUM[n]);
    float4 b0 = *(const float4*)(b), b1 = *(const float4*)(b + 4);
    acc0.x = elu(fmaf(acc0.x, rs, b0.x)); acc0.y = elu(fmaf(acc0.y, rs, b0.y));
    acc0.z = elu(fmaf(acc0.z, rs, b0.z)); acc0.w = elu(fmaf(acc0.w, rs, b0.w));
    acc1.x = elu(fmaf(acc1.x, rs, b1.x)); acc1.y = elu(fmaf(acc1.y, rs, b1.y));
    acc1.z = elu(fmaf(acc1.z, rs, b1.z)); acc1.w = elu(fmaf(acc1.w, rs, b1.w));
    *(float4*)(O + n * 8) = acc0;
    *(float4*)(O + n * 8 + 4) = acc1;
}

// ---------------- final per-edge MLP ----------------
__global__ void edge_mlp(const int* __restrict__ ei, const float* __restrict__ h3,
                         const float* __restrict__ ea, const float* __restrict__ yr,
                         const float* __restrict__ qt,
                         const float* __restrict__ fc1w, const float* __restrict__ fc1b,
                         const float* __restrict__ fc2w, const float* __restrict__ fc2b,
                         float* __restrict__ out) {
    __shared__ float w1[16 * 19];
    __shared__ float b1s[16];
    __shared__ float w2[16];
    int tid = threadIdx.x;
    for (int i = tid; i < 16 * 19; i += blockDim.x) w1[i] = fc1w[i];
    if (tid < 16) { b1s[tid] = fc1b[tid]; w2[tid] = fc2w[tid]; }
    __syncthreads();
    int e = blockIdx.x * blockDim.x + tid;
    if (e >= EE) return;
    int s = ei[e], d = ei[EE + e];
    float z[19];
    float4 a0 = *(const float4*)&h3[s * 8 + 0];
    float4 a1 = *(const float4*)&h3[s * 8 + 4];
    float4 c0 = *(const float4*)&h3[d * 8 + 0];
    float4 c1 = *(const float4*)&h3[d * 8 + 4];
    z[0] = a0.x; z[1] = a0.y; z[2] = a0.z; z[3] = a0.w;
    z[4] = a1.x; z[5] = a1.y; z[6] = a1.z; z[7] = a1.w;
    z[8] = c0.x; z[9] = c0.y; z[10] = c0.z; z[11] = c0.w;
    z[12] = c1.x; z[13] = c1.y; z[14] = c1.z; z[15] = c1.w;
    z[16] = ea[e]; z[17] = yr[e]; z[18] = qt[e];
    float acc = fc2b[0];
#pragma unroll
    for (int o = 0; o < 16; o++) {
        float t = b1s[o];
#pragma unroll
        for (int i = 0; i < 19; i++) t += w1[o * 19 + i] * z[i];
        t = fmaxf(t, 0.f);
        acc += t * w2[o];
    }
    out[e] = acc;
}

// ---------------- host driver ----------------
static inline int cdiv(long long a, int b) { return (int)((a + b - 1) / b); }

extern "C" void kernel_launch(void* const* d_in, const int* in_sizes, int n_in,
                              void* d_out, int out_size) {
    (void)in_sizes; (void)n_in; (void)out_size;
    const float* x    = (const float*)d_in[0];
    const int*   ei   = (const int*)  d_in[1];
    const float* ea   = (const float*)d_in[2];
    const float* yr   = (const float*)d_in[3];
    const float* qt   = (const float*)d_in[4];
    const float* W1   = (const float*)d_in[5];
    const float* a1s  = (const float*)d_in[6];
    const float* a1d  = (const float*)d_in[7];
    const float* b1   = (const float*)d_in[8];
    const float* W2   = (const float*)d_in[9];
    const float* a2s  = (const float*)d_in[10];
    const float* a2d  = (const float*)d_in[11];
    const float* b2   = (const float*)d_in[12];
    const float* W3   = (const float*)d_in[13];
    const float* a3s  = (const float*)d_in[14];
    const float* a3d  = (const float*)d_in[15];
    const float* b3   = (const float*)d_in[16];
    const float* fc1w = (const float*)d_in[17];
    const float* fc1b = (const float*)d_in[18];
    const float* fc2w = (const float*)d_in[19];
    const float* fc2b = (const float*)d_in[20];
    float* out = (float*)d_out;

    __half *H1h, *O1h, *H2h, *W2h;
    float *O2, *H3, *O3, *S, *D, *SUM, *EXc;
    int *cnt, *ofs, *cur, *pos, *esrc, *bsum, *bofs;
    cudaGetSymbolAddress((void**)&H1h, g_H1h);
    cudaGetSymbolAddress((void**)&O1h, g_O1h);
    cudaGetSymbolAddress((void**)&H2h, g_H2h);
    cudaGetSymbolAddress((void**)&W2h, g_W2h);
    cudaGetSymbolAddress((void**)&O2, g_O2);
    cudaGetSymbolAddress((void**)&H3, g_H3);
    cudaGetSymbolAddress((void**)&O3, g_O3);
    cudaGetSymbolAddress((void**)&S,  g_S);
    cudaGetSymbolAddress((void**)&D,  g_D);
    cudaGetSymbolAddress((void**)&SUM, g_SUM);
    cudaGetSymbolAddress((void**)&EXc, g_EXc);
    cudaGetSymbolAddress((void**)&cnt, g_cnt);
    cudaGetSymbolAddress((void**)&ofs, g_ofs);
    cudaGetSymbolAddress((void**)&cur, g_cur);
    cudaGetSymbolAddress((void**)&pos, g_pos);
    cudaGetSymbolAddress((void**)&esrc, g_esrc);
    cudaGetSymbolAddress((void**)&bsum, g_bsum);
    cudaGetSymbolAddress((void**)&bofs, g_bofs);

    const int T = 256;

    // ---------- CSR build + weight conversion ----------
    cvtW2_zero<<<cdiv(NN, T), T>>>(W2, W2h, cnt);
    k_count<<<cdiv(ET, T), T>>>(ei, cnt);
    scanA<<<SCAN_G, SCAN_B>>>(cnt, ofs, bsum);
    scanB<<<1, SCAN_B>>>(bsum, bofs);
    scanC<<<SCAN_G, SCAN_B>>>(bofs, ofs, cur);
    k_scatter<<<cdiv(ET, T), T>>>(ei, cur, pos, esrc);

    // ---------- layer 1: 128 -> 4 x 128 (tf32 GEMM + fused attscore, fp16 H) ----------
    gemm_att<128><<<dim3(4, cdiv(NN, 128)), T>>>(x, W1, H1h, a1s, a1d, S, D, SUM,
                                                 NN, 512, 128);
    edge_sum4<<<cdiv(ET, T), T>>>(ei, pos, S, D, SUM, EXc);
    agg1<<<cdiv((long long)NN * 64, T), T>>>(ofs, cnt, esrc, EXc, SUM, H1h, b1, O1h);

    // ---------- layer 2: 512 -> 4 x 32 (fp16 GEMM) ----------
    gemm_att_h<<<dim3(1, cdiv(NN, 128)), T>>>(O1h, W2h, H2h, a2s, a2d, S, D, SUM,
                                              NN, 128, 512);
    edge_sum4<<<cdiv(ET, T), T>>>(ei, pos, S, D, SUM, EXc);
    agg2<<<cdiv((long long)NN * 32, T), T>>>(ofs, cnt, esrc, EXc, SUM, H2h, b2, O2);

    // ---------- layer 3: 128 -> 1 x 8 ----------
    h3att<<<cdiv((long long)NN * 32, T), T>>>(O2, W3, a3s, a3d, H3, S, D, SUM);
    edge_sum1<<<cdiv(ET, T), T>>>(ei, pos, S, D, SUM, EXc);
    agg3<<<cdiv(NN, T), T>>>(ofs, cnt, esrc, EXc, SUM, H3, b3, O3);

    // ---------- final per-edge MLP ----------
    edge_mlp<<<cdiv(EE, T), T>>>(ei, O3, ea, yr, qt, fc1w, fc1b, fc2w, fc2b, out);
}